// round 7
// baseline (speedup 1.0000x reference)
#include <cuda_runtime.h>
#include <cuda_bf16.h>
#include <math.h>
#include <stdint.h>

#define Bn   16
#define Sn   512
#define Dn   2048
#define Hn   16
#define HDn  128
#define Mtot (Bn*Sn)      // 8192

// ---------------- scratch (alloc-free: __device__ globals) ----------------
__device__ float g_p[(size_t)Bn * Hn * Sn * Sn];    // 256 MB logits (fp32)
__device__ __nv_bfloat16 g_ahi[(size_t)Mtot * Dn];  // 32 MB (x / attn-out hi)
__device__ __nv_bfloat16 g_alo[(size_t)Mtot * Dn];  // 32 MB
__device__ __nv_bfloat16 g_whi[(size_t)3 * Dn * Dn]; // 24 MB (W^T qkv hi)
__device__ __nv_bfloat16 g_wlo[(size_t)3 * Dn * Dn]; // 24 MB
__device__ __nv_bfloat16 g_woh[(size_t)Dn * Dn];     // 8 MB  (W^T o hi)
__device__ __nv_bfloat16 g_wol[(size_t)Dn * Dn];     // 8 MB
__device__ __nv_bfloat16 g_qh[(size_t)Mtot * Dn];
__device__ __nv_bfloat16 g_ql[(size_t)Mtot * Dn];
__device__ __nv_bfloat16 g_kh[(size_t)Mtot * Dn];
__device__ __nv_bfloat16 g_kl[(size_t)Mtot * Dn];
__device__ __nv_bfloat16 g_vh[(size_t)Mtot * Dn];
__device__ __nv_bfloat16 g_vl[(size_t)Mtot * Dn];
__device__ __nv_bfloat16 g_ph[(size_t)Bn * Hn * Sn * Sn];  // 128 MB
__device__ __nv_bfloat16 g_pl[(size_t)Bn * Hn * Sn * Sn];  // 128 MB

// ============================================================================
// PTX helpers (sm_80-compatible subset)
// ============================================================================
__device__ __forceinline__ uint32_t smem_u32(const void* p) {
    uint32_t a;
    asm("{ .reg .u64 t; cvta.to.shared.u64 t, %1; cvt.u32.u64 %0, t; }" : "=r"(a) : "l"(p));
    return a;
}
__device__ __forceinline__ void cp16(uint32_t saddr, const void* gptr) {
    asm volatile("cp.async.cg.shared.global [%0], [%1], 16;" :: "r"(saddr), "l"(gptr) : "memory");
}
__device__ __forceinline__ void cp_commit() {
    asm volatile("cp.async.commit_group;" ::: "memory");
}
template <int N>
__device__ __forceinline__ void cp_wait() {
    asm volatile("cp.async.wait_group %0;" :: "n"(N) : "memory");
}
__device__ __forceinline__ void ldsm4(uint32_t* r, uint32_t addr) {
    asm volatile("ldmatrix.sync.aligned.m8n8.x4.shared.b16 {%0,%1,%2,%3}, [%4];"
                 : "=r"(r[0]), "=r"(r[1]), "=r"(r[2]), "=r"(r[3]) : "r"(addr));
}
__device__ __forceinline__ void ldsm4t(uint32_t* r, uint32_t addr) {
    asm volatile("ldmatrix.sync.aligned.m8n8.x4.trans.shared.b16 {%0,%1,%2,%3}, [%4];"
                 : "=r"(r[0]), "=r"(r[1]), "=r"(r[2]), "=r"(r[3]) : "r"(addr));
}
__device__ __forceinline__ void mma_bf16(float* d, const uint32_t* a, const uint32_t* b) {
    asm volatile("mma.sync.aligned.m16n8k16.row.col.f32.bf16.bf16.f32 "
                 "{%0,%1,%2,%3}, {%4,%5,%6,%7}, {%8,%9}, {%0,%1,%2,%3};"
                 : "+f"(d[0]), "+f"(d[1]), "+f"(d[2]), "+f"(d[3])
                 : "r"(a[0]), "r"(a[1]), "r"(a[2]), "r"(a[3]), "r"(b[0]), "r"(b[1]));
}

// ============================================================================
// Tile geometry
// ============================================================================
#define KC      32
#define ROWB    80                   // bytes/row for 32-bf16 tiles (padded)
#define TILE_B  (128 * ROWB)         // 10240 B
#define VROWB   272                  // bytes/row for 128-bf16 V tiles (padded)
#define VTILE_B (32 * VROWB)         // 8704 B

__device__ __forceinline__ void load_tile(const __nv_bfloat16* __restrict__ g,
                                          int ldg, uint32_t sdst, int tid)
{
    #pragma unroll
    for (int it = 0; it < 2; ++it) {
        int idx = tid + it * 256;
        int row = idx >> 2, seg = idx & 3;
        cp16(sdst + (uint32_t)(row * ROWB + seg * 16),
             (const char*)(g + (size_t)row * ldg) + seg * 16);
    }
}
__device__ __forceinline__ void load_vtile(const __nv_bfloat16* __restrict__ g,
                                           uint32_t sdst, int tid)
{
    #pragma unroll
    for (int it = 0; it < 2; ++it) {
        int idx = tid + it * 256;
        int row = idx >> 4, seg = idx & 15;
        cp16(sdst + (uint32_t)(row * VROWB + seg * 16),
             (const char*)(g + (size_t)row * Dn) + seg * 16);
    }
}

__device__ __forceinline__ void split_store(__nv_bfloat16* __restrict__ OH,
                                            __nv_bfloat16* __restrict__ OL,
                                            size_t off, float v0, float v1)
{
    __nv_bfloat16 h0 = __float2bfloat16(v0), h1 = __float2bfloat16(v1);
    __nv_bfloat16 l0 = __float2bfloat16(v0 - __bfloat162float(h0));
    __nv_bfloat16 l1 = __float2bfloat16(v1 - __bfloat162float(h1));
    *(__nv_bfloat162*)&OH[off] = __halves2bfloat162(h0, h1);
    *(__nv_bfloat162*)&OL[off] = __halves2bfloat162(l0, l1);
}

// ============================================================================
// Split / transpose preprocessing
// ============================================================================
__global__ void __launch_bounds__(256)
split_kernel(const float4* __restrict__ X, __nv_bfloat16* __restrict__ Hh,
             __nv_bfloat16* __restrict__ Hl)
{
    size_t i = (size_t)blockIdx.x * 256 + threadIdx.x;
    float4 v = X[i];
    float hx = __bfloat162float(__float2bfloat16(v.x));
    float hy = __bfloat162float(__float2bfloat16(v.y));
    float hz = __bfloat162float(__float2bfloat16(v.z));
    float hw = __bfloat162float(__float2bfloat16(v.w));
    __nv_bfloat162* H2 = (__nv_bfloat162*)Hh;
    __nv_bfloat162* L2 = (__nv_bfloat162*)Hl;
    H2[2*i]   = __floats2bfloat162_rn(hx, hy);
    H2[2*i+1] = __floats2bfloat162_rn(hz, hw);
    L2[2*i]   = __floats2bfloat162_rn(v.x - hx, v.y - hy);
    L2[2*i+1] = __floats2bfloat162_rn(v.z - hz, v.w - hw);
}

__global__ void __launch_bounds__(256)
splitT_kernel(const float* __restrict__ W, __nv_bfloat16* __restrict__ Th,
              __nv_bfloat16* __restrict__ Tl)
{
    __shared__ float t[32][33];
    int bx = blockIdx.x * 32;   // n
    int by = blockIdx.y * 32;   // k
    int tx = threadIdx.x, ty = threadIdx.y;
    #pragma unroll
    for (int i = 0; i < 32; i += 8)
        t[ty + i][tx] = W[(size_t)(by + ty + i) * Dn + bx + tx];
    __syncthreads();
    #pragma unroll
    for (int i = 0; i < 32; i += 8) {
        float v = t[tx][ty + i];
        float h = __bfloat162float(__float2bfloat16(v));
        size_t o = (size_t)(bx + ty + i) * Dn + by + tx;
        Th[o] = __float2bfloat16(h);
        Tl[o] = __float2bfloat16(v - h);
    }
}

// ============================================================================
// Merged QKV GEMM: one launch, grid (48, 64). W^T buffer holds q|k|v splits
// stacked along N (6144 rows). which = colStart>>11 selects bias / RoPE /
// output buffers. 256 threads, 8 warps, warp tile 64x32 (R4 shape), bH cached.
// ============================================================================
#define BUF_B     (4 * TILE_B)
#define GEMM_SMEM (2 * BUF_B)        // 81920

__global__ void __launch_bounds__(256)
gemm_qkv(const __nv_bfloat16* __restrict__ Ah, const __nv_bfloat16* __restrict__ Al,
         const __nv_bfloat16* __restrict__ Wh, const __nv_bfloat16* __restrict__ Wl,
         const float* __restrict__ bq, const float* __restrict__ bk,
         const float* __restrict__ bv,
         __nv_bfloat16* __restrict__ qh, __nv_bfloat16* __restrict__ ql,
         __nv_bfloat16* __restrict__ kh, __nv_bfloat16* __restrict__ kl,
         __nv_bfloat16* __restrict__ vh, __nv_bfloat16* __restrict__ vl)
{
    extern __shared__ char smem_raw[];
    const uint32_t sb = smem_u32(smem_raw);

    const int tid  = threadIdx.x;
    const int wid  = tid >> 5;
    const int lane = tid & 31;
    const int rowStart = blockIdx.y * 128;
    const int colStart = blockIdx.x * 128;     // 0..6143
    const int which = colStart >> 11;          // 0=q, 1=k, 2=v
    const int ccol  = colStart & (Dn - 1);     // local output column
    const int warp_m = (wid & 1) * 64;
    const int warp_n = (wid >> 1) * 32;

    const float* bias = (which == 0) ? bq : (which == 1) ? bk : bv;
    __nv_bfloat16* OH = (which == 0) ? qh : (which == 1) ? kh : vh;
    __nv_bfloat16* OL = (which == 0) ? ql : (which == 1) ? kl : vl;

    const __nv_bfloat16* gA0 = Ah + (size_t)rowStart * Dn;
    const __nv_bfloat16* gA1 = Al + (size_t)rowStart * Dn;
    const __nv_bfloat16* gB0 = Wh + (size_t)colStart * Dn;
    const __nv_bfloat16* gB1 = Wl + (size_t)colStart * Dn;

    const uint32_t aoff = (uint32_t)((lane & 15) * ROWB + (lane >> 4) * 16);
    const uint32_t boff = (uint32_t)(((lane & 7) + ((lane >> 4) << 3)) * ROWB
                                     + ((lane >> 3) & 1) * 16);

    float acc[4][4][4];
    #pragma unroll
    for (int i = 0; i < 4; i++)
        #pragma unroll
        for (int j = 0; j < 4; j++)
            #pragma unroll
            for (int r = 0; r < 4; r++) acc[i][j][r] = 0.f;

    const int NCHUNK = Dn / KC;   // 64

    {
        const uint32_t bb = sb;
        load_tile(gA0, Dn, bb,            tid);
        load_tile(gA1, Dn, bb + TILE_B,   tid);
        load_tile(gB0, Dn, bb + 2*TILE_B, tid);
        load_tile(gB1, Dn, bb + 3*TILE_B, tid);
        cp_commit();
    }

    #pragma unroll 1
    for (int c = 0; c < NCHUNK; ++c) {
        if (c + 1 < NCHUNK) {
            const uint32_t bb = sb + ((c + 1) & 1) * BUF_B;
            const int k0 = (c + 1) * KC;
            load_tile(gA0 + k0, Dn, bb,            tid);
            load_tile(gA1 + k0, Dn, bb + TILE_B,   tid);
            load_tile(gB0 + k0, Dn, bb + 2*TILE_B, tid);
            load_tile(gB1 + k0, Dn, bb + 3*TILE_B, tid);
            cp_commit();
            cp_wait<1>();
        } else {
            cp_wait<0>();
        }
        __syncthreads();

        const uint32_t bb  = sb + (c & 1) * BUF_B;
        const uint32_t sAh = bb,             sAl = bb + TILE_B;
        const uint32_t sBh = bb + 2*TILE_B,  sBl = bb + 3*TILE_B;

        #pragma unroll
        for (int kk = 0; kk < 2; ++kk) {
            const uint32_t kb = (uint32_t)(kk * 32);
            uint32_t afrag[4][4], bH[4][2], bL[4][2];

            #pragma unroll
            for (int i = 0; i < 4; ++i)
                ldsm4(afrag[i], sAh + aoff + kb + (uint32_t)((warp_m + i*16) * ROWB));
            #pragma unroll
            for (int p = 0; p < 2; ++p) {
                uint32_t r[4];
                ldsm4(r, sBh + boff + kb + (uint32_t)((warp_n + p*16) * ROWB));
                bH[p*2][0] = r[0]; bH[p*2][1] = r[1];
                bH[p*2+1][0] = r[2]; bH[p*2+1][1] = r[3];
            }
            #pragma unroll
            for (int i = 0; i < 4; ++i)
                #pragma unroll
                for (int j = 0; j < 4; ++j)
                    mma_bf16(acc[i][j], afrag[i], bH[j]);

            #pragma unroll
            for (int p = 0; p < 2; ++p) {
                uint32_t r[4];
                ldsm4(r, sBl + boff + kb + (uint32_t)((warp_n + p*16) * ROWB));
                bL[p*2][0] = r[0]; bL[p*2][1] = r[1];
                bL[p*2+1][0] = r[2]; bL[p*2+1][1] = r[3];
            }
            #pragma unroll
            for (int i = 0; i < 4; ++i)
                #pragma unroll
                for (int j = 0; j < 4; ++j)
                    mma_bf16(acc[i][j], afrag[i], bL[j]);

            #pragma unroll
            for (int i = 0; i < 4; ++i)
                ldsm4(afrag[i], sAl + aoff + kb + (uint32_t)((warp_m + i*16) * ROWB));
            #pragma unroll
            for (int i = 0; i < 4; ++i)
                #pragma unroll
                for (int j = 0; j < 4; ++j)
                    mma_bf16(acc[i][j], afrag[i], bH[j]);
        }
        __syncthreads();
    }

    const bool rope = (which < 2);
    #pragma unroll
    for (int i = 0; i < 4; ++i) {
        const int r0 = rowStart + warp_m + i * 16 + (lane >> 2);
        #pragma unroll
        for (int half = 0; half < 2; ++half) {
            const int r = r0 + half * 8;
            const int s = r & (Sn - 1);
            #pragma unroll
            for (int j = 0; j < 4; ++j) {
                const int c0 = ccol + warp_n + j * 8 + (lane & 3) * 2;
                float v0 = acc[i][j][half*2]   + bias[c0];
                float v1 = acc[i][j][half*2+1] + bias[c0 + 1];
                if (rope) {
                    int pidx = (c0 & (HDn - 1)) >> 1;
                    float inv = exp2f((float)pidx * (-13.287712379549449f / 64.0f));
                    float sn, cs;
                    sincosf((float)s * inv, &sn, &cs);
                    float e = v0, o = v1;
                    v0 = e * cs - o * sn;
                    v1 = o * cs + e * sn;
                }
                split_store(OH, OL, (size_t)r * Dn + c0, v0, v1);
            }
        }
    }
}

// ============================================================================
// WO GEMM (fp32 out), R4/R6 shape.
// ============================================================================
__global__ void __launch_bounds__(256)
gemm_wo(const __nv_bfloat16* __restrict__ Ah, const __nv_bfloat16* __restrict__ Al,
        const __nv_bfloat16* __restrict__ Bh, const __nv_bfloat16* __restrict__ Bl,
        const float* __restrict__ bias, float* __restrict__ Cf)
{
    extern __shared__ char smem_raw[];
    const uint32_t sb = smem_u32(smem_raw);

    const int tid  = threadIdx.x;
    const int wid  = tid >> 5;
    const int lane = tid & 31;
    const int rowStart = blockIdx.y * 128;
    const int colStart = blockIdx.x * 128;
    const int warp_m = (wid & 1) * 64;
    const int warp_n = (wid >> 1) * 32;

    const __nv_bfloat16* gA0 = Ah + (size_t)rowStart * Dn;
    const __nv_bfloat16* gA1 = Al + (size_t)rowStart * Dn;
    const __nv_bfloat16* gB0 = Bh + (size_t)colStart * Dn;
    const __nv_bfloat16* gB1 = Bl + (size_t)colStart * Dn;

    const uint32_t aoff = (uint32_t)((lane & 15) * ROWB + (lane >> 4) * 16);
    const uint32_t boff = (uint32_t)(((lane & 7) + ((lane >> 4) << 3)) * ROWB
                                     + ((lane >> 3) & 1) * 16);

    float acc[4][4][4];
    #pragma unroll
    for (int i = 0; i < 4; i++)
        #pragma unroll
        for (int j = 0; j < 4; j++)
            #pragma unroll
            for (int r = 0; r < 4; r++) acc[i][j][r] = 0.f;

    const int NCHUNK = Dn / KC;

    {
        const uint32_t bb = sb;
        load_tile(gA0, Dn, bb,            tid);
        load_tile(gA1, Dn, bb + TILE_B,   tid);
        load_tile(gB0, Dn, bb + 2*TILE_B, tid);
        load_tile(gB1, Dn, bb + 3*TILE_B, tid);
        cp_commit();
    }

    #pragma unroll 1
    for (int c = 0; c < NCHUNK; ++c) {
        if (c + 1 < NCHUNK) {
            const uint32_t bb = sb + ((c + 1) & 1) * BUF_B;
            const int k0 = (c + 1) * KC;
            load_tile(gA0 + k0, Dn, bb,            tid);
            load_tile(gA1 + k0, Dn, bb + TILE_B,   tid);
            load_tile(gB0 + k0, Dn, bb + 2*TILE_B, tid);
            load_tile(gB1 + k0, Dn, bb + 3*TILE_B, tid);
            cp_commit();
            cp_wait<1>();
        } else {
            cp_wait<0>();
        }
        __syncthreads();

        const uint32_t bb  = sb + (c & 1) * BUF_B;
        const uint32_t sAh = bb,             sAl = bb + TILE_B;
        const uint32_t sBh = bb + 2*TILE_B,  sBl = bb + 3*TILE_B;

        #pragma unroll
        for (int kk = 0; kk < 2; ++kk) {
            const uint32_t kb = (uint32_t)(kk * 32);
            uint32_t afrag[4][4], bH[4][2], bL[4][2];

            #pragma unroll
            for (int i = 0; i < 4; ++i)
                ldsm4(afrag[i], sAh + aoff + kb + (uint32_t)((warp_m + i*16) * ROWB));
            #pragma unroll
            for (int p = 0; p < 2; ++p) {
                uint32_t r[4];
                ldsm4(r, sBh + boff + kb + (uint32_t)((warp_n + p*16) * ROWB));
                bH[p*2][0] = r[0]; bH[p*2][1] = r[1];
                bH[p*2+1][0] = r[2]; bH[p*2+1][1] = r[3];
            }
            #pragma unroll
            for (int i = 0; i < 4; ++i)
                #pragma unroll
                for (int j = 0; j < 4; ++j)
                    mma_bf16(acc[i][j], afrag[i], bH[j]);

            #pragma unroll
            for (int p = 0; p < 2; ++p) {
                uint32_t r[4];
                ldsm4(r, sBl + boff + kb + (uint32_t)((warp_n + p*16) * ROWB));
                bL[p*2][0] = r[0]; bL[p*2][1] = r[1];
                bL[p*2+1][0] = r[2]; bL[p*2+1][1] = r[3];
            }
            #pragma unroll
            for (int i = 0; i < 4; ++i)
                #pragma unroll
                for (int j = 0; j < 4; ++j)
                    mma_bf16(acc[i][j], afrag[i], bL[j]);

            #pragma unroll
            for (int i = 0; i < 4; ++i)
                ldsm4(afrag[i], sAl + aoff + kb + (uint32_t)((warp_m + i*16) * ROWB));
            #pragma unroll
            for (int i = 0; i < 4; ++i)
                #pragma unroll
                for (int j = 0; j < 4; ++j)
                    mma_bf16(acc[i][j], afrag[i], bH[j]);
        }
        __syncthreads();
    }

    #pragma unroll
    for (int i = 0; i < 4; ++i) {
        const int r0 = rowStart + warp_m + i * 16 + (lane >> 2);
        #pragma unroll
        for (int half = 0; half < 2; ++half) {
            const int r = r0 + half * 8;
            #pragma unroll
            for (int j = 0; j < 4; ++j) {
                const int c0 = colStart + warp_n + j * 8 + (lane & 3) * 2;
                *(float2*)&Cf[(size_t)r * Dn + c0] =
                    make_float2(acc[i][j][half*2] + bias[c0],
                                acc[i][j][half*2+1] + bias[c0 + 1]);
            }
        }
    }
}

// ============================================================================
// Logits HMMA
// ============================================================================
#define LBUF_B     (4 * TILE_B)
#define LOGIT_SMEM (2 * LBUF_B)

__global__ void __launch_bounds__(256)
logits_mma(const __nv_bfloat16* __restrict__ Qh, const __nv_bfloat16* __restrict__ Ql,
           const __nv_bfloat16* __restrict__ Kh, const __nv_bfloat16* __restrict__ Kl,
           float* __restrict__ P)
{
    const int bh = blockIdx.z;
    const int rowStart = blockIdx.y * 128;
    const int colStart = blockIdx.x * 128;
    if (colStart > rowStart) return;

    extern __shared__ char smem_raw[];
    const uint32_t sb = smem_u32(smem_raw);

    const int b = bh >> 4, h = bh & 15;
    const int tid  = threadIdx.x;
    const int wid  = tid >> 5;
    const int lane = tid & 31;
    const int warp_m = (wid & 1) * 64;
    const int warp_n = (wid >> 1) * 32;

    const __nv_bfloat16* gQh = Qh + ((size_t)(b * Sn + rowStart) * Hn + h) * HDn;
    const __nv_bfloat16* gQl = Ql + ((size_t)(b * Sn + rowStart) * Hn + h) * HDn;
    const __nv_bfloat16* gKh = Kh + ((size_t)(b * Sn + colStart) * Hn + h) * HDn;
    const __nv_bfloat16* gKl = Kl + ((size_t)(b * Sn + colStart) * Hn + h) * HDn;

    const uint32_t aoff = (uint32_t)((lane & 15) * ROWB + (lane >> 4) * 16);
    const uint32_t boff = (uint32_t)(((lane & 7) + ((lane >> 4) << 3)) * ROWB
                                     + ((lane >> 3) & 1) * 16);

    float acc[4][4][4];
    #pragma unroll
    for (int i = 0; i < 4; i++)
        #pragma unroll
        for (int j = 0; j < 4; j++)
            #pragma unroll
            for (int r = 0; r < 4; r++) acc[i][j][r] = 0.f;

    {
        const uint32_t bb = sb;
        load_tile(gQh, Dn, bb,            tid);
        load_tile(gQl, Dn, bb + TILE_B,   tid);
        load_tile(gKh, Dn, bb + 2*TILE_B, tid);
        load_tile(gKl, Dn, bb + 3*TILE_B, tid);
        cp_commit();
    }

    #pragma unroll 1
    for (int c = 0; c < 4; ++c) {
        if (c + 1 < 4) {
            const uint32_t bb = sb + ((c + 1) & 1) * LBUF_B;
            const int k0 = (c + 1) * KC;
            load_tile(gQh + k0, Dn, bb,            tid);
            load_tile(gQl + k0, Dn, bb + TILE_B,   tid);
            load_tile(gKh + k0, Dn, bb + 2*TILE_B, tid);
            load_tile(gKl + k0, Dn, bb + 3*TILE_B, tid);
            cp_commit();
            cp_wait<1>();
        } else {
            cp_wait<0>();
        }
        __syncthreads();

        const uint32_t bb  = sb + (c & 1) * LBUF_B;
        const uint32_t sQh = bb,             sQl = bb + TILE_B;
        const uint32_t sKh = bb + 2*TILE_B,  sKl = bb + 3*TILE_B;

        #pragma unroll
        for (int kk = 0; kk < 2; ++kk) {
            const uint32_t kb = (uint32_t)(kk * 32);
            uint32_t afrag[4][4], bH[4][2], bL[4][2];

            #pragma unroll
            for (int i = 0; i < 4; ++i)
                ldsm4(afrag[i], sQh + aoff + kb + (uint32_t)((warp_m + i*16) * ROWB));
            #pragma unroll
            for (int p = 0; p < 2; ++p) {
                uint32_t r[4];
                ldsm4(r, sKh + boff + kb + (uint32_t)((warp_n + p*16) * ROWB));
                bH[p*2][0] = r[0]; bH[p*2][1] = r[1];
                bH[p*2+1][0] = r[2]; bH[p*2+1][1] = r[3];
            }
            #pragma unroll
            for (int i = 0; i < 4; ++i)
                #pragma unroll
                for (int j = 0; j < 4; ++j)
                    mma_bf16(acc[i][j], afrag[i], bH[j]);

            #pragma unroll
            for (int p = 0; p < 2; ++p) {
                uint32_t r[4];
                ldsm4(r, sKl + boff + kb + (uint32_t)((warp_n + p*16) * ROWB));
                bL[p*2][0] = r[0]; bL[p*2][1] = r[1];
                bL[p*2+1][0] = r[2]; bL[p*2+1][1] = r[3];
            }
            #pragma unroll
            for (int i = 0; i < 4; ++i)
                #pragma unroll
                for (int j = 0; j < 4; ++j)
                    mma_bf16(acc[i][j], afrag[i], bL[j]);

            #pragma unroll
            for (int i = 0; i < 4; ++i)
                ldsm4(afrag[i], sQl + aoff + kb + (uint32_t)((warp_m + i*16) * ROWB));
            #pragma unroll
            for (int i = 0; i < 4; ++i)
                #pragma unroll
                for (int j = 0; j < 4; ++j)
                    mma_bf16(acc[i][j], afrag[i], bH[j]);
        }
        __syncthreads();
    }

    const float scale = 0.08838834764831843f;
    float* Pout = P + (size_t)bh * Sn * Sn;
    #pragma unroll
    for (int i = 0; i < 4; ++i) {
        const int s0 = rowStart + warp_m + i * 16 + (lane >> 2);
        #pragma unroll
        for (int half = 0; half < 2; ++half) {
            const int s = s0 + half * 8;
            #pragma unroll
            for (int j = 0; j < 4; ++j) {
                const int t0 = colStart + warp_n + j * 8 + (lane & 3) * 2;
                *(float2*)&Pout[(size_t)s * Sn + t0] =
                    make_float2(acc[i][j][half*2] * scale, acc[i][j][half*2+1] * scale);
            }
        }
    }
}

// ============================================================================
// Softmax
// ============================================================================
__global__ void __launch_bounds__(128)
softmax_kernel(const float* __restrict__ P, __nv_bfloat16* __restrict__ PH,
               __nv_bfloat16* __restrict__ PL)
{
    const size_t row = blockIdx.x;
    const float* p = P + row * Sn;
    const int s = (int)(row & (Sn - 1));
    const int tid = threadIdx.x;
    float4 v = ((const float4*)p)[tid];
    const int t0 = tid * 4;
    v.x = (t0     <= s) ? v.x : -1e9f;
    v.y = (t0 + 1 <= s) ? v.y : -1e9f;
    v.z = (t0 + 2 <= s) ? v.z : -1e9f;
    v.w = (t0 + 3 <= s) ? v.w : -1e9f;

    float mx = fmaxf(fmaxf(v.x, v.y), fmaxf(v.z, v.w));
    #pragma unroll
    for (int o = 16; o; o >>= 1) mx = fmaxf(mx, __shfl_xor_sync(0xffffffffu, mx, o));
    __shared__ float red[4];
    if ((tid & 31) == 0) red[tid >> 5] = mx;
    __syncthreads();
    mx = fmaxf(fmaxf(red[0], red[1]), fmaxf(red[2], red[3]));

    float e0 = expf(v.x - mx), e1 = expf(v.y - mx);
    float e2 = expf(v.z - mx), e3 = expf(v.w - mx);
    float sm = e0 + e1 + e2 + e3;
    #pragma unroll
    for (int o = 16; o; o >>= 1) sm += __shfl_xor_sync(0xffffffffu, sm, o);
    __shared__ float red2[4];
    if ((tid & 31) == 0) red2[tid >> 5] = sm;
    __syncthreads();
    sm = red2[0] + red2[1] + red2[2] + red2[3];

    const float inv = 1.0f / sm;
    float p0 = e0 * inv, p1 = e1 * inv, p2 = e2 * inv, p3 = e3 * inv;

    __nv_bfloat16 h0 = __float2bfloat16(p0), h1 = __float2bfloat16(p1);
    __nv_bfloat16 h2 = __float2bfloat16(p2), h3 = __float2bfloat16(p3);
    __nv_bfloat162* PH2 = (__nv_bfloat162*)(PH + row * Sn);
    __nv_bfloat162* PL2 = (__nv_bfloat162*)(PL + row * Sn);
    PH2[tid*2]   = __halves2bfloat162(h0, h1);
    PH2[tid*2+1] = __halves2bfloat162(h2, h3);
    PL2[tid*2]   = __halves2bfloat162(
        __float2bfloat16(p0 - __bfloat162float(h0)),
        __float2bfloat16(p1 - __bfloat162float(h1)));
    PL2[tid*2+1] = __halves2bfloat162(
        __float2bfloat16(p2 - __bfloat162float(h2)),
        __float2bfloat16(p3 - __bfloat162float(h3)));
}

// ============================================================================
// AV HMMA
// ============================================================================
#define AVBUF_B  (2 * TILE_B + 2 * VTILE_B)
#define AV_SMEM  (2 * AVBUF_B)

__global__ void __launch_bounds__(256)
av_mma(const __nv_bfloat16* __restrict__ Ph, const __nv_bfloat16* __restrict__ Pl,
       const __nv_bfloat16* __restrict__ Vh, const __nv_bfloat16* __restrict__ Vl,
       __nv_bfloat16* __restrict__ Oh, __nv_bfloat16* __restrict__ Ol)
{
    extern __shared__ char smem_raw[];
    const uint32_t sb = smem_u32(smem_raw);

    const int bh = blockIdx.z;
    const int b = bh >> 4, h = bh & 15;
    const int rowStart = blockIdx.y * 128;
    const int tid  = threadIdx.x;
    const int wid  = tid >> 5;
    const int lane = tid & 31;
    const int warp_m = (wid & 1) * 64;
    const int warp_n = (wid >> 1) * 32;

    const __nv_bfloat16* gPh = Ph + (size_t)bh * Sn * Sn + (size_t)rowStart * Sn;
    const __nv_bfloat16* gPl = Pl + (size_t)bh * Sn * Sn + (size_t)rowStart * Sn;
    const __nv_bfloat16* gVh = Vh + (size_t)(b * Sn) * Dn + h * HDn;
    const __nv_bfloat16* gVl = Vl + (size_t)(b * Sn) * Dn + h * HDn;

    const uint32_t aoff  = (uint32_t)((lane & 15) * ROWB + (lane >> 4) * 16);
    const uint32_t boffT = (uint32_t)(((lane & 7) + ((lane >> 3) & 1) * 8) * VROWB
                                      + (lane >> 4) * 16);

    float acc[4][4][4];
    #pragma unroll
    for (int i = 0; i < 4; i++)
        #pragma unroll
        for (int j = 0; j < 4; j++)
            #pragma unroll
            for (int r = 0; r < 4; r++) acc[i][j][r] = 0.f;

    const int nchunk = (blockIdx.y + 1) * 4;

    {
        const uint32_t bb = sb;
        load_tile (gPh, Sn, bb, tid);
        load_tile (gPl, Sn, bb + TILE_B, tid);
        load_vtile(gVh, bb + 2*TILE_B, tid);
        load_vtile(gVl, bb + 2*TILE_B + VTILE_B, tid);
        cp_commit();
    }

    #pragma unroll 1
    for (int c = 0; c < nchunk; ++c) {
        if (c + 1 < nchunk) {
            const uint32_t bb = sb + ((c + 1) & 1) * AVBUF_B;
            const int k0 = (c + 1) * KC;
            load_tile (gPh + k0, Sn, bb, tid);
            load_tile (gPl + k0, Sn, bb + TILE_B, tid);
            load_vtile(gVh + (size_t)k0 * Dn, bb + 2*TILE_B, tid);
            load_vtile(gVl + (size_t)k0 * Dn, bb + 2*TILE_B + VTILE_B, tid);
            cp_commit();
            cp_wait<1>();
        } else {
            cp_wait<0>();
        }
        __syncthreads();

        const uint32_t bb  = sb + (c & 1) * AVBUF_B;
        const uint32_t sPh = bb,            sPl = bb + TILE_B;
        const uint32_t sVh = bb + 2*TILE_B, sVl = bb + 2*TILE_B + VTILE_B;

        #pragma unroll
        for (int kk = 0; kk < 2; ++kk) {
            const uint32_t kbA = (uint32_t)(kk * 32);
            const uint32_t kbB = (uint32_t)(kk * 16 * VROWB);
            uint32_t afrag[4][4], bH[4][2], bL[4][2];

            #pragma unroll
            for (int i = 0; i < 4; ++i)
                ldsm4(afrag[i], sPh + aoff + kbA + (uint32_t)((warp_m + i*16) * ROWB));
            #pragma unroll
            for (int g = 0; g < 2; ++g) {
                uint32_t r[4];
                ldsm4t(r, sVh + boffT + kbB + (uint32_t)((warp_n + g*16) * 2));
                bH[g*2][0] = r[0]; bH[g*2][1] = r[1];
                bH[g*2+1][0] = r[2]; bH[g*2+1][1] = r[3];
            }
            #pragma unroll
            for (int i = 0; i < 4; ++i)
                #pragma unroll
                for (int j = 0; j < 4; ++j)
                    mma_bf16(acc[i][j], afrag[i], bH[j]);

            #pragma unroll
            for (int g = 0; g < 2; ++g) {
                uint32_t r[4];
                ldsm4t(r, sVl + boffT + kbB + (uint32_t)((warp_n + g*16) * 2));
                bL[g*2][0] = r[0]; bL[g*2][1] = r[1];
                bL[g*2+1][0] = r[2]; bL[g*2+1][1] = r[3];
            }
            #pragma unroll
            for (int i = 0; i < 4; ++i)
                #pragma unroll
                for (int j = 0; j < 4; ++j)
                    mma_bf16(acc[i][j], afrag[i], bL[j]);

            #pragma unroll
            for (int i = 0; i < 4; ++i)
                ldsm4(afrag[i], sPl + aoff + kbA + (uint32_t)((warp_m + i*16) * ROWB));
            #pragma unroll
            for (int i = 0; i < 4; ++i)
                #pragma unroll
                for (int j = 0; j < 4; ++j)
                    mma_bf16(acc[i][j], afrag[i], bH[j]);
        }
        __syncthreads();
    }

    #pragma unroll
    for (int i = 0; i < 4; ++i) {
        const int s0 = rowStart + warp_m + i * 16 + (lane >> 2);
        #pragma unroll
        for (int half = 0; half < 2; ++half) {
            const int s = s0 + half * 8;
            const size_t rbase = ((size_t)(b * Sn + s)) * Dn + h * HDn;
            #pragma unroll
            for (int j = 0; j < 4; ++j) {
                const int c0 = warp_n + j * 8 + (lane & 3) * 2;
                split_store(Oh, Ol, rbase + c0, acc[i][j][half*2], acc[i][j][half*2+1]);
            }
        }
    }
}

// ============================================================================
extern "C" void kernel_launch(void* const* d_in, const int* in_sizes, int n_in,
                              void* d_out, int out_size)
{
    const float* x  = (const float*)d_in[0];
    const float* wq = (const float*)d_in[2];
    const float* bq = (const float*)d_in[3];
    const float* wk = (const float*)d_in[4];
    const float* bk = (const float*)d_in[5];
    const float* wv = (const float*)d_in[6];
    const float* bv = (const float*)d_in[7];
    const float* wo = (const float*)d_in[8];
    const float* bo = (const float*)d_in[9];
    float* out = (float*)d_out;

    float* pp;
    __nv_bfloat16 *ahi, *alo, *whi, *wlo, *woh, *wol;
    __nv_bfloat16 *qh, *ql, *kh, *kl, *vh, *vl, *ph, *pl;
    cudaGetSymbolAddress((void**)&pp, g_p);
    cudaGetSymbolAddress((void**)&ahi, g_ahi);
    cudaGetSymbolAddress((void**)&alo, g_alo);
    cudaGetSymbolAddress((void**)&whi, g_whi);
    cudaGetSymbolAddress((void**)&wlo, g_wlo);
    cudaGetSymbolAddress((void**)&woh, g_woh);
    cudaGetSymbolAddress((void**)&wol, g_wol);
    cudaGetSymbolAddress((void**)&qh, g_qh);
    cudaGetSymbolAddress((void**)&ql, g_ql);
    cudaGetSymbolAddress((void**)&kh, g_kh);
    cudaGetSymbolAddress((void**)&kl, g_kl);
    cudaGetSymbolAddress((void**)&vh, g_vh);
    cudaGetSymbolAddress((void**)&vl, g_vl);
    cudaGetSymbolAddress((void**)&ph, g_ph);
    cudaGetSymbolAddress((void**)&pl, g_pl);

    cudaFuncSetAttribute(gemm_qkv,  cudaFuncAttributeMaxDynamicSharedMemorySize, GEMM_SMEM);
    cudaFuncSetAttribute(gemm_wo,   cudaFuncAttributeMaxDynamicSharedMemorySize, GEMM_SMEM);
    cudaFuncSetAttribute(logits_mma, cudaFuncAttributeMaxDynamicSharedMemorySize, LOGIT_SMEM);
    cudaFuncSetAttribute(av_mma,    cudaFuncAttributeMaxDynamicSharedMemorySize, AV_SMEM);

    const int nSplitBlks = (int)(((size_t)Mtot * Dn / 4) / 256);
    dim3 gT(Dn / 32, Dn / 32), bT(32, 8);

    // --- all preprocessing up front (launch #5 = gemm_qkv -> ncu profiles it)
    split_kernel<<<nSplitBlks, 256>>>((const float4*)x, ahi, alo);       // 0
    splitT_kernel<<<gT, bT>>>(wq, whi,              wlo);                // 1
    splitT_kernel<<<gT, bT>>>(wk, whi + (size_t)Dn*Dn,   wlo + (size_t)Dn*Dn);   // 2
    splitT_kernel<<<gT, bT>>>(wv, whi + (size_t)2*Dn*Dn, wlo + (size_t)2*Dn*Dn); // 3
    splitT_kernel<<<gT, bT>>>(wo, woh, wol);                             // 4

    // --- merged QKV projection (one launch, grid 48x64) ---
    dim3 gQKV(3 * Dn / 128, Mtot / 128);                                 // 5
    gemm_qkv<<<gQKV, 256, GEMM_SMEM>>>(ahi, alo, whi, wlo,
                                       bq, bk, bv, qh, ql, kh, kl, vh, vl);

    // --- attention ---
    dim3 glog(Sn / 128, Sn / 128, Bn * Hn);
    logits_mma<<<glog, 256, LOGIT_SMEM>>>(qh, ql, kh, kl, pp);
    softmax_kernel<<<Bn * Hn * Sn, 128>>>(pp, ph, pl);
    dim3 gav(1, Sn / 128, Bn * Hn);
    av_mma<<<gav, 256, AV_SMEM>>>(ph, pl, vh, vl, ahi, alo);

    // --- output projection ---
    dim3 gG(Dn / 128, Mtot / 128);
    gemm_wo<<<gG, 256, GEMM_SMEM>>>(ahi, alo, woh, wol, bo, out);
}

// round 8
// speedup vs baseline: 1.1299x; 1.1299x over previous
#include <cuda_runtime.h>
#include <cuda_bf16.h>
#include <math.h>
#include <stdint.h>

#define Bn   16
#define Sn   512
#define Dn   2048
#define Hn   16
#define HDn  128
#define Mtot (Bn*Sn)      // 8192

// ---------------- scratch (alloc-free: __device__ globals) ----------------
__device__ float g_p[(size_t)Bn * Hn * Sn * Sn];    // 256 MB logits (fp32)
__device__ __nv_bfloat16 g_ahi[(size_t)Mtot * Dn];  // 32 MB (x / attn-out hi)
__device__ __nv_bfloat16 g_alo[(size_t)Mtot * Dn];  // 32 MB
__device__ __nv_bfloat16 g_whi[(size_t)3 * Dn * Dn]; // 24 MB (W^T q|k|v hi)
__device__ __nv_bfloat16 g_wlo[(size_t)3 * Dn * Dn]; // 24 MB
__device__ __nv_bfloat16 g_woh[(size_t)Dn * Dn];     // 8 MB  (W^T o hi)
__device__ __nv_bfloat16 g_wol[(size_t)Dn * Dn];     // 8 MB
__device__ __nv_bfloat16 g_qh[(size_t)Mtot * Dn];
__device__ __nv_bfloat16 g_ql[(size_t)Mtot * Dn];
__device__ __nv_bfloat16 g_kh[(size_t)Mtot * Dn];
__device__ __nv_bfloat16 g_kl[(size_t)Mtot * Dn];
__device__ __nv_bfloat16 g_vh[(size_t)Mtot * Dn];
__device__ __nv_bfloat16 g_vl[(size_t)Mtot * Dn];
__device__ __nv_bfloat16 g_ph[(size_t)Bn * Hn * Sn * Sn];  // 128 MB
__device__ __nv_bfloat16 g_pl[(size_t)Bn * Hn * Sn * Sn];  // 128 MB

// ============================================================================
// PTX helpers (sm_80-compatible subset)
// ============================================================================
__device__ __forceinline__ uint32_t smem_u32(const void* p) {
    uint32_t a;
    asm("{ .reg .u64 t; cvta.to.shared.u64 t, %1; cvt.u32.u64 %0, t; }" : "=r"(a) : "l"(p));
    return a;
}
__device__ __forceinline__ void cp16(uint32_t saddr, const void* gptr) {
    asm volatile("cp.async.cg.shared.global [%0], [%1], 16;" :: "r"(saddr), "l"(gptr) : "memory");
}
__device__ __forceinline__ void cp_commit() {
    asm volatile("cp.async.commit_group;" ::: "memory");
}
template <int N>
__device__ __forceinline__ void cp_wait() {
    asm volatile("cp.async.wait_group %0;" :: "n"(N) : "memory");
}
__device__ __forceinline__ void ldsm4(uint32_t* r, uint32_t addr) {
    asm volatile("ldmatrix.sync.aligned.m8n8.x4.shared.b16 {%0,%1,%2,%3}, [%4];"
                 : "=r"(r[0]), "=r"(r[1]), "=r"(r[2]), "=r"(r[3]) : "r"(addr));
}
__device__ __forceinline__ void ldsm4t(uint32_t* r, uint32_t addr) {
    asm volatile("ldmatrix.sync.aligned.m8n8.x4.trans.shared.b16 {%0,%1,%2,%3}, [%4];"
                 : "=r"(r[0]), "=r"(r[1]), "=r"(r[2]), "=r"(r[3]) : "r"(addr));
}
__device__ __forceinline__ void mma_bf16(float* d, const uint32_t* a, const uint32_t* b) {
    asm volatile("mma.sync.aligned.m16n8k16.row.col.f32.bf16.bf16.f32 "
                 "{%0,%1,%2,%3}, {%4,%5,%6,%7}, {%8,%9}, {%0,%1,%2,%3};"
                 : "+f"(d[0]), "+f"(d[1]), "+f"(d[2]), "+f"(d[3])
                 : "r"(a[0]), "r"(a[1]), "r"(a[2]), "r"(a[3]), "r"(b[0]), "r"(b[1]));
}

// ============================================================================
// Tile geometry
// ============================================================================
#define KC      32
#define ROWB    80                   // bytes/row for 32-bf16 tiles (padded)
#define TILE_B  (128 * ROWB)         // 10240 B
#define VROWB   272                  // bytes/row for 128-bf16 V tiles (padded)
#define VTILE_B (32 * VROWB)         // 8704 B

__device__ __forceinline__ void load_tile(const __nv_bfloat16* __restrict__ g,
                                          int ldg, uint32_t sdst, int tid)
{
    #pragma unroll
    for (int it = 0; it < 2; ++it) {
        int idx = tid + it * 256;
        int row = idx >> 2, seg = idx & 3;
        cp16(sdst + (uint32_t)(row * ROWB + seg * 16),
             (const char*)(g + (size_t)row * ldg) + seg * 16);
    }
}
__device__ __forceinline__ void load_vtile(const __nv_bfloat16* __restrict__ g,
                                           uint32_t sdst, int tid)
{
    #pragma unroll
    for (int it = 0; it < 2; ++it) {
        int idx = tid + it * 256;
        int row = idx >> 4, seg = idx & 15;
        cp16(sdst + (uint32_t)(row * VROWB + seg * 16),
             (const char*)(g + (size_t)row * Dn) + seg * 16);
    }
}

__device__ __forceinline__ void split_store(__nv_bfloat16* __restrict__ OH,
                                            __nv_bfloat16* __restrict__ OL,
                                            size_t off, float v0, float v1)
{
    __nv_bfloat16 h0 = __float2bfloat16(v0), h1 = __float2bfloat16(v1);
    __nv_bfloat16 l0 = __float2bfloat16(v0 - __bfloat162float(h0));
    __nv_bfloat16 l1 = __float2bfloat16(v1 - __bfloat162float(h1));
    *(__nv_bfloat162*)&OH[off] = __halves2bfloat162(h0, h1);
    *(__nv_bfloat162*)&OL[off] = __halves2bfloat162(l0, l1);
}

// ============================================================================
// Split / transpose preprocessing
// ============================================================================
__global__ void __launch_bounds__(256)
split_kernel(const float4* __restrict__ X, __nv_bfloat16* __restrict__ Hh,
             __nv_bfloat16* __restrict__ Hl)
{
    size_t i = (size_t)blockIdx.x * 256 + threadIdx.x;
    float4 v = X[i];
    float hx = __bfloat162float(__float2bfloat16(v.x));
    float hy = __bfloat162float(__float2bfloat16(v.y));
    float hz = __bfloat162float(__float2bfloat16(v.z));
    float hw = __bfloat162float(__float2bfloat16(v.w));
    __nv_bfloat162* H2 = (__nv_bfloat162*)Hh;
    __nv_bfloat162* L2 = (__nv_bfloat162*)Hl;
    H2[2*i]   = __floats2bfloat162_rn(hx, hy);
    H2[2*i+1] = __floats2bfloat162_rn(hz, hw);
    L2[2*i]   = __floats2bfloat162_rn(v.x - hx, v.y - hy);
    L2[2*i+1] = __floats2bfloat162_rn(v.z - hz, v.w - hw);
}

__global__ void __launch_bounds__(256)
splitT_kernel(const float* __restrict__ W, __nv_bfloat16* __restrict__ Th,
              __nv_bfloat16* __restrict__ Tl)
{
    __shared__ float t[32][33];
    int bx = blockIdx.x * 32;   // n
    int by = blockIdx.y * 32;   // k
    int tx = threadIdx.x, ty = threadIdx.y;
    #pragma unroll
    for (int i = 0; i < 32; i += 8)
        t[ty + i][tx] = W[(size_t)(by + ty + i) * Dn + bx + tx];
    __syncthreads();
    #pragma unroll
    for (int i = 0; i < 32; i += 8) {
        float v = t[tx][ty + i];
        float h = __bfloat162float(__float2bfloat16(v));
        size_t o = (size_t)(bx + ty + i) * Dn + by + tx;
        Th[o] = __float2bfloat16(h);
        Tl[o] = __float2bfloat16(v - h);
    }
}

// ============================================================================
// HMMA split-3 projection GEMM. 256 threads, 8 warps, warp tile 64x32,
// CTA tile 128x128 (R4/R6 shape), bH cached across passes 1->3.
// EPI: 0 = bias->fp32, 1 = bias+RoPE->split, 2 = bias->split.
// ============================================================================
#define BUF_B     (4 * TILE_B)
#define GEMM_SMEM (2 * BUF_B)        // 81920

template <int EPI>
__global__ void __launch_bounds__(256)
gemm_mma(const __nv_bfloat16* __restrict__ Ah, const __nv_bfloat16* __restrict__ Al,
         const __nv_bfloat16* __restrict__ Bh, const __nv_bfloat16* __restrict__ Bl,
         const float* __restrict__ bias, float* __restrict__ Cf,
         __nv_bfloat16* __restrict__ Oh, __nv_bfloat16* __restrict__ Ol)
{
    extern __shared__ char smem_raw[];
    const uint32_t sb = smem_u32(smem_raw);

    const int tid  = threadIdx.x;
    const int wid  = tid >> 5;
    const int lane = tid & 31;
    const int rowStart = blockIdx.y * 128;
    const int colStart = blockIdx.x * 128;
    const int warp_m = (wid & 1) * 64;
    const int warp_n = (wid >> 1) * 32;

    const __nv_bfloat16* gA0 = Ah + (size_t)rowStart * Dn;
    const __nv_bfloat16* gA1 = Al + (size_t)rowStart * Dn;
    const __nv_bfloat16* gB0 = Bh + (size_t)colStart * Dn;
    const __nv_bfloat16* gB1 = Bl + (size_t)colStart * Dn;

    const uint32_t aoff = (uint32_t)((lane & 15) * ROWB + (lane >> 4) * 16);
    const uint32_t boff = (uint32_t)(((lane & 7) + ((lane >> 4) << 3)) * ROWB
                                     + ((lane >> 3) & 1) * 16);

    float acc[4][4][4];
    #pragma unroll
    for (int i = 0; i < 4; i++)
        #pragma unroll
        for (int j = 0; j < 4; j++)
            #pragma unroll
            for (int r = 0; r < 4; r++) acc[i][j][r] = 0.f;

    const int NCHUNK = Dn / KC;   // 64

    {
        const uint32_t bb = sb;
        load_tile(gA0, Dn, bb,            tid);
        load_tile(gA1, Dn, bb + TILE_B,   tid);
        load_tile(gB0, Dn, bb + 2*TILE_B, tid);
        load_tile(gB1, Dn, bb + 3*TILE_B, tid);
        cp_commit();
    }

    #pragma unroll 1
    for (int c = 0; c < NCHUNK; ++c) {
        if (c + 1 < NCHUNK) {
            const uint32_t bb = sb + ((c + 1) & 1) * BUF_B;
            const int k0 = (c + 1) * KC;
            load_tile(gA0 + k0, Dn, bb,            tid);
            load_tile(gA1 + k0, Dn, bb + TILE_B,   tid);
            load_tile(gB0 + k0, Dn, bb + 2*TILE_B, tid);
            load_tile(gB1 + k0, Dn, bb + 3*TILE_B, tid);
            cp_commit();
            cp_wait<1>();
        } else {
            cp_wait<0>();
        }
        __syncthreads();

        const uint32_t bb  = sb + (c & 1) * BUF_B;
        const uint32_t sAh = bb,             sAl = bb + TILE_B;
        const uint32_t sBh = bb + 2*TILE_B,  sBl = bb + 3*TILE_B;

        #pragma unroll
        for (int kk = 0; kk < 2; ++kk) {
            const uint32_t kb = (uint32_t)(kk * 32);
            uint32_t afrag[4][4], bH[4][2], bL[4][2];

            // load Ah + Bh; pass 1: Ah x Bh
            #pragma unroll
            for (int i = 0; i < 4; ++i)
                ldsm4(afrag[i], sAh + aoff + kb + (uint32_t)((warp_m + i*16) * ROWB));
            #pragma unroll
            for (int p = 0; p < 2; ++p) {
                uint32_t r[4];
                ldsm4(r, sBh + boff + kb + (uint32_t)((warp_n + p*16) * ROWB));
                bH[p*2][0] = r[0]; bH[p*2][1] = r[1];
                bH[p*2+1][0] = r[2]; bH[p*2+1][1] = r[3];
            }
            #pragma unroll
            for (int i = 0; i < 4; ++i)
                #pragma unroll
                for (int j = 0; j < 4; ++j)
                    mma_bf16(acc[i][j], afrag[i], bH[j]);

            // load Bl; pass 2: Ah x Bl
            #pragma unroll
            for (int p = 0; p < 2; ++p) {
                uint32_t r[4];
                ldsm4(r, sBl + boff + kb + (uint32_t)((warp_n + p*16) * ROWB));
                bL[p*2][0] = r[0]; bL[p*2][1] = r[1];
                bL[p*2+1][0] = r[2]; bL[p*2+1][1] = r[3];
            }
            #pragma unroll
            for (int i = 0; i < 4; ++i)
                #pragma unroll
                for (int j = 0; j < 4; ++j)
                    mma_bf16(acc[i][j], afrag[i], bL[j]);

            // load Al; pass 3: Al x Bh (bH cached)
            #pragma unroll
            for (int i = 0; i < 4; ++i)
                ldsm4(afrag[i], sAl + aoff + kb + (uint32_t)((warp_m + i*16) * ROWB));
            #pragma unroll
            for (int i = 0; i < 4; ++i)
                #pragma unroll
                for (int j = 0; j < 4; ++j)
                    mma_bf16(acc[i][j], afrag[i], bH[j]);
        }
        __syncthreads();
    }

    // ---- epilogue ----
    #pragma unroll
    for (int i = 0; i < 4; ++i) {
        const int r0 = rowStart + warp_m + i * 16 + (lane >> 2);
        #pragma unroll
        for (int half = 0; half < 2; ++half) {
            const int r = r0 + half * 8;
            const int s = r & (Sn - 1);
            #pragma unroll
            for (int j = 0; j < 4; ++j) {
                const int c0 = colStart + warp_n + j * 8 + (lane & 3) * 2;
                float v0 = acc[i][j][half*2]   + bias[c0];
                float v1 = acc[i][j][half*2+1] + bias[c0 + 1];
                if (EPI == 1) {
                    int pidx = (c0 & (HDn - 1)) >> 1;
                    float inv = exp2f((float)pidx * (-13.287712379549449f / 64.0f));
                    float sn, cs;
                    sincosf((float)s * inv, &sn, &cs);
                    float e = v0, o = v1;
                    v0 = e * cs - o * sn;
                    v1 = o * cs + e * sn;
                }
                if (EPI == 0)
                    *(float2*)&Cf[(size_t)r * Dn + c0] = make_float2(v0, v1);
                else
                    split_store(Oh, Ol, (size_t)r * Dn + c0, v0, v1);
            }
        }
    }
}

// ============================================================================
// Logits HMMA
// ============================================================================
#define LBUF_B     (4 * TILE_B)
#define LOGIT_SMEM (2 * LBUF_B)

__global__ void __launch_bounds__(256)
logits_mma(const __nv_bfloat16* __restrict__ Qh, const __nv_bfloat16* __restrict__ Ql,
           const __nv_bfloat16* __restrict__ Kh, const __nv_bfloat16* __restrict__ Kl,
           float* __restrict__ P)
{
    const int bh = blockIdx.z;
    const int rowStart = blockIdx.y * 128;
    const int colStart = blockIdx.x * 128;
    if (colStart > rowStart) return;

    extern __shared__ char smem_raw[];
    const uint32_t sb = smem_u32(smem_raw);

    const int b = bh >> 4, h = bh & 15;
    const int tid  = threadIdx.x;
    const int wid  = tid >> 5;
    const int lane = tid & 31;
    const int warp_m = (wid & 1) * 64;
    const int warp_n = (wid >> 1) * 32;

    const __nv_bfloat16* gQh = Qh + ((size_t)(b * Sn + rowStart) * Hn + h) * HDn;
    const __nv_bfloat16* gQl = Ql + ((size_t)(b * Sn + rowStart) * Hn + h) * HDn;
    const __nv_bfloat16* gKh = Kh + ((size_t)(b * Sn + colStart) * Hn + h) * HDn;
    const __nv_bfloat16* gKl = Kl + ((size_t)(b * Sn + colStart) * Hn + h) * HDn;

    const uint32_t aoff = (uint32_t)((lane & 15) * ROWB + (lane >> 4) * 16);
    const uint32_t boff = (uint32_t)(((lane & 7) + ((lane >> 4) << 3)) * ROWB
                                     + ((lane >> 3) & 1) * 16);

    float acc[4][4][4];
    #pragma unroll
    for (int i = 0; i < 4; i++)
        #pragma unroll
        for (int j = 0; j < 4; j++)
            #pragma unroll
            for (int r = 0; r < 4; r++) acc[i][j][r] = 0.f;

    {
        const uint32_t bb = sb;
        load_tile(gQh, Dn, bb,            tid);
        load_tile(gQl, Dn, bb + TILE_B,   tid);
        load_tile(gKh, Dn, bb + 2*TILE_B, tid);
        load_tile(gKl, Dn, bb + 3*TILE_B, tid);
        cp_commit();
    }

    #pragma unroll 1
    for (int c = 0; c < 4; ++c) {
        if (c + 1 < 4) {
            const uint32_t bb = sb + ((c + 1) & 1) * LBUF_B;
            const int k0 = (c + 1) * KC;
            load_tile(gQh + k0, Dn, bb,            tid);
            load_tile(gQl + k0, Dn, bb + TILE_B,   tid);
            load_tile(gKh + k0, Dn, bb + 2*TILE_B, tid);
            load_tile(gKl + k0, Dn, bb + 3*TILE_B, tid);
            cp_commit();
            cp_wait<1>();
        } else {
            cp_wait<0>();
        }
        __syncthreads();

        const uint32_t bb  = sb + (c & 1) * LBUF_B;
        const uint32_t sQh = bb,             sQl = bb + TILE_B;
        const uint32_t sKh = bb + 2*TILE_B,  sKl = bb + 3*TILE_B;

        #pragma unroll
        for (int kk = 0; kk < 2; ++kk) {
            const uint32_t kb = (uint32_t)(kk * 32);
            uint32_t afrag[4][4], bH[4][2], bL[4][2];

            #pragma unroll
            for (int i = 0; i < 4; ++i)
                ldsm4(afrag[i], sQh + aoff + kb + (uint32_t)((warp_m + i*16) * ROWB));
            #pragma unroll
            for (int p = 0; p < 2; ++p) {
                uint32_t r[4];
                ldsm4(r, sKh + boff + kb + (uint32_t)((warp_n + p*16) * ROWB));
                bH[p*2][0] = r[0]; bH[p*2][1] = r[1];
                bH[p*2+1][0] = r[2]; bH[p*2+1][1] = r[3];
            }
            #pragma unroll
            for (int i = 0; i < 4; ++i)
                #pragma unroll
                for (int j = 0; j < 4; ++j)
                    mma_bf16(acc[i][j], afrag[i], bH[j]);

            #pragma unroll
            for (int p = 0; p < 2; ++p) {
                uint32_t r[4];
                ldsm4(r, sKl + boff + kb + (uint32_t)((warp_n + p*16) * ROWB));
                bL[p*2][0] = r[0]; bL[p*2][1] = r[1];
                bL[p*2+1][0] = r[2]; bL[p*2+1][1] = r[3];
            }
            #pragma unroll
            for (int i = 0; i < 4; ++i)
                #pragma unroll
                for (int j = 0; j < 4; ++j)
                    mma_bf16(acc[i][j], afrag[i], bL[j]);

            #pragma unroll
            for (int i = 0; i < 4; ++i)
                ldsm4(afrag[i], sQl + aoff + kb + (uint32_t)((warp_m + i*16) * ROWB));
            #pragma unroll
            for (int i = 0; i < 4; ++i)
                #pragma unroll
                for (int j = 0; j < 4; ++j)
                    mma_bf16(acc[i][j], afrag[i], bH[j]);
        }
        __syncthreads();
    }

    const float scale = 0.08838834764831843f;
    float* Pout = P + (size_t)bh * Sn * Sn;
    #pragma unroll
    for (int i = 0; i < 4; ++i) {
        const int s0 = rowStart + warp_m + i * 16 + (lane >> 2);
        #pragma unroll
        for (int half = 0; half < 2; ++half) {
            const int s = s0 + half * 8;
            #pragma unroll
            for (int j = 0; j < 4; ++j) {
                const int t0 = colStart + warp_n + j * 8 + (lane & 3) * 2;
                *(float2*)&Pout[(size_t)s * Sn + t0] =
                    make_float2(acc[i][j][half*2] * scale, acc[i][j][half*2+1] * scale);
            }
        }
    }
}

// ============================================================================
// Softmax
// ============================================================================
__global__ void __launch_bounds__(128)
softmax_kernel(const float* __restrict__ P, __nv_bfloat16* __restrict__ PH,
               __nv_bfloat16* __restrict__ PL)
{
    const size_t row = blockIdx.x;
    const float* p = P + row * Sn;
    const int s = (int)(row & (Sn - 1));
    const int tid = threadIdx.x;
    float4 v = ((const float4*)p)[tid];
    const int t0 = tid * 4;
    v.x = (t0     <= s) ? v.x : -1e9f;
    v.y = (t0 + 1 <= s) ? v.y : -1e9f;
    v.z = (t0 + 2 <= s) ? v.z : -1e9f;
    v.w = (t0 + 3 <= s) ? v.w : -1e9f;

    float mx = fmaxf(fmaxf(v.x, v.y), fmaxf(v.z, v.w));
    #pragma unroll
    for (int o = 16; o; o >>= 1) mx = fmaxf(mx, __shfl_xor_sync(0xffffffffu, mx, o));
    __shared__ float red[4];
    if ((tid & 31) == 0) red[tid >> 5] = mx;
    __syncthreads();
    mx = fmaxf(fmaxf(red[0], red[1]), fmaxf(red[2], red[3]));

    float e0 = expf(v.x - mx), e1 = expf(v.y - mx);
    float e2 = expf(v.z - mx), e3 = expf(v.w - mx);
    float sm = e0 + e1 + e2 + e3;
    #pragma unroll
    for (int o = 16; o; o >>= 1) sm += __shfl_xor_sync(0xffffffffu, sm, o);
    __shared__ float red2[4];
    if ((tid & 31) == 0) red2[tid >> 5] = sm;
    __syncthreads();
    sm = red2[0] + red2[1] + red2[2] + red2[3];

    const float inv = 1.0f / sm;
    float p0 = e0 * inv, p1 = e1 * inv, p2 = e2 * inv, p3 = e3 * inv;

    __nv_bfloat16 h0 = __float2bfloat16(p0), h1 = __float2bfloat16(p1);
    __nv_bfloat16 h2 = __float2bfloat16(p2), h3 = __float2bfloat16(p3);
    __nv_bfloat162* PH2 = (__nv_bfloat162*)(PH + row * Sn);
    __nv_bfloat162* PL2 = (__nv_bfloat162*)(PL + row * Sn);
    PH2[tid*2]   = __halves2bfloat162(h0, h1);
    PH2[tid*2+1] = __halves2bfloat162(h2, h3);
    PL2[tid*2]   = __halves2bfloat162(
        __float2bfloat16(p0 - __bfloat162float(h0)),
        __float2bfloat16(p1 - __bfloat162float(h1)));
    PL2[tid*2+1] = __halves2bfloat162(
        __float2bfloat16(p2 - __bfloat162float(h2)),
        __float2bfloat16(p3 - __bfloat162float(h3)));
}

// ============================================================================
// AV HMMA
// ============================================================================
#define AVBUF_B  (2 * TILE_B + 2 * VTILE_B)
#define AV_SMEM  (2 * AVBUF_B)

__global__ void __launch_bounds__(256)
av_mma(const __nv_bfloat16* __restrict__ Ph, const __nv_bfloat16* __restrict__ Pl,
       const __nv_bfloat16* __restrict__ Vh, const __nv_bfloat16* __restrict__ Vl,
       __nv_bfloat16* __restrict__ Oh, __nv_bfloat16* __restrict__ Ol)
{
    extern __shared__ char smem_raw[];
    const uint32_t sb = smem_u32(smem_raw);

    const int bh = blockIdx.z;
    const int b = bh >> 4, h = bh & 15;
    const int rowStart = blockIdx.y * 128;
    const int tid  = threadIdx.x;
    const int wid  = tid >> 5;
    const int lane = tid & 31;
    const int warp_m = (wid & 1) * 64;
    const int warp_n = (wid >> 1) * 32;

    const __nv_bfloat16* gPh = Ph + (size_t)bh * Sn * Sn + (size_t)rowStart * Sn;
    const __nv_bfloat16* gPl = Pl + (size_t)bh * Sn * Sn + (size_t)rowStart * Sn;
    const __nv_bfloat16* gVh = Vh + (size_t)(b * Sn) * Dn + h * HDn;
    const __nv_bfloat16* gVl = Vl + (size_t)(b * Sn) * Dn + h * HDn;

    const uint32_t aoff  = (uint32_t)((lane & 15) * ROWB + (lane >> 4) * 16);
    const uint32_t boffT = (uint32_t)(((lane & 7) + ((lane >> 3) & 1) * 8) * VROWB
                                      + (lane >> 4) * 16);

    float acc[4][4][4];
    #pragma unroll
    for (int i = 0; i < 4; i++)
        #pragma unroll
        for (int j = 0; j < 4; j++)
            #pragma unroll
            for (int r = 0; r < 4; r++) acc[i][j][r] = 0.f;

    const int nchunk = (blockIdx.y + 1) * 4;

    {
        const uint32_t bb = sb;
        load_tile (gPh, Sn, bb, tid);
        load_tile (gPl, Sn, bb + TILE_B, tid);
        load_vtile(gVh, bb + 2*TILE_B, tid);
        load_vtile(gVl, bb + 2*TILE_B + VTILE_B, tid);
        cp_commit();
    }

    #pragma unroll 1
    for (int c = 0; c < nchunk; ++c) {
        if (c + 1 < nchunk) {
            const uint32_t bb = sb + ((c + 1) & 1) * AVBUF_B;
            const int k0 = (c + 1) * KC;
            load_tile (gPh + k0, Sn, bb, tid);
            load_tile (gPl + k0, Sn, bb + TILE_B, tid);
            load_vtile(gVh + (size_t)k0 * Dn, bb + 2*TILE_B, tid);
            load_vtile(gVl + (size_t)k0 * Dn, bb + 2*TILE_B + VTILE_B, tid);
            cp_commit();
            cp_wait<1>();
        } else {
            cp_wait<0>();
        }
        __syncthreads();

        const uint32_t bb  = sb + (c & 1) * AVBUF_B;
        const uint32_t sPh = bb,            sPl = bb + TILE_B;
        const uint32_t sVh = bb + 2*TILE_B, sVl = bb + 2*TILE_B + VTILE_B;

        #pragma unroll
        for (int kk = 0; kk < 2; ++kk) {
            const uint32_t kbA = (uint32_t)(kk * 32);
            const uint32_t kbB = (uint32_t)(kk * 16 * VROWB);
            uint32_t afrag[4][4], bH[4][2], bL[4][2];

            #pragma unroll
            for (int i = 0; i < 4; ++i)
                ldsm4(afrag[i], sPh + aoff + kbA + (uint32_t)((warp_m + i*16) * ROWB));
            #pragma unroll
            for (int g = 0; g < 2; ++g) {
                uint32_t r[4];
                ldsm4t(r, sVh + boffT + kbB + (uint32_t)((warp_n + g*16) * 2));
                bH[g*2][0] = r[0]; bH[g*2][1] = r[1];
                bH[g*2+1][0] = r[2]; bH[g*2+1][1] = r[3];
            }
            #pragma unroll
            for (int i = 0; i < 4; ++i)
                #pragma unroll
                for (int j = 0; j < 4; ++j)
                    mma_bf16(acc[i][j], afrag[i], bH[j]);

            #pragma unroll
            for (int g = 0; g < 2; ++g) {
                uint32_t r[4];
                ldsm4t(r, sVl + boffT + kbB + (uint32_t)((warp_n + g*16) * 2));
                bL[g*2][0] = r[0]; bL[g*2][1] = r[1];
                bL[g*2+1][0] = r[2]; bL[g*2+1][1] = r[3];
            }
            #pragma unroll
            for (int i = 0; i < 4; ++i)
                #pragma unroll
                for (int j = 0; j < 4; ++j)
                    mma_bf16(acc[i][j], afrag[i], bL[j]);

            #pragma unroll
            for (int i = 0; i < 4; ++i)
                ldsm4(afrag[i], sPl + aoff + kbA + (uint32_t)((warp_m + i*16) * ROWB));
            #pragma unroll
            for (int i = 0; i < 4; ++i)
                #pragma unroll
                for (int j = 0; j < 4; ++j)
                    mma_bf16(acc[i][j], afrag[i], bH[j]);
        }
        __syncthreads();
    }

    #pragma unroll
    for (int i = 0; i < 4; ++i) {
        const int s0 = rowStart + warp_m + i * 16 + (lane >> 2);
        #pragma unroll
        for (int half = 0; half < 2; ++half) {
            const int s = s0 + half * 8;
            const size_t rbase = ((size_t)(b * Sn + s)) * Dn + h * HDn;
            #pragma unroll
            for (int j = 0; j < 4; ++j) {
                const int c0 = warp_n + j * 8 + (lane & 3) * 2;
                split_store(Oh, Ol, rbase + c0, acc[i][j][half*2], acc[i][j][half*2+1]);
            }
        }
    }
}

// ============================================================================
extern "C" void kernel_launch(void* const* d_in, const int* in_sizes, int n_in,
                              void* d_out, int out_size)
{
    const float* x  = (const float*)d_in[0];
    const float* wq = (const float*)d_in[2];
    const float* bq = (const float*)d_in[3];
    const float* wk = (const float*)d_in[4];
    const float* bk = (const float*)d_in[5];
    const float* wv = (const float*)d_in[6];
    const float* bv = (const float*)d_in[7];
    const float* wo = (const float*)d_in[8];
    const float* bo = (const float*)d_in[9];
    float* out = (float*)d_out;

    float* pp;
    __nv_bfloat16 *ahi, *alo, *whi, *wlo, *woh, *wol;
    __nv_bfloat16 *qh, *ql, *kh, *kl, *vh, *vl, *ph, *pl;
    cudaGetSymbolAddress((void**)&pp, g_p);
    cudaGetSymbolAddress((void**)&ahi, g_ahi);
    cudaGetSymbolAddress((void**)&alo, g_alo);
    cudaGetSymbolAddress((void**)&whi, g_whi);
    cudaGetSymbolAddress((void**)&wlo, g_wlo);
    cudaGetSymbolAddress((void**)&woh, g_woh);
    cudaGetSymbolAddress((void**)&wol, g_wol);
    cudaGetSymbolAddress((void**)&qh, g_qh);
    cudaGetSymbolAddress((void**)&ql, g_ql);
    cudaGetSymbolAddress((void**)&kh, g_kh);
    cudaGetSymbolAddress((void**)&kl, g_kl);
    cudaGetSymbolAddress((void**)&vh, g_vh);
    cudaGetSymbolAddress((void**)&vl, g_vl);
    cudaGetSymbolAddress((void**)&ph, g_ph);
    cudaGetSymbolAddress((void**)&pl, g_pl);

    cudaFuncSetAttribute(gemm_mma<0>, cudaFuncAttributeMaxDynamicSharedMemorySize, GEMM_SMEM);
    cudaFuncSetAttribute(gemm_mma<1>, cudaFuncAttributeMaxDynamicSharedMemorySize, GEMM_SMEM);
    cudaFuncSetAttribute(gemm_mma<2>, cudaFuncAttributeMaxDynamicSharedMemorySize, GEMM_SMEM);
    cudaFuncSetAttribute(logits_mma, cudaFuncAttributeMaxDynamicSharedMemorySize, LOGIT_SMEM);
    cudaFuncSetAttribute(av_mma,    cudaFuncAttributeMaxDynamicSharedMemorySize, AV_SMEM);

    const int nSplitBlks = (int)(((size_t)Mtot * Dn / 4) / 256);
    dim3 gT(Dn / 32, Dn / 32), bT(32, 8);
    dim3 gG(Dn / 128, Mtot / 128);   // (16, 64)

    const size_t WSZ = (size_t)Dn * Dn;

    // --- all preprocessing up front (launch #5 = gemm_mma<1> -> ncu target)
    split_kernel<<<nSplitBlks, 256>>>((const float4*)x, ahi, alo);   // 0
    splitT_kernel<<<gT, bT>>>(wq, whi,         wlo);                 // 1
    splitT_kernel<<<gT, bT>>>(wk, whi + WSZ,   wlo + WSZ);           // 2
    splitT_kernel<<<gT, bT>>>(wv, whi + 2*WSZ, wlo + 2*WSZ);         // 3
    splitT_kernel<<<gT, bT>>>(wo, woh, wol);                         // 4

    // --- separate Q/K/V projections (W stays L2-resident per kernel) ---
    gemm_mma<1><<<gG, 256, GEMM_SMEM>>>(ahi, alo, whi,         wlo,         bq, nullptr, qh, ql); // 5
    gemm_mma<1><<<gG, 256, GEMM_SMEM>>>(ahi, alo, whi + WSZ,   wlo + WSZ,   bk, nullptr, kh, kl);
    gemm_mma<2><<<gG, 256, GEMM_SMEM>>>(ahi, alo, whi + 2*WSZ, wlo + 2*WSZ, bv, nullptr, vh, vl);

    // --- attention ---
    dim3 glog(Sn / 128, Sn / 128, Bn * Hn);
    logits_mma<<<glog, 256, LOGIT_SMEM>>>(qh, ql, kh, kl, pp);
    softmax_kernel<<<Bn * Hn * Sn, 128>>>(pp, ph, pl);
    dim3 gav(1, Sn / 128, Bn * Hn);
    av_mma<<<gav, 256, AV_SMEM>>>(ph, pl, vh, vl, ahi, alo);

    // --- output projection ---
    gemm_mma<0><<<gG, 256, GEMM_SMEM>>>(ahi, alo, woh, wol, bo, out, nullptr, nullptr);
}

// round 9
// speedup vs baseline: 1.5377x; 1.3609x over previous
#include <cuda_runtime.h>
#include <cuda_bf16.h>
#include <cuda_fp16.h>
#include <math.h>
#include <stdint.h>

#define Bn   16
#define Sn   512
#define Dn   2048
#define Hn   16
#define HDn  128
#define Mtot (Bn*Sn)      // 8192

// ---------------- scratch (alloc-free: __device__ globals) ----------------
__device__ float g_p[(size_t)Bn * Hn * Sn * Sn];     // 256 MB logits (fp32)
__device__ __half g_x16[(size_t)Mtot * Dn];          // 32 MB x (fp16)
__device__ __half g_o16[(size_t)Mtot * Dn];          // 32 MB attn-out (fp16)
__device__ __half g_whi[(size_t)3 * Dn * Dn];        // 24 MB W^T q|k|v hi
__device__ __half g_wlo[(size_t)3 * Dn * Dn];        // 24 MB W^T q|k|v lo
__device__ __half g_woh[(size_t)Dn * Dn];            // 8 MB  W^T o hi
__device__ __half g_wol[(size_t)Dn * Dn];            // 8 MB  W^T o lo
__device__ __nv_bfloat16 g_qh[(size_t)Mtot * Dn];
__device__ __nv_bfloat16 g_ql[(size_t)Mtot * Dn];
__device__ __nv_bfloat16 g_kh[(size_t)Mtot * Dn];
__device__ __nv_bfloat16 g_kl[(size_t)Mtot * Dn];
__device__ __nv_bfloat16 g_vh[(size_t)Mtot * Dn];
__device__ __nv_bfloat16 g_vl[(size_t)Mtot * Dn];
__device__ __nv_bfloat16 g_ph[(size_t)Bn * Hn * Sn * Sn];  // 128 MB
__device__ __nv_bfloat16 g_pl[(size_t)Bn * Hn * Sn * Sn];  // 128 MB

// ============================================================================
// PTX helpers (sm_80-compatible subset)
// ============================================================================
__device__ __forceinline__ uint32_t smem_u32(const void* p) {
    uint32_t a;
    asm("{ .reg .u64 t; cvta.to.shared.u64 t, %1; cvt.u32.u64 %0, t; }" : "=r"(a) : "l"(p));
    return a;
}
__device__ __forceinline__ void cp16(uint32_t saddr, const void* gptr) {
    asm volatile("cp.async.cg.shared.global [%0], [%1], 16;" :: "r"(saddr), "l"(gptr) : "memory");
}
__device__ __forceinline__ void cp_commit() {
    asm volatile("cp.async.commit_group;" ::: "memory");
}
template <int N>
__device__ __forceinline__ void cp_wait() {
    asm volatile("cp.async.wait_group %0;" :: "n"(N) : "memory");
}
__device__ __forceinline__ void ldsm4(uint32_t* r, uint32_t addr) {
    asm volatile("ldmatrix.sync.aligned.m8n8.x4.shared.b16 {%0,%1,%2,%3}, [%4];"
                 : "=r"(r[0]), "=r"(r[1]), "=r"(r[2]), "=r"(r[3]) : "r"(addr));
}
__device__ __forceinline__ void ldsm4t(uint32_t* r, uint32_t addr) {
    asm volatile("ldmatrix.sync.aligned.m8n8.x4.trans.shared.b16 {%0,%1,%2,%3}, [%4];"
                 : "=r"(r[0]), "=r"(r[1]), "=r"(r[2]), "=r"(r[3]) : "r"(addr));
}
__device__ __forceinline__ void mma_bf16(float* d, const uint32_t* a, const uint32_t* b) {
    asm volatile("mma.sync.aligned.m16n8k16.row.col.f32.bf16.bf16.f32 "
                 "{%0,%1,%2,%3}, {%4,%5,%6,%7}, {%8,%9}, {%0,%1,%2,%3};"
                 : "+f"(d[0]), "+f"(d[1]), "+f"(d[2]), "+f"(d[3])
                 : "r"(a[0]), "r"(a[1]), "r"(a[2]), "r"(a[3]), "r"(b[0]), "r"(b[1]));
}
__device__ __forceinline__ void mma_f16(float* d, const uint32_t* a, const uint32_t* b) {
    asm volatile("mma.sync.aligned.m16n8k16.row.col.f32.f16.f16.f32 "
                 "{%0,%1,%2,%3}, {%4,%5,%6,%7}, {%8,%9}, {%0,%1,%2,%3};"
                 : "+f"(d[0]), "+f"(d[1]), "+f"(d[2]), "+f"(d[3])
                 : "r"(a[0]), "r"(a[1]), "r"(a[2]), "r"(a[3]), "r"(b[0]), "r"(b[1]));
}

// ============================================================================
// Tile geometry
// ============================================================================
#define KC      32
#define ROWB    80                   // bytes/row for 32-elem 16-bit tiles
#define TILE_B  (128 * ROWB)         // 10240 B
#define VROWB   272                  // bytes/row for 128-bf16 V tiles
#define VTILE_B (32 * VROWB)         // 8704 B

template <typename T>
__device__ __forceinline__ void load_tile(const T* __restrict__ g,
                                          int ldg, uint32_t sdst, int tid)
{
    #pragma unroll
    for (int it = 0; it < 2; ++it) {
        int idx = tid + it * 256;
        int row = idx >> 2, seg = idx & 3;
        cp16(sdst + (uint32_t)(row * ROWB + seg * 16),
             (const char*)(g + (size_t)row * ldg) + seg * 16);
    }
}
__device__ __forceinline__ void load_vtile(const __nv_bfloat16* __restrict__ g,
                                           uint32_t sdst, int tid)
{
    #pragma unroll
    for (int it = 0; it < 2; ++it) {
        int idx = tid + it * 256;
        int row = idx >> 4, seg = idx & 15;
        cp16(sdst + (uint32_t)(row * VROWB + seg * 16),
             (const char*)(g + (size_t)row * Dn) + seg * 16);
    }
}

__device__ __forceinline__ void split_store(__nv_bfloat16* __restrict__ OH,
                                            __nv_bfloat16* __restrict__ OL,
                                            size_t off, float v0, float v1)
{
    __nv_bfloat16 h0 = __float2bfloat16(v0), h1 = __float2bfloat16(v1);
    __nv_bfloat16 l0 = __float2bfloat16(v0 - __bfloat162float(h0));
    __nv_bfloat16 l1 = __float2bfloat16(v1 - __bfloat162float(h1));
    *(__nv_bfloat162*)&OH[off] = __halves2bfloat162(h0, h1);
    *(__nv_bfloat162*)&OL[off] = __halves2bfloat162(l0, l1);
}

// ============================================================================
// Preprocessing: x -> fp16 single; W -> fp16 hi/lo transposed split
// ============================================================================
__global__ void __launch_bounds__(256)
half_kernel(const float4* __restrict__ X, __half* __restrict__ H)
{
    size_t i = (size_t)blockIdx.x * 256 + threadIdx.x;
    float4 v = X[i];
    __half2* H2 = (__half2*)H;
    H2[2*i]   = __floats2half2_rn(v.x, v.y);
    H2[2*i+1] = __floats2half2_rn(v.z, v.w);
}

__global__ void __launch_bounds__(256)
splitT_kernel(const float* __restrict__ W, __half* __restrict__ Th,
              __half* __restrict__ Tl)
{
    __shared__ float t[32][33];
    int bx = blockIdx.x * 32;   // n
    int by = blockIdx.y * 32;   // k
    int tx = threadIdx.x, ty = threadIdx.y;
    #pragma unroll
    for (int i = 0; i < 32; i += 8)
        t[ty + i][tx] = W[(size_t)(by + ty + i) * Dn + bx + tx];
    __syncthreads();
    #pragma unroll
    for (int i = 0; i < 32; i += 8) {
        float v = t[tx][ty + i];
        __half h = __float2half_rn(v);
        size_t o = (size_t)(bx + ty + i) * Dn + by + tx;
        Th[o] = h;
        Tl[o] = __float2half_rn(v - __half2float(h));
    }
}

// ============================================================================
// fp16 A-single / B-split-2 projection GEMM. 256 threads, 8 warps, warp tile
// 64x32, CTA tile 128x128. Per kk: ldsm A, ldsm Bh -> 16 mma, ldsm Bl -> 16 mma.
// EPI: 0 = bias->fp32, 1 = bias+RoPE->bf16 split, 2 = bias->bf16 split.
// ============================================================================
#define BUF_B     (3 * TILE_B)       // A, Bh, Bl
#define GEMM_SMEM (2 * BUF_B)        // 61440

template <int EPI>
__global__ void __launch_bounds__(256)
gemm_f16(const __half* __restrict__ A,
         const __half* __restrict__ Bh, const __half* __restrict__ Bl,
         const float* __restrict__ bias, float* __restrict__ Cf,
         __nv_bfloat16* __restrict__ Oh, __nv_bfloat16* __restrict__ Ol)
{
    extern __shared__ char smem_raw[];
    const uint32_t sb = smem_u32(smem_raw);

    const int tid  = threadIdx.x;
    const int wid  = tid >> 5;
    const int lane = tid & 31;
    const int rowStart = blockIdx.y * 128;
    const int colStart = blockIdx.x * 128;
    const int warp_m = (wid & 1) * 64;
    const int warp_n = (wid >> 1) * 32;

    const __half* gA  = A  + (size_t)rowStart * Dn;
    const __half* gB0 = Bh + (size_t)colStart * Dn;
    const __half* gB1 = Bl + (size_t)colStart * Dn;

    const uint32_t aoff = (uint32_t)((lane & 15) * ROWB + (lane >> 4) * 16);
    const uint32_t boff = (uint32_t)(((lane & 7) + ((lane >> 4) << 3)) * ROWB
                                     + ((lane >> 3) & 1) * 16);

    float acc[4][4][4];
    #pragma unroll
    for (int i = 0; i < 4; i++)
        #pragma unroll
        for (int j = 0; j < 4; j++)
            #pragma unroll
            for (int r = 0; r < 4; r++) acc[i][j][r] = 0.f;

    const int NCHUNK = Dn / KC;   // 64

    {
        const uint32_t bb = sb;
        load_tile(gA,  Dn, bb,            tid);
        load_tile(gB0, Dn, bb + TILE_B,   tid);
        load_tile(gB1, Dn, bb + 2*TILE_B, tid);
        cp_commit();
    }

    #pragma unroll 1
    for (int c = 0; c < NCHUNK; ++c) {
        if (c + 1 < NCHUNK) {
            const uint32_t bb = sb + ((c + 1) & 1) * BUF_B;
            const int k0 = (c + 1) * KC;
            load_tile(gA  + k0, Dn, bb,            tid);
            load_tile(gB0 + k0, Dn, bb + TILE_B,   tid);
            load_tile(gB1 + k0, Dn, bb + 2*TILE_B, tid);
            cp_commit();
            cp_wait<1>();
        } else {
            cp_wait<0>();
        }
        __syncthreads();

        const uint32_t bb  = sb + (c & 1) * BUF_B;
        const uint32_t sA  = bb;
        const uint32_t sBh = bb + TILE_B;
        const uint32_t sBl = bb + 2*TILE_B;

        #pragma unroll
        for (int kk = 0; kk < 2; ++kk) {
            const uint32_t kb = (uint32_t)(kk * 32);
            uint32_t afrag[4][4], bfrag[4][2];

            #pragma unroll
            for (int i = 0; i < 4; ++i)
                ldsm4(afrag[i], sA + aoff + kb + (uint32_t)((warp_m + i*16) * ROWB));

            // pass 1: A x Bh
            #pragma unroll
            for (int p = 0; p < 2; ++p) {
                uint32_t r[4];
                ldsm4(r, sBh + boff + kb + (uint32_t)((warp_n + p*16) * ROWB));
                bfrag[p*2][0] = r[0]; bfrag[p*2][1] = r[1];
                bfrag[p*2+1][0] = r[2]; bfrag[p*2+1][1] = r[3];
            }
            #pragma unroll
            for (int i = 0; i < 4; ++i)
                #pragma unroll
                for (int j = 0; j < 4; ++j)
                    mma_f16(acc[i][j], afrag[i], bfrag[j]);

            // pass 2: A x Bl
            #pragma unroll
            for (int p = 0; p < 2; ++p) {
                uint32_t r[4];
                ldsm4(r, sBl + boff + kb + (uint32_t)((warp_n + p*16) * ROWB));
                bfrag[p*2][0] = r[0]; bfrag[p*2][1] = r[1];
                bfrag[p*2+1][0] = r[2]; bfrag[p*2+1][1] = r[3];
            }
            #pragma unroll
            for (int i = 0; i < 4; ++i)
                #pragma unroll
                for (int j = 0; j < 4; ++j)
                    mma_f16(acc[i][j], afrag[i], bfrag[j]);
        }
        __syncthreads();
    }

    // ---- epilogue ----
    #pragma unroll
    for (int i = 0; i < 4; ++i) {
        const int r0 = rowStart + warp_m + i * 16 + (lane >> 2);
        #pragma unroll
        for (int half = 0; half < 2; ++half) {
            const int r = r0 + half * 8;
            const int s = r & (Sn - 1);
            #pragma unroll
            for (int j = 0; j < 4; ++j) {
                const int c0 = colStart + warp_n + j * 8 + (lane & 3) * 2;
                float v0 = acc[i][j][half*2]   + bias[c0];
                float v1 = acc[i][j][half*2+1] + bias[c0 + 1];
                if (EPI == 1) {
                    int pidx = (c0 & (HDn - 1)) >> 1;
                    float inv = exp2f((float)pidx * (-13.287712379549449f / 64.0f));
                    float sn, cs;
                    sincosf((float)s * inv, &sn, &cs);
                    float e = v0, o = v1;
                    v0 = e * cs - o * sn;
                    v1 = o * cs + e * sn;
                }
                if (EPI == 0)
                    *(float2*)&Cf[(size_t)r * Dn + c0] = make_float2(v0, v1);
                else
                    split_store(Oh, Ol, (size_t)r * Dn + c0, v0, v1);
            }
        }
    }
}

// ============================================================================
// Logits HMMA (bf16 split-3, unchanged)
// ============================================================================
#define LBUF_B     (4 * TILE_B)
#define LOGIT_SMEM (2 * LBUF_B)

__global__ void __launch_bounds__(256)
logits_mma(const __nv_bfloat16* __restrict__ Qh, const __nv_bfloat16* __restrict__ Ql,
           const __nv_bfloat16* __restrict__ Kh, const __nv_bfloat16* __restrict__ Kl,
           float* __restrict__ P)
{
    const int bh = blockIdx.z;
    const int rowStart = blockIdx.y * 128;
    const int colStart = blockIdx.x * 128;
    if (colStart > rowStart) return;

    extern __shared__ char smem_raw[];
    const uint32_t sb = smem_u32(smem_raw);

    const int b = bh >> 4, h = bh & 15;
    const int tid  = threadIdx.x;
    const int wid  = tid >> 5;
    const int lane = tid & 31;
    const int warp_m = (wid & 1) * 64;
    const int warp_n = (wid >> 1) * 32;

    const __nv_bfloat16* gQh = Qh + ((size_t)(b * Sn + rowStart) * Hn + h) * HDn;
    const __nv_bfloat16* gQl = Ql + ((size_t)(b * Sn + rowStart) * Hn + h) * HDn;
    const __nv_bfloat16* gKh = Kh + ((size_t)(b * Sn + colStart) * Hn + h) * HDn;
    const __nv_bfloat16* gKl = Kl + ((size_t)(b * Sn + colStart) * Hn + h) * HDn;

    const uint32_t aoff = (uint32_t)((lane & 15) * ROWB + (lane >> 4) * 16);
    const uint32_t boff = (uint32_t)(((lane & 7) + ((lane >> 4) << 3)) * ROWB
                                     + ((lane >> 3) & 1) * 16);

    float acc[4][4][4];
    #pragma unroll
    for (int i = 0; i < 4; i++)
        #pragma unroll
        for (int j = 0; j < 4; j++)
            #pragma unroll
            for (int r = 0; r < 4; r++) acc[i][j][r] = 0.f;

    {
        const uint32_t bb = sb;
        load_tile(gQh, Dn, bb,            tid);
        load_tile(gQl, Dn, bb + TILE_B,   tid);
        load_tile(gKh, Dn, bb + 2*TILE_B, tid);
        load_tile(gKl, Dn, bb + 3*TILE_B, tid);
        cp_commit();
    }

    #pragma unroll 1
    for (int c = 0; c < 4; ++c) {
        if (c + 1 < 4) {
            const uint32_t bb = sb + ((c + 1) & 1) * LBUF_B;
            const int k0 = (c + 1) * KC;
            load_tile(gQh + k0, Dn, bb,            tid);
            load_tile(gQl + k0, Dn, bb + TILE_B,   tid);
            load_tile(gKh + k0, Dn, bb + 2*TILE_B, tid);
            load_tile(gKl + k0, Dn, bb + 3*TILE_B, tid);
            cp_commit();
            cp_wait<1>();
        } else {
            cp_wait<0>();
        }
        __syncthreads();

        const uint32_t bb  = sb + (c & 1) * LBUF_B;
        const uint32_t sQh = bb,             sQl = bb + TILE_B;
        const uint32_t sKh = bb + 2*TILE_B,  sKl = bb + 3*TILE_B;

        #pragma unroll
        for (int kk = 0; kk < 2; ++kk) {
            const uint32_t kb = (uint32_t)(kk * 32);
            uint32_t afrag[4][4], bH[4][2], bL[4][2];

            #pragma unroll
            for (int i = 0; i < 4; ++i)
                ldsm4(afrag[i], sQh + aoff + kb + (uint32_t)((warp_m + i*16) * ROWB));
            #pragma unroll
            for (int p = 0; p < 2; ++p) {
                uint32_t r[4];
                ldsm4(r, sKh + boff + kb + (uint32_t)((warp_n + p*16) * ROWB));
                bH[p*2][0] = r[0]; bH[p*2][1] = r[1];
                bH[p*2+1][0] = r[2]; bH[p*2+1][1] = r[3];
            }
            #pragma unroll
            for (int i = 0; i < 4; ++i)
                #pragma unroll
                for (int j = 0; j < 4; ++j)
                    mma_bf16(acc[i][j], afrag[i], bH[j]);

            #pragma unroll
            for (int p = 0; p < 2; ++p) {
                uint32_t r[4];
                ldsm4(r, sKl + boff + kb + (uint32_t)((warp_n + p*16) * ROWB));
                bL[p*2][0] = r[0]; bL[p*2][1] = r[1];
                bL[p*2+1][0] = r[2]; bL[p*2+1][1] = r[3];
            }
            #pragma unroll
            for (int i = 0; i < 4; ++i)
                #pragma unroll
                for (int j = 0; j < 4; ++j)
                    mma_bf16(acc[i][j], afrag[i], bL[j]);

            #pragma unroll
            for (int i = 0; i < 4; ++i)
                ldsm4(afrag[i], sQl + aoff + kb + (uint32_t)((warp_m + i*16) * ROWB));
            #pragma unroll
            for (int i = 0; i < 4; ++i)
                #pragma unroll
                for (int j = 0; j < 4; ++j)
                    mma_bf16(acc[i][j], afrag[i], bH[j]);
        }
        __syncthreads();
    }

    const float scale = 0.08838834764831843f;
    float* Pout = P + (size_t)bh * Sn * Sn;
    #pragma unroll
    for (int i = 0; i < 4; ++i) {
        const int s0 = rowStart + warp_m + i * 16 + (lane >> 2);
        #pragma unroll
        for (int half = 0; half < 2; ++half) {
            const int s = s0 + half * 8;
            #pragma unroll
            for (int j = 0; j < 4; ++j) {
                const int t0 = colStart + warp_n + j * 8 + (lane & 3) * 2;
                *(float2*)&Pout[(size_t)s * Sn + t0] =
                    make_float2(acc[i][j][half*2] * scale, acc[i][j][half*2+1] * scale);
            }
        }
    }
}

// ============================================================================
// Softmax (bf16 split probs, unchanged)
// ============================================================================
__global__ void __launch_bounds__(128)
softmax_kernel(const float* __restrict__ P, __nv_bfloat16* __restrict__ PH,
               __nv_bfloat16* __restrict__ PL)
{
    const size_t row = blockIdx.x;
    const float* p = P + row * Sn;
    const int s = (int)(row & (Sn - 1));
    const int tid = threadIdx.x;
    float4 v = ((const float4*)p)[tid];
    const int t0 = tid * 4;
    v.x = (t0     <= s) ? v.x : -1e9f;
    v.y = (t0 + 1 <= s) ? v.y : -1e9f;
    v.z = (t0 + 2 <= s) ? v.z : -1e9f;
    v.w = (t0 + 3 <= s) ? v.w : -1e9f;

    float mx = fmaxf(fmaxf(v.x, v.y), fmaxf(v.z, v.w));
    #pragma unroll
    for (int o = 16; o; o >>= 1) mx = fmaxf(mx, __shfl_xor_sync(0xffffffffu, mx, o));
    __shared__ float red[4];
    if ((tid & 31) == 0) red[tid >> 5] = mx;
    __syncthreads();
    mx = fmaxf(fmaxf(red[0], red[1]), fmaxf(red[2], red[3]));

    float e0 = expf(v.x - mx), e1 = expf(v.y - mx);
    float e2 = expf(v.z - mx), e3 = expf(v.w - mx);
    float sm = e0 + e1 + e2 + e3;
    #pragma unroll
    for (int o = 16; o; o >>= 1) sm += __shfl_xor_sync(0xffffffffu, sm, o);
    __shared__ float red2[4];
    if ((tid & 31) == 0) red2[tid >> 5] = sm;
    __syncthreads();
    sm = red2[0] + red2[1] + red2[2] + red2[3];

    const float inv = 1.0f / sm;
    float p0 = e0 * inv, p1 = e1 * inv, p2 = e2 * inv, p3 = e3 * inv;

    __nv_bfloat16 h0 = __float2bfloat16(p0), h1 = __float2bfloat16(p1);
    __nv_bfloat16 h2 = __float2bfloat16(p2), h3 = __float2bfloat16(p3);
    __nv_bfloat162* PH2 = (__nv_bfloat162*)(PH + row * Sn);
    __nv_bfloat162* PL2 = (__nv_bfloat162*)(PL + row * Sn);
    PH2[tid*2]   = __halves2bfloat162(h0, h1);
    PH2[tid*2+1] = __halves2bfloat162(h2, h3);
    PL2[tid*2]   = __halves2bfloat162(
        __float2bfloat16(p0 - __bfloat162float(h0)),
        __float2bfloat16(p1 - __bfloat162float(h1)));
    PL2[tid*2+1] = __halves2bfloat162(
        __float2bfloat16(p2 - __bfloat162float(h2)),
        __float2bfloat16(p3 - __bfloat162float(h3)));
}

// ============================================================================
// AV HMMA (bf16 split-3 mainloop; fp16 single output for WO GEMM)
// ============================================================================
#define AVBUF_B  (2 * TILE_B + 2 * VTILE_B)
#define AV_SMEM  (2 * AVBUF_B)

__global__ void __launch_bounds__(256)
av_mma(const __nv_bfloat16* __restrict__ Ph, const __nv_bfloat16* __restrict__ Pl,
       const __nv_bfloat16* __restrict__ Vh, const __nv_bfloat16* __restrict__ Vl,
       __half* __restrict__ O16)
{
    extern __shared__ char smem_raw[];
    const uint32_t sb = smem_u32(smem_raw);

    const int bh = blockIdx.z;
    const int b = bh >> 4, h = bh & 15;
    const int rowStart = blockIdx.y * 128;
    const int tid  = threadIdx.x;
    const int wid  = tid >> 5;
    const int lane = tid & 31;
    const int warp_m = (wid & 1) * 64;
    const int warp_n = (wid >> 1) * 32;

    const __nv_bfloat16* gPh = Ph + (size_t)bh * Sn * Sn + (size_t)rowStart * Sn;
    const __nv_bfloat16* gPl = Pl + (size_t)bh * Sn * Sn + (size_t)rowStart * Sn;
    const __nv_bfloat16* gVh = Vh + (size_t)(b * Sn) * Dn + h * HDn;
    const __nv_bfloat16* gVl = Vl + (size_t)(b * Sn) * Dn + h * HDn;

    const uint32_t aoff  = (uint32_t)((lane & 15) * ROWB + (lane >> 4) * 16);
    const uint32_t boffT = (uint32_t)(((lane & 7) + ((lane >> 3) & 1) * 8) * VROWB
                                      + (lane >> 4) * 16);

    float acc[4][4][4];
    #pragma unroll
    for (int i = 0; i < 4; i++)
        #pragma unroll
        for (int j = 0; j < 4; j++)
            #pragma unroll
            for (int r = 0; r < 4; r++) acc[i][j][r] = 0.f;

    const int nchunk = (blockIdx.y + 1) * 4;

    {
        const uint32_t bb = sb;
        load_tile (gPh, Sn, bb, tid);
        load_tile (gPl, Sn, bb + TILE_B, tid);
        load_vtile(gVh, bb + 2*TILE_B, tid);
        load_vtile(gVl, bb + 2*TILE_B + VTILE_B, tid);
        cp_commit();
    }

    #pragma unroll 1
    for (int c = 0; c < nchunk; ++c) {
        if (c + 1 < nchunk) {
            const uint32_t bb = sb + ((c + 1) & 1) * AVBUF_B;
            const int k0 = (c + 1) * KC;
            load_tile (gPh + k0, Sn, bb, tid);
            load_tile (gPl + k0, Sn, bb + TILE_B, tid);
            load_vtile(gVh + (size_t)k0 * Dn, bb + 2*TILE_B, tid);
            load_vtile(gVl + (size_t)k0 * Dn, bb + 2*TILE_B + VTILE_B, tid);
            cp_commit();
            cp_wait<1>();
        } else {
            cp_wait<0>();
        }
        __syncthreads();

        const uint32_t bb  = sb + (c & 1) * AVBUF_B;
        const uint32_t sPh = bb,            sPl = bb + TILE_B;
        const uint32_t sVh = bb + 2*TILE_B, sVl = bb + 2*TILE_B + VTILE_B;

        #pragma unroll
        for (int kk = 0; kk < 2; ++kk) {
            const uint32_t kbA = (uint32_t)(kk * 32);
            const uint32_t kbB = (uint32_t)(kk * 16 * VROWB);
            uint32_t afrag[4][4], bH[4][2], bL[4][2];

            #pragma unroll
            for (int i = 0; i < 4; ++i)
                ldsm4(afrag[i], sPh + aoff + kbA + (uint32_t)((warp_m + i*16) * ROWB));
            #pragma unroll
            for (int g = 0; g < 2; ++g) {
                uint32_t r[4];
                ldsm4t(r, sVh + boffT + kbB + (uint32_t)((warp_n + g*16) * 2));
                bH[g*2][0] = r[0]; bH[g*2][1] = r[1];
                bH[g*2+1][0] = r[2]; bH[g*2+1][1] = r[3];
            }
            #pragma unroll
            for (int i = 0; i < 4; ++i)
                #pragma unroll
                for (int j = 0; j < 4; ++j)
                    mma_bf16(acc[i][j], afrag[i], bH[j]);

            #pragma unroll
            for (int g = 0; g < 2; ++g) {
                uint32_t r[4];
                ldsm4t(r, sVl + boffT + kbB + (uint32_t)((warp_n + g*16) * 2));
                bL[g*2][0] = r[0]; bL[g*2][1] = r[1];
                bL[g*2+1][0] = r[2]; bL[g*2+1][1] = r[3];
            }
            #pragma unroll
            for (int i = 0; i < 4; ++i)
                #pragma unroll
                for (int j = 0; j < 4; ++j)
                    mma_bf16(acc[i][j], afrag[i], bL[j]);

            #pragma unroll
            for (int i = 0; i < 4; ++i)
                ldsm4(afrag[i], sPl + aoff + kbA + (uint32_t)((warp_m + i*16) * ROWB));
            #pragma unroll
            for (int i = 0; i < 4; ++i)
                #pragma unroll
                for (int j = 0; j < 4; ++j)
                    mma_bf16(acc[i][j], afrag[i], bH[j]);
        }
        __syncthreads();
    }

    #pragma unroll
    for (int i = 0; i < 4; ++i) {
        const int s0 = rowStart + warp_m + i * 16 + (lane >> 2);
        #pragma unroll
        for (int half = 0; half < 2; ++half) {
            const int s = s0 + half * 8;
            const size_t rbase = ((size_t)(b * Sn + s)) * Dn + h * HDn;
            #pragma unroll
            for (int j = 0; j < 4; ++j) {
                const int c0 = warp_n + j * 8 + (lane & 3) * 2;
                *(__half2*)&O16[rbase + c0] =
                    __floats2half2_rn(acc[i][j][half*2], acc[i][j][half*2+1]);
            }
        }
    }
}

// ============================================================================
extern "C" void kernel_launch(void* const* d_in, const int* in_sizes, int n_in,
                              void* d_out, int out_size)
{
    const float* x  = (const float*)d_in[0];
    const float* wq = (const float*)d_in[2];
    const float* bq = (const float*)d_in[3];
    const float* wk = (const float*)d_in[4];
    const float* bk = (const float*)d_in[5];
    const float* wv = (const float*)d_in[6];
    const float* bv = (const float*)d_in[7];
    const float* wo = (const float*)d_in[8];
    const float* bo = (const float*)d_in[9];
    float* out = (float*)d_out;

    float* pp;
    __half *x16, *o16, *whi, *wlo, *woh, *wol;
    __nv_bfloat16 *qh, *ql, *kh, *kl, *vh, *vl, *ph, *pl;
    cudaGetSymbolAddress((void**)&pp, g_p);
    cudaGetSymbolAddress((void**)&x16, g_x16);
    cudaGetSymbolAddress((void**)&o16, g_o16);
    cudaGetSymbolAddress((void**)&whi, g_whi);
    cudaGetSymbolAddress((void**)&wlo, g_wlo);
    cudaGetSymbolAddress((void**)&woh, g_woh);
    cudaGetSymbolAddress((void**)&wol, g_wol);
    cudaGetSymbolAddress((void**)&qh, g_qh);
    cudaGetSymbolAddress((void**)&ql, g_ql);
    cudaGetSymbolAddress((void**)&kh, g_kh);
    cudaGetSymbolAddress((void**)&kl, g_kl);
    cudaGetSymbolAddress((void**)&vh, g_vh);
    cudaGetSymbolAddress((void**)&vl, g_vl);
    cudaGetSymbolAddress((void**)&ph, g_ph);
    cudaGetSymbolAddress((void**)&pl, g_pl);

    cudaFuncSetAttribute(gemm_f16<0>, cudaFuncAttributeMaxDynamicSharedMemorySize, GEMM_SMEM);
    cudaFuncSetAttribute(gemm_f16<1>, cudaFuncAttributeMaxDynamicSharedMemorySize, GEMM_SMEM);
    cudaFuncSetAttribute(gemm_f16<2>, cudaFuncAttributeMaxDynamicSharedMemorySize, GEMM_SMEM);
    cudaFuncSetAttribute(logits_mma, cudaFuncAttributeMaxDynamicSharedMemorySize, LOGIT_SMEM);
    cudaFuncSetAttribute(av_mma,    cudaFuncAttributeMaxDynamicSharedMemorySize, AV_SMEM);

    const int nSplitBlks = (int)(((size_t)Mtot * Dn / 4) / 256);
    dim3 gT(Dn / 32, Dn / 32), bT(32, 8);
    dim3 gG(Dn / 128, Mtot / 128);   // (16, 64)

    const size_t WSZ = (size_t)Dn * Dn;

    // --- preprocessing up front ---
    half_kernel<<<nSplitBlks, 256>>>((const float4*)x, x16);
    splitT_kernel<<<gT, bT>>>(wq, whi,         wlo);
    splitT_kernel<<<gT, bT>>>(wk, whi + WSZ,   wlo + WSZ);
    splitT_kernel<<<gT, bT>>>(wv, whi + 2*WSZ, wlo + 2*WSZ);
    splitT_kernel<<<gT, bT>>>(wo, woh, wol);

    // --- Q/K/V projections (fp16 A-single / B-split-2) ---
    gemm_f16<1><<<gG, 256, GEMM_SMEM>>>(x16, whi,         wlo,         bq, nullptr, qh, ql);
    gemm_f16<1><<<gG, 256, GEMM_SMEM>>>(x16, whi + WSZ,   wlo + WSZ,   bk, nullptr, kh, kl);
    gemm_f16<2><<<gG, 256, GEMM_SMEM>>>(x16, whi + 2*WSZ, wlo + 2*WSZ, bv, nullptr, vh, vl);

    // --- attention (bf16 split-3, unchanged) ---
    dim3 glog(Sn / 128, Sn / 128, Bn * Hn);
    logits_mma<<<glog, 256, LOGIT_SMEM>>>(qh, ql, kh, kl, pp);
    softmax_kernel<<<Bn * Hn * Sn, 128>>>(pp, ph, pl);
    dim3 gav(1, Sn / 128, Bn * Hn);
    av_mma<<<gav, 256, AV_SMEM>>>(ph, pl, vh, vl, o16);

    // --- output projection ---
    gemm_f16<0><<<gG, 256, GEMM_SMEM>>>(o16, woh, wol, bo, out, nullptr, nullptr);
}

// round 10
// speedup vs baseline: 1.5966x; 1.0383x over previous
#include <cuda_runtime.h>
#include <cuda_bf16.h>
#include <cuda_fp16.h>
#include <math.h>
#include <stdint.h>

#define Bn   16
#define Sn   512
#define Dn   2048
#define Hn   16
#define HDn  128
#define Mtot (Bn*Sn)      // 8192

// ---------------- scratch (alloc-free: __device__ globals) ----------------
__device__ float g_p[(size_t)Bn * Hn * Sn * Sn];     // 256 MB logits (fp32)
__device__ __half g_p16[(size_t)Bn * Hn * Sn * Sn];  // 128 MB probs (fp16)
__device__ __half g_x16[(size_t)Mtot * Dn];          // 32 MB x (fp16)
__device__ __half g_o16[(size_t)Mtot * Dn];          // 32 MB attn-out (fp16)
__device__ __half g_whi[(size_t)3 * Dn * Dn];        // 24 MB W^T q|k|v hi
__device__ __half g_wlo[(size_t)3 * Dn * Dn];        // 24 MB W^T q|k|v lo
__device__ __half g_woh[(size_t)Dn * Dn];            // 8 MB  W^T o hi
__device__ __half g_wol[(size_t)Dn * Dn];            // 8 MB  W^T o lo
__device__ __half g_q16[(size_t)Mtot * Dn];          // 32 MB Q (fp16 single)
__device__ __half g_kh[(size_t)Mtot * Dn];
__device__ __half g_kl[(size_t)Mtot * Dn];
__device__ __half g_vh[(size_t)Mtot * Dn];
__device__ __half g_vl[(size_t)Mtot * Dn];

// ============================================================================
// PTX helpers (sm_80-compatible subset)
// ============================================================================
__device__ __forceinline__ uint32_t smem_u32(const void* p) {
    uint32_t a;
    asm("{ .reg .u64 t; cvta.to.shared.u64 t, %1; cvt.u32.u64 %0, t; }" : "=r"(a) : "l"(p));
    return a;
}
__device__ __forceinline__ void cp16(uint32_t saddr, const void* gptr) {
    asm volatile("cp.async.cg.shared.global [%0], [%1], 16;" :: "r"(saddr), "l"(gptr) : "memory");
}
__device__ __forceinline__ void cp_commit() {
    asm volatile("cp.async.commit_group;" ::: "memory");
}
template <int N>
__device__ __forceinline__ void cp_wait() {
    asm volatile("cp.async.wait_group %0;" :: "n"(N) : "memory");
}
__device__ __forceinline__ void ldsm4(uint32_t* r, uint32_t addr) {
    asm volatile("ldmatrix.sync.aligned.m8n8.x4.shared.b16 {%0,%1,%2,%3}, [%4];"
                 : "=r"(r[0]), "=r"(r[1]), "=r"(r[2]), "=r"(r[3]) : "r"(addr));
}
__device__ __forceinline__ void ldsm4t(uint32_t* r, uint32_t addr) {
    asm volatile("ldmatrix.sync.aligned.m8n8.x4.trans.shared.b16 {%0,%1,%2,%3}, [%4];"
                 : "=r"(r[0]), "=r"(r[1]), "=r"(r[2]), "=r"(r[3]) : "r"(addr));
}
__device__ __forceinline__ void mma_f16(float* d, const uint32_t* a, const uint32_t* b) {
    asm volatile("mma.sync.aligned.m16n8k16.row.col.f32.f16.f16.f32 "
                 "{%0,%1,%2,%3}, {%4,%5,%6,%7}, {%8,%9}, {%0,%1,%2,%3};"
                 : "+f"(d[0]), "+f"(d[1]), "+f"(d[2]), "+f"(d[3])
                 : "r"(a[0]), "r"(a[1]), "r"(a[2]), "r"(a[3]), "r"(b[0]), "r"(b[1]));
}

// ============================================================================
// Tile geometry
// ============================================================================
#define KC      32
#define ROWB    80                   // bytes/row for 32-elem 16-bit tiles
#define TILE_B  (128 * ROWB)         // 10240 B
#define VROWB   272                  // bytes/row for 128-elem 16-bit V tiles
#define VTILE_B (32 * VROWB)         // 8704 B

template <typename T>
__device__ __forceinline__ void load_tile(const T* __restrict__ g,
                                          int ldg, uint32_t sdst, int tid)
{
    #pragma unroll
    for (int it = 0; it < 2; ++it) {
        int idx = tid + it * 256;
        int row = idx >> 2, seg = idx & 3;
        cp16(sdst + (uint32_t)(row * ROWB + seg * 16),
             (const char*)(g + (size_t)row * ldg) + seg * 16);
    }
}
__device__ __forceinline__ void load_vtile(const __half* __restrict__ g,
                                           uint32_t sdst, int tid)
{
    #pragma unroll
    for (int it = 0; it < 2; ++it) {
        int idx = tid + it * 256;
        int row = idx >> 4, seg = idx & 15;
        cp16(sdst + (uint32_t)(row * VROWB + seg * 16),
             (const char*)(g + (size_t)row * Dn) + seg * 16);
    }
}

__device__ __forceinline__ void split_store16(__half* __restrict__ OH,
                                              __half* __restrict__ OL,
                                              size_t off, float v0, float v1)
{
    __half h0 = __float2half_rn(v0), h1 = __float2half_rn(v1);
    __half l0 = __float2half_rn(v0 - __half2float(h0));
    __half l1 = __float2half_rn(v1 - __half2float(h1));
    *(__half2*)&OH[off] = __halves2half2(h0, h1);
    *(__half2*)&OL[off] = __halves2half2(l0, l1);
}

// ============================================================================
// Preprocessing
// ============================================================================
__global__ void __launch_bounds__(256)
half_kernel(const float4* __restrict__ X, __half* __restrict__ H)
{
    size_t i = (size_t)blockIdx.x * 256 + threadIdx.x;
    float4 v = X[i];
    __half2* H2 = (__half2*)H;
    H2[2*i]   = __floats2half2_rn(v.x, v.y);
    H2[2*i+1] = __floats2half2_rn(v.z, v.w);
}

__global__ void __launch_bounds__(256)
splitT_kernel(const float* __restrict__ W, __half* __restrict__ Th,
              __half* __restrict__ Tl)
{
    __shared__ float t[32][33];
    int bx = blockIdx.x * 32;   // n
    int by = blockIdx.y * 32;   // k
    int tx = threadIdx.x, ty = threadIdx.y;
    #pragma unroll
    for (int i = 0; i < 32; i += 8)
        t[ty + i][tx] = W[(size_t)(by + ty + i) * Dn + bx + tx];
    __syncthreads();
    #pragma unroll
    for (int i = 0; i < 32; i += 8) {
        float v = t[tx][ty + i];
        __half h = __float2half_rn(v);
        size_t o = (size_t)(bx + ty + i) * Dn + by + tx;
        Th[o] = h;
        Tl[o] = __float2half_rn(v - __half2float(h));
    }
}

// ============================================================================
// fp16 A-single / B-split-2 projection GEMM. 256 threads, 8 warps,
// warp tile 64x32, CTA tile 128x128.
// EPI: 0 = bias->fp32 | 1 = bias+RoPE->fp16 single | 2 = bias+RoPE->fp16 split
//      3 = bias->fp16 split
// ============================================================================
#define BUF_B     (3 * TILE_B)       // A, Bh, Bl
#define GEMM_SMEM (2 * BUF_B)        // 61440

template <int EPI>
__global__ void __launch_bounds__(256)
gemm_f16(const __half* __restrict__ A,
         const __half* __restrict__ Bh, const __half* __restrict__ Bl,
         const float* __restrict__ bias, float* __restrict__ Cf,
         __half* __restrict__ Oh, __half* __restrict__ Ol)
{
    extern __shared__ char smem_raw[];
    const uint32_t sb = smem_u32(smem_raw);

    const int tid  = threadIdx.x;
    const int wid  = tid >> 5;
    const int lane = tid & 31;
    const int rowStart = blockIdx.y * 128;
    const int colStart = blockIdx.x * 128;
    const int warp_m = (wid & 1) * 64;
    const int warp_n = (wid >> 1) * 32;

    const __half* gA  = A  + (size_t)rowStart * Dn;
    const __half* gB0 = Bh + (size_t)colStart * Dn;
    const __half* gB1 = Bl + (size_t)colStart * Dn;

    const uint32_t aoff = (uint32_t)((lane & 15) * ROWB + (lane >> 4) * 16);
    const uint32_t boff = (uint32_t)(((lane & 7) + ((lane >> 4) << 3)) * ROWB
                                     + ((lane >> 3) & 1) * 16);

    float acc[4][4][4];
    #pragma unroll
    for (int i = 0; i < 4; i++)
        #pragma unroll
        for (int j = 0; j < 4; j++)
            #pragma unroll
            for (int r = 0; r < 4; r++) acc[i][j][r] = 0.f;

    const int NCHUNK = Dn / KC;   // 64

    {
        const uint32_t bb = sb;
        load_tile(gA,  Dn, bb,            tid);
        load_tile(gB0, Dn, bb + TILE_B,   tid);
        load_tile(gB1, Dn, bb + 2*TILE_B, tid);
        cp_commit();
    }

    #pragma unroll 1
    for (int c = 0; c < NCHUNK; ++c) {
        if (c + 1 < NCHUNK) {
            const uint32_t bb = sb + ((c + 1) & 1) * BUF_B;
            const int k0 = (c + 1) * KC;
            load_tile(gA  + k0, Dn, bb,            tid);
            load_tile(gB0 + k0, Dn, bb + TILE_B,   tid);
            load_tile(gB1 + k0, Dn, bb + 2*TILE_B, tid);
            cp_commit();
            cp_wait<1>();
        } else {
            cp_wait<0>();
        }
        __syncthreads();

        const uint32_t bb  = sb + (c & 1) * BUF_B;
        const uint32_t sA  = bb;
        const uint32_t sBh = bb + TILE_B;
        const uint32_t sBl = bb + 2*TILE_B;

        #pragma unroll
        for (int kk = 0; kk < 2; ++kk) {
            const uint32_t kb = (uint32_t)(kk * 32);
            uint32_t afrag[4][4], bfrag[4][2];

            #pragma unroll
            for (int i = 0; i < 4; ++i)
                ldsm4(afrag[i], sA + aoff + kb + (uint32_t)((warp_m + i*16) * ROWB));

            #pragma unroll
            for (int p = 0; p < 2; ++p) {
                uint32_t r[4];
                ldsm4(r, sBh + boff + kb + (uint32_t)((warp_n + p*16) * ROWB));
                bfrag[p*2][0] = r[0]; bfrag[p*2][1] = r[1];
                bfrag[p*2+1][0] = r[2]; bfrag[p*2+1][1] = r[3];
            }
            #pragma unroll
            for (int i = 0; i < 4; ++i)
                #pragma unroll
                for (int j = 0; j < 4; ++j)
                    mma_f16(acc[i][j], afrag[i], bfrag[j]);

            #pragma unroll
            for (int p = 0; p < 2; ++p) {
                uint32_t r[4];
                ldsm4(r, sBl + boff + kb + (uint32_t)((warp_n + p*16) * ROWB));
                bfrag[p*2][0] = r[0]; bfrag[p*2][1] = r[1];
                bfrag[p*2+1][0] = r[2]; bfrag[p*2+1][1] = r[3];
            }
            #pragma unroll
            for (int i = 0; i < 4; ++i)
                #pragma unroll
                for (int j = 0; j < 4; ++j)
                    mma_f16(acc[i][j], afrag[i], bfrag[j]);
        }
        __syncthreads();
    }

    // ---- epilogue ----
    #pragma unroll
    for (int i = 0; i < 4; ++i) {
        const int r0 = rowStart + warp_m + i * 16 + (lane >> 2);
        #pragma unroll
        for (int half = 0; half < 2; ++half) {
            const int r = r0 + half * 8;
            const int s = r & (Sn - 1);
            #pragma unroll
            for (int j = 0; j < 4; ++j) {
                const int c0 = colStart + warp_n + j * 8 + (lane & 3) * 2;
                float v0 = acc[i][j][half*2]   + bias[c0];
                float v1 = acc[i][j][half*2+1] + bias[c0 + 1];
                if (EPI == 1 || EPI == 2) {
                    int pidx = (c0 & (HDn - 1)) >> 1;
                    float inv = exp2f((float)pidx * (-13.287712379549449f / 64.0f));
                    float sn, cs;
                    sincosf((float)s * inv, &sn, &cs);
                    float e = v0, o = v1;
                    v0 = e * cs - o * sn;
                    v1 = o * cs + e * sn;
                }
                if (EPI == 0)
                    *(float2*)&Cf[(size_t)r * Dn + c0] = make_float2(v0, v1);
                else if (EPI == 1)
                    *(__half2*)&Oh[(size_t)r * Dn + c0] = __floats2half2_rn(v0, v1);
                else
                    split_store16(Oh, Ol, (size_t)r * Dn + c0, v0, v1);
            }
        }
    }
}

// ============================================================================
// Logits: Q fp16 single x K fp16 split-2 (2 passes), fp32 out.
// ============================================================================
#define LBUF_B     (3 * TILE_B)
#define LOGIT_SMEM (2 * LBUF_B)      // 61440

__global__ void __launch_bounds__(256)
logits_f16(const __half* __restrict__ Q,
           const __half* __restrict__ Kh, const __half* __restrict__ Kl,
           float* __restrict__ P)
{
    const int bh = blockIdx.z;
    const int rowStart = blockIdx.y * 128;
    const int colStart = blockIdx.x * 128;
    if (colStart > rowStart) return;

    extern __shared__ char smem_raw[];
    const uint32_t sb = smem_u32(smem_raw);

    const int b = bh >> 4, h = bh & 15;
    const int tid  = threadIdx.x;
    const int wid  = tid >> 5;
    const int lane = tid & 31;
    const int warp_m = (wid & 1) * 64;
    const int warp_n = (wid >> 1) * 32;

    const __half* gQ  = Q  + ((size_t)(b * Sn + rowStart) * Hn + h) * HDn;
    const __half* gKh = Kh + ((size_t)(b * Sn + colStart) * Hn + h) * HDn;
    const __half* gKl = Kl + ((size_t)(b * Sn + colStart) * Hn + h) * HDn;

    const uint32_t aoff = (uint32_t)((lane & 15) * ROWB + (lane >> 4) * 16);
    const uint32_t boff = (uint32_t)(((lane & 7) + ((lane >> 4) << 3)) * ROWB
                                     + ((lane >> 3) & 1) * 16);

    float acc[4][4][4];
    #pragma unroll
    for (int i = 0; i < 4; i++)
        #pragma unroll
        for (int j = 0; j < 4; j++)
            #pragma unroll
            for (int r = 0; r < 4; r++) acc[i][j][r] = 0.f;

    {
        const uint32_t bb = sb;
        load_tile(gQ,  Dn, bb,            tid);
        load_tile(gKh, Dn, bb + TILE_B,   tid);
        load_tile(gKl, Dn, bb + 2*TILE_B, tid);
        cp_commit();
    }

    #pragma unroll 1
    for (int c = 0; c < 4; ++c) {
        if (c + 1 < 4) {
            const uint32_t bb = sb + ((c + 1) & 1) * LBUF_B;
            const int k0 = (c + 1) * KC;
            load_tile(gQ  + k0, Dn, bb,            tid);
            load_tile(gKh + k0, Dn, bb + TILE_B,   tid);
            load_tile(gKl + k0, Dn, bb + 2*TILE_B, tid);
            cp_commit();
            cp_wait<1>();
        } else {
            cp_wait<0>();
        }
        __syncthreads();

        const uint32_t bb  = sb + (c & 1) * LBUF_B;
        const uint32_t sQ  = bb;
        const uint32_t sKh = bb + TILE_B;
        const uint32_t sKl = bb + 2*TILE_B;

        #pragma unroll
        for (int kk = 0; kk < 2; ++kk) {
            const uint32_t kb = (uint32_t)(kk * 32);
            uint32_t afrag[4][4], bfrag[4][2];

            #pragma unroll
            for (int i = 0; i < 4; ++i)
                ldsm4(afrag[i], sQ + aoff + kb + (uint32_t)((warp_m + i*16) * ROWB));

            #pragma unroll
            for (int p = 0; p < 2; ++p) {
                uint32_t r[4];
                ldsm4(r, sKh + boff + kb + (uint32_t)((warp_n + p*16) * ROWB));
                bfrag[p*2][0] = r[0]; bfrag[p*2][1] = r[1];
                bfrag[p*2+1][0] = r[2]; bfrag[p*2+1][1] = r[3];
            }
            #pragma unroll
            for (int i = 0; i < 4; ++i)
                #pragma unroll
                for (int j = 0; j < 4; ++j)
                    mma_f16(acc[i][j], afrag[i], bfrag[j]);

            #pragma unroll
            for (int p = 0; p < 2; ++p) {
                uint32_t r[4];
                ldsm4(r, sKl + boff + kb + (uint32_t)((warp_n + p*16) * ROWB));
                bfrag[p*2][0] = r[0]; bfrag[p*2][1] = r[1];
                bfrag[p*2+1][0] = r[2]; bfrag[p*2+1][1] = r[3];
            }
            #pragma unroll
            for (int i = 0; i < 4; ++i)
                #pragma unroll
                for (int j = 0; j < 4; ++j)
                    mma_f16(acc[i][j], afrag[i], bfrag[j]);
        }
        __syncthreads();
    }

    const float scale = 0.08838834764831843f;
    float* Pout = P + (size_t)bh * Sn * Sn;
    #pragma unroll
    for (int i = 0; i < 4; ++i) {
        const int s0 = rowStart + warp_m + i * 16 + (lane >> 2);
        #pragma unroll
        for (int half = 0; half < 2; ++half) {
            const int s = s0 + half * 8;
            #pragma unroll
            for (int j = 0; j < 4; ++j) {
                const int t0 = colStart + warp_n + j * 8 + (lane & 3) * 2;
                *(float2*)&Pout[(size_t)s * Sn + t0] =
                    make_float2(acc[i][j][half*2] * scale, acc[i][j][half*2+1] * scale);
            }
        }
    }
}

// ============================================================================
// Softmax: fp32 logits -> fp16 single probs, mask by index.
// ============================================================================
__global__ void __launch_bounds__(128)
softmax_kernel(const float* __restrict__ P, __half* __restrict__ P16)
{
    const size_t row = blockIdx.x;
    const float* p = P + row * Sn;
    const int s = (int)(row & (Sn - 1));
    const int tid = threadIdx.x;
    float4 v = ((const float4*)p)[tid];
    const int t0 = tid * 4;
    v.x = (t0     <= s) ? v.x : -1e9f;
    v.y = (t0 + 1 <= s) ? v.y : -1e9f;
    v.z = (t0 + 2 <= s) ? v.z : -1e9f;
    v.w = (t0 + 3 <= s) ? v.w : -1e9f;

    float mx = fmaxf(fmaxf(v.x, v.y), fmaxf(v.z, v.w));
    #pragma unroll
    for (int o = 16; o; o >>= 1) mx = fmaxf(mx, __shfl_xor_sync(0xffffffffu, mx, o));
    __shared__ float red[4];
    if ((tid & 31) == 0) red[tid >> 5] = mx;
    __syncthreads();
    mx = fmaxf(fmaxf(red[0], red[1]), fmaxf(red[2], red[3]));

    float e0 = expf(v.x - mx), e1 = expf(v.y - mx);
    float e2 = expf(v.z - mx), e3 = expf(v.w - mx);
    float sm = e0 + e1 + e2 + e3;
    #pragma unroll
    for (int o = 16; o; o >>= 1) sm += __shfl_xor_sync(0xffffffffu, sm, o);
    __shared__ float red2[4];
    if ((tid & 31) == 0) red2[tid >> 5] = sm;
    __syncthreads();
    sm = red2[0] + red2[1] + red2[2] + red2[3];

    const float inv = 1.0f / sm;
    __half2* P2 = (__half2*)(P16 + row * Sn);
    P2[tid*2]   = __floats2half2_rn(e0 * inv, e1 * inv);
    P2[tid*2+1] = __floats2half2_rn(e2 * inv, e3 * inv);
}

// ============================================================================
// AV: P fp16 single x V fp16 split-2 (2 passes); fp16 single out for WO.
// ============================================================================
#define AVBUF_B  (TILE_B + 2 * VTILE_B)   // 27648
#define AV_SMEM  (2 * AVBUF_B)            // 55296

__global__ void __launch_bounds__(256)
av_f16(const __half* __restrict__ P16,
       const __half* __restrict__ Vh, const __half* __restrict__ Vl,
       __half* __restrict__ O16)
{
    extern __shared__ char smem_raw[];
    const uint32_t sb = smem_u32(smem_raw);

    const int bh = blockIdx.z;
    const int b = bh >> 4, h = bh & 15;
    const int rowStart = blockIdx.y * 128;
    const int tid  = threadIdx.x;
    const int wid  = tid >> 5;
    const int lane = tid & 31;
    const int warp_m = (wid & 1) * 64;
    const int warp_n = (wid >> 1) * 32;

    const __half* gP  = P16 + (size_t)bh * Sn * Sn + (size_t)rowStart * Sn;
    const __half* gVh = Vh + (size_t)(b * Sn) * Dn + h * HDn;
    const __half* gVl = Vl + (size_t)(b * Sn) * Dn + h * HDn;

    const uint32_t aoff  = (uint32_t)((lane & 15) * ROWB + (lane >> 4) * 16);
    const uint32_t boffT = (uint32_t)(((lane & 7) + ((lane >> 3) & 1) * 8) * VROWB
                                      + (lane >> 4) * 16);

    float acc[4][4][4];
    #pragma unroll
    for (int i = 0; i < 4; i++)
        #pragma unroll
        for (int j = 0; j < 4; j++)
            #pragma unroll
            for (int r = 0; r < 4; r++) acc[i][j][r] = 0.f;

    const int nchunk = (blockIdx.y + 1) * 4;

    {
        const uint32_t bb = sb;
        load_tile (gP, Sn, bb, tid);
        load_vtile(gVh, bb + TILE_B, tid);
        load_vtile(gVl, bb + TILE_B + VTILE_B, tid);
        cp_commit();
    }

    #pragma unroll 1
    for (int c = 0; c < nchunk; ++c) {
        if (c + 1 < nchunk) {
            const uint32_t bb = sb + ((c + 1) & 1) * AVBUF_B;
            const int k0 = (c + 1) * KC;
            load_tile (gP + k0, Sn, bb, tid);
            load_vtile(gVh + (size_t)k0 * Dn, bb + TILE_B, tid);
            load_vtile(gVl + (size_t)k0 * Dn, bb + TILE_B + VTILE_B, tid);
            cp_commit();
            cp_wait<1>();
        } else {
            cp_wait<0>();
        }
        __syncthreads();

        const uint32_t bb  = sb + (c & 1) * AVBUF_B;
        const uint32_t sP  = bb;
        const uint32_t sVh = bb + TILE_B;
        const uint32_t sVl = bb + TILE_B + VTILE_B;

        #pragma unroll
        for (int kk = 0; kk < 2; ++kk) {
            const uint32_t kbA = (uint32_t)(kk * 32);
            const uint32_t kbB = (uint32_t)(kk * 16 * VROWB);
            uint32_t afrag[4][4], bfrag[4][2];

            #pragma unroll
            for (int i = 0; i < 4; ++i)
                ldsm4(afrag[i], sP + aoff + kbA + (uint32_t)((warp_m + i*16) * ROWB));

            #pragma unroll
            for (int g = 0; g < 2; ++g) {
                uint32_t r[4];
                ldsm4t(r, sVh + boffT + kbB + (uint32_t)((warp_n + g*16) * 2));
                bfrag[g*2][0] = r[0]; bfrag[g*2][1] = r[1];
                bfrag[g*2+1][0] = r[2]; bfrag[g*2+1][1] = r[3];
            }
            #pragma unroll
            for (int i = 0; i < 4; ++i)
                #pragma unroll
                for (int j = 0; j < 4; ++j)
                    mma_f16(acc[i][j], afrag[i], bfrag[j]);

            #pragma unroll
            for (int g = 0; g < 2; ++g) {
                uint32_t r[4];
                ldsm4t(r, sVl + boffT + kbB + (uint32_t)((warp_n + g*16) * 2));
                bfrag[g*2][0] = r[0]; bfrag[g*2][1] = r[1];
                bfrag[g*2+1][0] = r[2]; bfrag[g*2+1][1] = r[3];
            }
            #pragma unroll
            for (int i = 0; i < 4; ++i)
                #pragma unroll
                for (int j = 0; j < 4; ++j)
                    mma_f16(acc[i][j], afrag[i], bfrag[j]);
        }
        __syncthreads();
    }

    #pragma unroll
    for (int i = 0; i < 4; ++i) {
        const int s0 = rowStart + warp_m + i * 16 + (lane >> 2);
        #pragma unroll
        for (int half = 0; half < 2; ++half) {
            const int s = s0 + half * 8;
            const size_t rbase = ((size_t)(b * Sn + s)) * Dn + h * HDn;
            #pragma unroll
            for (int j = 0; j < 4; ++j) {
                const int c0 = warp_n + j * 8 + (lane & 3) * 2;
                *(__half2*)&O16[rbase + c0] =
                    __floats2half2_rn(acc[i][j][half*2], acc[i][j][half*2+1]);
            }
        }
    }
}

// ============================================================================
extern "C" void kernel_launch(void* const* d_in, const int* in_sizes, int n_in,
                              void* d_out, int out_size)
{
    const float* x  = (const float*)d_in[0];
    const float* wq = (const float*)d_in[2];
    const float* bq = (const float*)d_in[3];
    const float* wk = (const float*)d_in[4];
    const float* bk = (const float*)d_in[5];
    const float* wv = (const float*)d_in[6];
    const float* bv = (const float*)d_in[7];
    const float* wo = (const float*)d_in[8];
    const float* bo = (const float*)d_in[9];
    float* out = (float*)d_out;

    float* pp;
    __half *p16, *x16, *o16, *whi, *wlo, *woh, *wol, *q16, *kh, *kl, *vh, *vl;
    cudaGetSymbolAddress((void**)&pp,  g_p);
    cudaGetSymbolAddress((void**)&p16, g_p16);
    cudaGetSymbolAddress((void**)&x16, g_x16);
    cudaGetSymbolAddress((void**)&o16, g_o16);
    cudaGetSymbolAddress((void**)&whi, g_whi);
    cudaGetSymbolAddress((void**)&wlo, g_wlo);
    cudaGetSymbolAddress((void**)&woh, g_woh);
    cudaGetSymbolAddress((void**)&wol, g_wol);
    cudaGetSymbolAddress((void**)&q16, g_q16);
    cudaGetSymbolAddress((void**)&kh, g_kh);
    cudaGetSymbolAddress((void**)&kl, g_kl);
    cudaGetSymbolAddress((void**)&vh, g_vh);
    cudaGetSymbolAddress((void**)&vl, g_vl);

    cudaFuncSetAttribute(gemm_f16<0>, cudaFuncAttributeMaxDynamicSharedMemorySize, GEMM_SMEM);
    cudaFuncSetAttribute(gemm_f16<1>, cudaFuncAttributeMaxDynamicSharedMemorySize, GEMM_SMEM);
    cudaFuncSetAttribute(gemm_f16<2>, cudaFuncAttributeMaxDynamicSharedMemorySize, GEMM_SMEM);
    cudaFuncSetAttribute(gemm_f16<3>, cudaFuncAttributeMaxDynamicSharedMemorySize, GEMM_SMEM);
    cudaFuncSetAttribute(logits_f16, cudaFuncAttributeMaxDynamicSharedMemorySize, LOGIT_SMEM);
    cudaFuncSetAttribute(av_f16,    cudaFuncAttributeMaxDynamicSharedMemorySize, AV_SMEM);

    const int nSplitBlks = (int)(((size_t)Mtot * Dn / 4) / 256);
    dim3 gT(Dn / 32, Dn / 32), bT(32, 8);
    dim3 gG(Dn / 128, Mtot / 128);   // (16, 64)

    const size_t WSZ = (size_t)Dn * Dn;

    // --- preprocessing up front ---
    half_kernel<<<nSplitBlks, 256>>>((const float4*)x, x16);
    splitT_kernel<<<gT, bT>>>(wq, whi,         wlo);
    splitT_kernel<<<gT, bT>>>(wk, whi + WSZ,   wlo + WSZ);
    splitT_kernel<<<gT, bT>>>(wv, whi + 2*WSZ, wlo + 2*WSZ);
    splitT_kernel<<<gT, bT>>>(wo, woh, wol);

    // --- Q/K/V projections ---
    gemm_f16<1><<<gG, 256, GEMM_SMEM>>>(x16, whi,         wlo,         bq, nullptr, q16, nullptr); // Q: RoPE, fp16 single
    gemm_f16<2><<<gG, 256, GEMM_SMEM>>>(x16, whi + WSZ,   wlo + WSZ,   bk, nullptr, kh, kl);       // K: RoPE, split
    gemm_f16<3><<<gG, 256, GEMM_SMEM>>>(x16, whi + 2*WSZ, wlo + 2*WSZ, bv, nullptr, vh, vl);       // V: split

    // --- attention (fp16) ---
    dim3 glog(Sn / 128, Sn / 128, Bn * Hn);
    logits_f16<<<glog, 256, LOGIT_SMEM>>>(q16, kh, kl, pp);
    softmax_kernel<<<Bn * Hn * Sn, 128>>>(pp, p16);
    dim3 gav(1, Sn / 128, Bn * Hn);
    av_f16<<<gav, 256, AV_SMEM>>>(p16, vh, vl, o16);

    // --- output projection ---
    gemm_f16<0><<<gG, 256, GEMM_SMEM>>>(o16, woh, wol, bo, out, nullptr, nullptr);
}

// round 11
// speedup vs baseline: 2.1044x; 1.3181x over previous
#include <cuda_runtime.h>
#include <cuda_fp16.h>
#include <math.h>
#include <stdint.h>

#define Bn   16
#define Sn   512
#define Dn   2048
#define Hn   16
#define HDn  128
#define Mtot (Bn*Sn)      // 8192

// ---------------- scratch (alloc-free: __device__ globals) ----------------
__device__ float g_p[(size_t)Bn * Hn * Sn * Sn];     // 256 MB logits (fp32)
__device__ __half g_p16[(size_t)Bn * Hn * Sn * Sn];  // 128 MB probs (fp16)
__device__ __half g_x16[(size_t)Mtot * Dn];          // 32 MB x (fp16)
__device__ __half g_o16[(size_t)Mtot * Dn];          // 32 MB attn-out (fp16)
__device__ __half g_w16[(size_t)3 * Dn * Dn];        // 24 MB W^T q|k|v (single)
__device__ __half g_woh[(size_t)Dn * Dn];            // 8 MB  W^T o hi
__device__ __half g_wol[(size_t)Dn * Dn];            // 8 MB  W^T o lo
__device__ __half g_q16[(size_t)Mtot * Dn];          // 32 MB Q
__device__ __half g_k16[(size_t)Mtot * Dn];          // 32 MB K
__device__ __half g_v16[(size_t)Mtot * Dn];          // 32 MB V

// ============================================================================
// PTX helpers
// ============================================================================
__device__ __forceinline__ uint32_t smem_u32(const void* p) {
    uint32_t a;
    asm("{ .reg .u64 t; cvta.to.shared.u64 t, %1; cvt.u32.u64 %0, t; }" : "=r"(a) : "l"(p));
    return a;
}
__device__ __forceinline__ void cp16(uint32_t saddr, const void* gptr) {
    asm volatile("cp.async.cg.shared.global [%0], [%1], 16;" :: "r"(saddr), "l"(gptr) : "memory");
}
__device__ __forceinline__ void cp_commit() {
    asm volatile("cp.async.commit_group;" ::: "memory");
}
template <int N>
__device__ __forceinline__ void cp_wait() {
    asm volatile("cp.async.wait_group %0;" :: "n"(N) : "memory");
}
__device__ __forceinline__ void ldsm4(uint32_t* r, uint32_t addr) {
    asm volatile("ldmatrix.sync.aligned.m8n8.x4.shared.b16 {%0,%1,%2,%3}, [%4];"
                 : "=r"(r[0]), "=r"(r[1]), "=r"(r[2]), "=r"(r[3]) : "r"(addr));
}
__device__ __forceinline__ void ldsm4t(uint32_t* r, uint32_t addr) {
    asm volatile("ldmatrix.sync.aligned.m8n8.x4.trans.shared.b16 {%0,%1,%2,%3}, [%4];"
                 : "=r"(r[0]), "=r"(r[1]), "=r"(r[2]), "=r"(r[3]) : "r"(addr));
}
__device__ __forceinline__ void mma_f16(float* d, const uint32_t* a, const uint32_t* b) {
    asm volatile("mma.sync.aligned.m16n8k16.row.col.f32.f16.f16.f32 "
                 "{%0,%1,%2,%3}, {%4,%5,%6,%7}, {%8,%9}, {%0,%1,%2,%3};"
                 : "+f"(d[0]), "+f"(d[1]), "+f"(d[2]), "+f"(d[3])
                 : "r"(a[0]), "r"(a[1]), "r"(a[2]), "r"(a[3]), "r"(b[0]), "r"(b[1]));
}

// ============================================================================
// Tile geometry
// ============================================================================
#define KC      32
#define ROWB    80
#define TILE_B  (128 * ROWB)         // 10240 B
#define VROWB   272
#define VTILE_B (32 * VROWB)         // 8704 B

template <typename T>
__device__ __forceinline__ void load_tile(const T* __restrict__ g,
                                          int ldg, uint32_t sdst, int tid)
{
    #pragma unroll
    for (int it = 0; it < 2; ++it) {
        int idx = tid + it * 256;
        int row = idx >> 2, seg = idx & 3;
        cp16(sdst + (uint32_t)(row * ROWB + seg * 16),
             (const char*)(g + (size_t)row * ldg) + seg * 16);
    }
}
__device__ __forceinline__ void load_vtile(const __half* __restrict__ g,
                                           uint32_t sdst, int tid)
{
    #pragma unroll
    for (int it = 0; it < 2; ++it) {
        int idx = tid + it * 256;
        int row = idx >> 4, seg = idx & 15;
        cp16(sdst + (uint32_t)(row * VROWB + seg * 16),
             (const char*)(g + (size_t)row * Dn) + seg * 16);
    }
}

// ============================================================================
// Preprocessing
// ============================================================================
__global__ void __launch_bounds__(256)
half_kernel(const float4* __restrict__ X, __half* __restrict__ H)
{
    size_t i = (size_t)blockIdx.x * 256 + threadIdx.x;
    float4 v = X[i];
    __half2* H2 = (__half2*)H;
    H2[2*i]   = __floats2half2_rn(v.x, v.y);
    H2[2*i+1] = __floats2half2_rn(v.z, v.w);
}

// W[k][n] fp32 -> T[n][k] fp16 single
__global__ void __launch_bounds__(256)
halfT_kernel(const float* __restrict__ W, __half* __restrict__ T)
{
    __shared__ float t[32][33];
    int bx = blockIdx.x * 32;   // n
    int by = blockIdx.y * 32;   // k
    int tx = threadIdx.x, ty = threadIdx.y;
    #pragma unroll
    for (int i = 0; i < 32; i += 8)
        t[ty + i][tx] = W[(size_t)(by + ty + i) * Dn + bx + tx];
    __syncthreads();
    #pragma unroll
    for (int i = 0; i < 32; i += 8)
        T[(size_t)(bx + ty + i) * Dn + by + tx] = __float2half_rn(t[tx][ty + i]);
}

// W[k][n] fp32 -> Th/Tl[n][k] fp16 split (WO only)
__global__ void __launch_bounds__(256)
splitT_kernel(const float* __restrict__ W, __half* __restrict__ Th,
              __half* __restrict__ Tl)
{
    __shared__ float t[32][33];
    int bx = blockIdx.x * 32;
    int by = blockIdx.y * 32;
    int tx = threadIdx.x, ty = threadIdx.y;
    #pragma unroll
    for (int i = 0; i < 32; i += 8)
        t[ty + i][tx] = W[(size_t)(by + ty + i) * Dn + bx + tx];
    __syncthreads();
    #pragma unroll
    for (int i = 0; i < 32; i += 8) {
        float v = t[tx][ty + i];
        __half h = __float2half_rn(v);
        size_t o = (size_t)(bx + ty + i) * Dn + by + tx;
        Th[o] = h;
        Tl[o] = __float2half_rn(v - __half2float(h));
    }
}

// ============================================================================
// Single-precision-fp16 GEMM (A single x B single, 1 pass/kk) for QKV.
// EPI: 1 = bias+RoPE->fp16, 2 = bias->fp16.
// ============================================================================
#define SBUF_B      (2 * TILE_B)     // A, B
#define GEMM_SMEM_S (2 * SBUF_B)     // 40960

template <int EPI>
__global__ void __launch_bounds__(256)
gemm_f16s(const __half* __restrict__ A, const __half* __restrict__ B,
          const float* __restrict__ bias, __half* __restrict__ O)
{
    extern __shared__ char smem_raw[];
    const uint32_t sb = smem_u32(smem_raw);

    const int tid  = threadIdx.x;
    const int wid  = tid >> 5;
    const int lane = tid & 31;
    const int rowStart = blockIdx.y * 128;
    const int colStart = blockIdx.x * 128;
    const int warp_m = (wid & 1) * 64;
    const int warp_n = (wid >> 1) * 32;

    const __half* gA = A + (size_t)rowStart * Dn;
    const __half* gB = B + (size_t)colStart * Dn;

    const uint32_t aoff = (uint32_t)((lane & 15) * ROWB + (lane >> 4) * 16);
    const uint32_t boff = (uint32_t)(((lane & 7) + ((lane >> 4) << 3)) * ROWB
                                     + ((lane >> 3) & 1) * 16);

    float acc[4][4][4];
    #pragma unroll
    for (int i = 0; i < 4; i++)
        #pragma unroll
        for (int j = 0; j < 4; j++)
            #pragma unroll
            for (int r = 0; r < 4; r++) acc[i][j][r] = 0.f;

    const int NCHUNK = Dn / KC;   // 64

    {
        const uint32_t bb = sb;
        load_tile(gA, Dn, bb,          tid);
        load_tile(gB, Dn, bb + TILE_B, tid);
        cp_commit();
    }

    #pragma unroll 1
    for (int c = 0; c < NCHUNK; ++c) {
        if (c + 1 < NCHUNK) {
            const uint32_t bb = sb + ((c + 1) & 1) * SBUF_B;
            const int k0 = (c + 1) * KC;
            load_tile(gA + k0, Dn, bb,          tid);
            load_tile(gB + k0, Dn, bb + TILE_B, tid);
            cp_commit();
            cp_wait<1>();
        } else {
            cp_wait<0>();
        }
        __syncthreads();

        const uint32_t bb = sb + (c & 1) * SBUF_B;
        const uint32_t sA = bb, sB = bb + TILE_B;

        #pragma unroll
        for (int kk = 0; kk < 2; ++kk) {
            const uint32_t kb = (uint32_t)(kk * 32);
            uint32_t afrag[4][4], bfrag[4][2];

            #pragma unroll
            for (int i = 0; i < 4; ++i)
                ldsm4(afrag[i], sA + aoff + kb + (uint32_t)((warp_m + i*16) * ROWB));
            #pragma unroll
            for (int p = 0; p < 2; ++p) {
                uint32_t r[4];
                ldsm4(r, sB + boff + kb + (uint32_t)((warp_n + p*16) * ROWB));
                bfrag[p*2][0] = r[0]; bfrag[p*2][1] = r[1];
                bfrag[p*2+1][0] = r[2]; bfrag[p*2+1][1] = r[3];
            }
            #pragma unroll
            for (int i = 0; i < 4; ++i)
                #pragma unroll
                for (int j = 0; j < 4; ++j)
                    mma_f16(acc[i][j], afrag[i], bfrag[j]);
        }
        __syncthreads();
    }

    #pragma unroll
    for (int i = 0; i < 4; ++i) {
        const int r0 = rowStart + warp_m + i * 16 + (lane >> 2);
        #pragma unroll
        for (int half = 0; half < 2; ++half) {
            const int r = r0 + half * 8;
            const int s = r & (Sn - 1);
            #pragma unroll
            for (int j = 0; j < 4; ++j) {
                const int c0 = colStart + warp_n + j * 8 + (lane & 3) * 2;
                float v0 = acc[i][j][half*2]   + bias[c0];
                float v1 = acc[i][j][half*2+1] + bias[c0 + 1];
                if (EPI == 1) {
                    int pidx = (c0 & (HDn - 1)) >> 1;
                    float inv = exp2f((float)pidx * (-13.287712379549449f / 64.0f));
                    float sn, cs;
                    sincosf((float)s * inv, &sn, &cs);
                    float e = v0, o = v1;
                    v0 = e * cs - o * sn;
                    v1 = o * cs + e * sn;
                }
                *(__half2*)&O[(size_t)r * Dn + c0] = __floats2half2_rn(v0, v1);
            }
        }
    }
}

// ============================================================================
// A-single x B-split-2 GEMM (2 passes) for WO, fp32 out.
// ============================================================================
#define DBUF_B      (3 * TILE_B)
#define GEMM_SMEM_D (2 * DBUF_B)     // 61440

__global__ void __launch_bounds__(256)
gemm_f16d(const __half* __restrict__ A,
          const __half* __restrict__ Bh, const __half* __restrict__ Bl,
          const float* __restrict__ bias, float* __restrict__ Cf)
{
    extern __shared__ char smem_raw[];
    const uint32_t sb = smem_u32(smem_raw);

    const int tid  = threadIdx.x;
    const int wid  = tid >> 5;
    const int lane = tid & 31;
    const int rowStart = blockIdx.y * 128;
    const int colStart = blockIdx.x * 128;
    const int warp_m = (wid & 1) * 64;
    const int warp_n = (wid >> 1) * 32;

    const __half* gA  = A  + (size_t)rowStart * Dn;
    const __half* gB0 = Bh + (size_t)colStart * Dn;
    const __half* gB1 = Bl + (size_t)colStart * Dn;

    const uint32_t aoff = (uint32_t)((lane & 15) * ROWB + (lane >> 4) * 16);
    const uint32_t boff = (uint32_t)(((lane & 7) + ((lane >> 4) << 3)) * ROWB
                                     + ((lane >> 3) & 1) * 16);

    float acc[4][4][4];
    #pragma unroll
    for (int i = 0; i < 4; i++)
        #pragma unroll
        for (int j = 0; j < 4; j++)
            #pragma unroll
            for (int r = 0; r < 4; r++) acc[i][j][r] = 0.f;

    const int NCHUNK = Dn / KC;

    {
        const uint32_t bb = sb;
        load_tile(gA,  Dn, bb,            tid);
        load_tile(gB0, Dn, bb + TILE_B,   tid);
        load_tile(gB1, Dn, bb + 2*TILE_B, tid);
        cp_commit();
    }

    #pragma unroll 1
    for (int c = 0; c < NCHUNK; ++c) {
        if (c + 1 < NCHUNK) {
            const uint32_t bb = sb + ((c + 1) & 1) * DBUF_B;
            const int k0 = (c + 1) * KC;
            load_tile(gA  + k0, Dn, bb,            tid);
            load_tile(gB0 + k0, Dn, bb + TILE_B,   tid);
            load_tile(gB1 + k0, Dn, bb + 2*TILE_B, tid);
            cp_commit();
            cp_wait<1>();
        } else {
            cp_wait<0>();
        }
        __syncthreads();

        const uint32_t bb  = sb + (c & 1) * DBUF_B;
        const uint32_t sA  = bb;
        const uint32_t sBh = bb + TILE_B;
        const uint32_t sBl = bb + 2*TILE_B;

        #pragma unroll
        for (int kk = 0; kk < 2; ++kk) {
            const uint32_t kb = (uint32_t)(kk * 32);
            uint32_t afrag[4][4], bfrag[4][2];

            #pragma unroll
            for (int i = 0; i < 4; ++i)
                ldsm4(afrag[i], sA + aoff + kb + (uint32_t)((warp_m + i*16) * ROWB));

            #pragma unroll
            for (int p = 0; p < 2; ++p) {
                uint32_t r[4];
                ldsm4(r, sBh + boff + kb + (uint32_t)((warp_n + p*16) * ROWB));
                bfrag[p*2][0] = r[0]; bfrag[p*2][1] = r[1];
                bfrag[p*2+1][0] = r[2]; bfrag[p*2+1][1] = r[3];
            }
            #pragma unroll
            for (int i = 0; i < 4; ++i)
                #pragma unroll
                for (int j = 0; j < 4; ++j)
                    mma_f16(acc[i][j], afrag[i], bfrag[j]);

            #pragma unroll
            for (int p = 0; p < 2; ++p) {
                uint32_t r[4];
                ldsm4(r, sBl + boff + kb + (uint32_t)((warp_n + p*16) * ROWB));
                bfrag[p*2][0] = r[0]; bfrag[p*2][1] = r[1];
                bfrag[p*2+1][0] = r[2]; bfrag[p*2+1][1] = r[3];
            }
            #pragma unroll
            for (int i = 0; i < 4; ++i)
                #pragma unroll
                for (int j = 0; j < 4; ++j)
                    mma_f16(acc[i][j], afrag[i], bfrag[j]);
        }
        __syncthreads();
    }

    #pragma unroll
    for (int i = 0; i < 4; ++i) {
        const int r0 = rowStart + warp_m + i * 16 + (lane >> 2);
        #pragma unroll
        for (int half = 0; half < 2; ++half) {
            const int r = r0 + half * 8;
            #pragma unroll
            for (int j = 0; j < 4; ++j) {
                const int c0 = colStart + warp_n + j * 8 + (lane & 3) * 2;
                *(float2*)&Cf[(size_t)r * Dn + c0] =
                    make_float2(acc[i][j][half*2] + bias[c0],
                                acc[i][j][half*2+1] + bias[c0 + 1]);
            }
        }
    }
}

// ============================================================================
// Logits: Q x K (fp16 single, 1 pass), fp32 out, upper tiles skipped.
// ============================================================================
#define LBUF_B     (2 * TILE_B)
#define LOGIT_SMEM (2 * LBUF_B)      // 40960

__global__ void __launch_bounds__(256)
logits_f16(const __half* __restrict__ Q, const __half* __restrict__ K,
           float* __restrict__ P)
{
    const int bh = blockIdx.z;
    const int rowStart = blockIdx.y * 128;
    const int colStart = blockIdx.x * 128;
    if (colStart > rowStart) return;

    extern __shared__ char smem_raw[];
    const uint32_t sb = smem_u32(smem_raw);

    const int b = bh >> 4, h = bh & 15;
    const int tid  = threadIdx.x;
    const int wid  = tid >> 5;
    const int lane = tid & 31;
    const int warp_m = (wid & 1) * 64;
    const int warp_n = (wid >> 1) * 32;

    const __half* gQ = Q + ((size_t)(b * Sn + rowStart) * Hn + h) * HDn;
    const __half* gK = K + ((size_t)(b * Sn + colStart) * Hn + h) * HDn;

    const uint32_t aoff = (uint32_t)((lane & 15) * ROWB + (lane >> 4) * 16);
    const uint32_t boff = (uint32_t)(((lane & 7) + ((lane >> 4) << 3)) * ROWB
                                     + ((lane >> 3) & 1) * 16);

    float acc[4][4][4];
    #pragma unroll
    for (int i = 0; i < 4; i++)
        #pragma unroll
        for (int j = 0; j < 4; j++)
            #pragma unroll
            for (int r = 0; r < 4; r++) acc[i][j][r] = 0.f;

    {
        const uint32_t bb = sb;
        load_tile(gQ, Dn, bb,          tid);
        load_tile(gK, Dn, bb + TILE_B, tid);
        cp_commit();
    }

    #pragma unroll 1
    for (int c = 0; c < 4; ++c) {
        if (c + 1 < 4) {
            const uint32_t bb = sb + ((c + 1) & 1) * LBUF_B;
            const int k0 = (c + 1) * KC;
            load_tile(gQ + k0, Dn, bb,          tid);
            load_tile(gK + k0, Dn, bb + TILE_B, tid);
            cp_commit();
            cp_wait<1>();
        } else {
            cp_wait<0>();
        }
        __syncthreads();

        const uint32_t bb = sb + (c & 1) * LBUF_B;
        const uint32_t sQ = bb, sK = bb + TILE_B;

        #pragma unroll
        for (int kk = 0; kk < 2; ++kk) {
            const uint32_t kb = (uint32_t)(kk * 32);
            uint32_t afrag[4][4], bfrag[4][2];

            #pragma unroll
            for (int i = 0; i < 4; ++i)
                ldsm4(afrag[i], sQ + aoff + kb + (uint32_t)((warp_m + i*16) * ROWB));
            #pragma unroll
            for (int p = 0; p < 2; ++p) {
                uint32_t r[4];
                ldsm4(r, sK + boff + kb + (uint32_t)((warp_n + p*16) * ROWB));
                bfrag[p*2][0] = r[0]; bfrag[p*2][1] = r[1];
                bfrag[p*2+1][0] = r[2]; bfrag[p*2+1][1] = r[3];
            }
            #pragma unroll
            for (int i = 0; i < 4; ++i)
                #pragma unroll
                for (int j = 0; j < 4; ++j)
                    mma_f16(acc[i][j], afrag[i], bfrag[j]);
        }
        __syncthreads();
    }

    const float scale = 0.08838834764831843f;
    float* Pout = P + (size_t)bh * Sn * Sn;
    #pragma unroll
    for (int i = 0; i < 4; ++i) {
        const int s0 = rowStart + warp_m + i * 16 + (lane >> 2);
        #pragma unroll
        for (int half = 0; half < 2; ++half) {
            const int s = s0 + half * 8;
            #pragma unroll
            for (int j = 0; j < 4; ++j) {
                const int t0 = colStart + warp_n + j * 8 + (lane & 3) * 2;
                *(float2*)&Pout[(size_t)s * Sn + t0] =
                    make_float2(acc[i][j][half*2] * scale, acc[i][j][half*2+1] * scale);
            }
        }
    }
}

// ============================================================================
// Softmax: fp32 logits -> fp16 probs, mask by index.
// ============================================================================
__global__ void __launch_bounds__(128)
softmax_kernel(const float* __restrict__ P, __half* __restrict__ P16)
{
    const size_t row = blockIdx.x;
    const float* p = P + row * Sn;
    const int s = (int)(row & (Sn - 1));
    const int tid = threadIdx.x;
    float4 v = ((const float4*)p)[tid];
    const int t0 = tid * 4;
    v.x = (t0     <= s) ? v.x : -1e9f;
    v.y = (t0 + 1 <= s) ? v.y : -1e9f;
    v.z = (t0 + 2 <= s) ? v.z : -1e9f;
    v.w = (t0 + 3 <= s) ? v.w : -1e9f;

    float mx = fmaxf(fmaxf(v.x, v.y), fmaxf(v.z, v.w));
    #pragma unroll
    for (int o = 16; o; o >>= 1) mx = fmaxf(mx, __shfl_xor_sync(0xffffffffu, mx, o));
    __shared__ float red[4];
    if ((tid & 31) == 0) red[tid >> 5] = mx;
    __syncthreads();
    mx = fmaxf(fmaxf(red[0], red[1]), fmaxf(red[2], red[3]));

    float e0 = expf(v.x - mx), e1 = expf(v.y - mx);
    float e2 = expf(v.z - mx), e3 = expf(v.w - mx);
    float sm = e0 + e1 + e2 + e3;
    #pragma unroll
    for (int o = 16; o; o >>= 1) sm += __shfl_xor_sync(0xffffffffu, sm, o);
    __shared__ float red2[4];
    if ((tid & 31) == 0) red2[tid >> 5] = sm;
    __syncthreads();
    sm = red2[0] + red2[1] + red2[2] + red2[3];

    const float inv = 1.0f / sm;
    __half2* P2 = (__half2*)(P16 + row * Sn);
    P2[tid*2]   = __floats2half2_rn(e0 * inv, e1 * inv);
    P2[tid*2+1] = __floats2half2_rn(e2 * inv, e3 * inv);
}

// ============================================================================
// AV: P x V (fp16 single, 1 pass); fp16 out for WO.
// ============================================================================
#define AVBUF_B  (TILE_B + VTILE_B)       // 18944
#define AV_SMEM  (2 * AVBUF_B)            // 37888

__global__ void __launch_bounds__(256)
av_f16(const __half* __restrict__ P16, const __half* __restrict__ V,
       __half* __restrict__ O16)
{
    extern __shared__ char smem_raw[];
    const uint32_t sb = smem_u32(smem_raw);

    const int bh = blockIdx.z;
    const int b = bh >> 4, h = bh & 15;
    const int rowStart = blockIdx.y * 128;
    const int tid  = threadIdx.x;
    const int wid  = tid >> 5;
    const int lane = tid & 31;
    const int warp_m = (wid & 1) * 64;
    const int warp_n = (wid >> 1) * 32;

    const __half* gP = P16 + (size_t)bh * Sn * Sn + (size_t)rowStart * Sn;
    const __half* gV = V + (size_t)(b * Sn) * Dn + h * HDn;

    const uint32_t aoff  = (uint32_t)((lane & 15) * ROWB + (lane >> 4) * 16);
    const uint32_t boffT = (uint32_t)(((lane & 7) + ((lane >> 3) & 1) * 8) * VROWB
                                      + (lane >> 4) * 16);

    float acc[4][4][4];
    #pragma unroll
    for (int i = 0; i < 4; i++)
        #pragma unroll
        for (int j = 0; j < 4; j++)
            #pragma unroll
            for (int r = 0; r < 4; r++) acc[i][j][r] = 0.f;

    const int nchunk = (blockIdx.y + 1) * 4;

    {
        const uint32_t bb = sb;
        load_tile (gP, Sn, bb, tid);
        load_vtile(gV, bb + TILE_B, tid);
        cp_commit();
    }

    #pragma unroll 1
    for (int c = 0; c < nchunk; ++c) {
        if (c + 1 < nchunk) {
            const uint32_t bb = sb + ((c + 1) & 1) * AVBUF_B;
            const int k0 = (c + 1) * KC;
            load_tile (gP + k0, Sn, bb, tid);
            load_vtile(gV + (size_t)k0 * Dn, bb + TILE_B, tid);
            cp_commit();
            cp_wait<1>();
        } else {
            cp_wait<0>();
        }
        __syncthreads();

        const uint32_t bb = sb + (c & 1) * AVBUF_B;
        const uint32_t sP = bb, sV = bb + TILE_B;

        #pragma unroll
        for (int kk = 0; kk < 2; ++kk) {
            const uint32_t kbA = (uint32_t)(kk * 32);
            const uint32_t kbB = (uint32_t)(kk * 16 * VROWB);
            uint32_t afrag[4][4], bfrag[4][2];

            #pragma unroll
            for (int i = 0; i < 4; ++i)
                ldsm4(afrag[i], sP + aoff + kbA + (uint32_t)((warp_m + i*16) * ROWB));
            #pragma unroll
            for (int g = 0; g < 2; ++g) {
                uint32_t r[4];
                ldsm4t(r, sV + boffT + kbB + (uint32_t)((warp_n + g*16) * 2));
                bfrag[g*2][0] = r[0]; bfrag[g*2][1] = r[1];
                bfrag[g*2+1][0] = r[2]; bfrag[g*2+1][1] = r[3];
            }
            #pragma unroll
            for (int i = 0; i < 4; ++i)
                #pragma unroll
                for (int j = 0; j < 4; ++j)
                    mma_f16(acc[i][j], afrag[i], bfrag[j]);
        }
        __syncthreads();
    }

    #pragma unroll
    for (int i = 0; i < 4; ++i) {
        const int s0 = rowStart + warp_m + i * 16 + (lane >> 2);
        #pragma unroll
        for (int half = 0; half < 2; ++half) {
            const int s = s0 + half * 8;
            const size_t rbase = ((size_t)(b * Sn + s)) * Dn + h * HDn;
            #pragma unroll
            for (int j = 0; j < 4; ++j) {
                const int c0 = warp_n + j * 8 + (lane & 3) * 2;
                *(__half2*)&O16[rbase + c0] =
                    __floats2half2_rn(acc[i][j][half*2], acc[i][j][half*2+1]);
            }
        }
    }
}

// ============================================================================
extern "C" void kernel_launch(void* const* d_in, const int* in_sizes, int n_in,
                              void* d_out, int out_size)
{
    const float* x  = (const float*)d_in[0];
    const float* wq = (const float*)d_in[2];
    const float* bq = (const float*)d_in[3];
    const float* wk = (const float*)d_in[4];
    const float* bk = (const float*)d_in[5];
    const float* wv = (const float*)d_in[6];
    const float* bv = (const float*)d_in[7];
    const float* wo = (const float*)d_in[8];
    const float* bo = (const float*)d_in[9];
    float* out = (float*)d_out;

    float* pp;
    __half *p16, *x16, *o16, *w16, *woh, *wol, *q16, *k16, *v16;
    cudaGetSymbolAddress((void**)&pp,  g_p);
    cudaGetSymbolAddress((void**)&p16, g_p16);
    cudaGetSymbolAddress((void**)&x16, g_x16);
    cudaGetSymbolAddress((void**)&o16, g_o16);
    cudaGetSymbolAddress((void**)&w16, g_w16);
    cudaGetSymbolAddress((void**)&woh, g_woh);
    cudaGetSymbolAddress((void**)&wol, g_wol);
    cudaGetSymbolAddress((void**)&q16, g_q16);
    cudaGetSymbolAddress((void**)&k16, g_k16);
    cudaGetSymbolAddress((void**)&v16, g_v16);

    cudaFuncSetAttribute(gemm_f16s<1>, cudaFuncAttributeMaxDynamicSharedMemorySize, GEMM_SMEM_S);
    cudaFuncSetAttribute(gemm_f16s<2>, cudaFuncAttributeMaxDynamicSharedMemorySize, GEMM_SMEM_S);
    cudaFuncSetAttribute(gemm_f16d,   cudaFuncAttributeMaxDynamicSharedMemorySize, GEMM_SMEM_D);
    cudaFuncSetAttribute(logits_f16,  cudaFuncAttributeMaxDynamicSharedMemorySize, LOGIT_SMEM);
    cudaFuncSetAttribute(av_f16,      cudaFuncAttributeMaxDynamicSharedMemorySize, AV_SMEM);

    const int nSplitBlks = (int)(((size_t)Mtot * Dn / 4) / 256);
    dim3 gT(Dn / 32, Dn / 32), bT(32, 8);
    dim3 gG(Dn / 128, Mtot / 128);   // (16, 64)

    const size_t WSZ = (size_t)Dn * Dn;

    // --- preprocessing up front ---
    half_kernel<<<nSplitBlks, 256>>>((const float4*)x, x16);
    halfT_kernel<<<gT, bT>>>(wq, w16);
    halfT_kernel<<<gT, bT>>>(wk, w16 + WSZ);
    halfT_kernel<<<gT, bT>>>(wv, w16 + 2*WSZ);
    splitT_kernel<<<gT, bT>>>(wo, woh, wol);

    // --- Q/K/V projections (fp16 single x single, 1 pass) ---
    gemm_f16s<1><<<gG, 256, GEMM_SMEM_S>>>(x16, w16,         bq, q16);
    gemm_f16s<1><<<gG, 256, GEMM_SMEM_S>>>(x16, w16 + WSZ,   bk, k16);
    gemm_f16s<2><<<gG, 256, GEMM_SMEM_S>>>(x16, w16 + 2*WSZ, bv, v16);

    // --- attention (fp16 single) ---
    dim3 glog(Sn / 128, Sn / 128, Bn * Hn);
    logits_f16<<<glog, 256, LOGIT_SMEM>>>(q16, k16, pp);
    softmax_kernel<<<Bn * Hn * Sn, 128>>>(pp, p16);
    dim3 gav(1, Sn / 128, Bn * Hn);
    av_f16<<<gav, 256, AV_SMEM>>>(p16, v16, o16);

    // --- output projection (A single x B split-2, fp32 out) ---
    gemm_f16d<<<gG, 256, GEMM_SMEM_D>>>(o16, woh, wol, bo, out);
}

// round 12
// speedup vs baseline: 2.3247x; 1.1047x over previous
#include <cuda_runtime.h>
#include <cuda_fp16.h>
#include <math.h>
#include <stdint.h>

#define Bn   16
#define Sn   512
#define Dn   2048
#define Hn   16
#define HDn  128
#define Mtot (Bn*Sn)      // 8192

// ---------------- scratch (alloc-free: __device__ globals) ----------------
__device__ float g_p[(size_t)Bn * Hn * Sn * Sn];     // 256 MB logits (fp32)
__device__ __half g_p16[(size_t)Bn * Hn * Sn * Sn];  // 128 MB probs (fp16)
__device__ __half g_x16[(size_t)Mtot * Dn];          // 32 MB x (fp16)
__device__ __half g_o16[(size_t)Mtot * Dn];          // 32 MB attn-out (fp16)
__device__ __half g_w16[(size_t)4 * Dn * Dn];        // 32 MB W^T q|k|v|o
__device__ __half g_q16[(size_t)Mtot * Dn];          // 32 MB Q
__device__ __half g_k16[(size_t)Mtot * Dn];          // 32 MB K
__device__ __half g_v16[(size_t)Mtot * Dn];          // 32 MB V

// ============================================================================
// PTX helpers
// ============================================================================
__device__ __forceinline__ uint32_t smem_u32(const void* p) {
    uint32_t a;
    asm("{ .reg .u64 t; cvta.to.shared.u64 t, %1; cvt.u32.u64 %0, t; }" : "=r"(a) : "l"(p));
    return a;
}
__device__ __forceinline__ void cp16(uint32_t saddr, const void* gptr) {
    asm volatile("cp.async.cg.shared.global [%0], [%1], 16;" :: "r"(saddr), "l"(gptr) : "memory");
}
__device__ __forceinline__ void cp_commit() {
    asm volatile("cp.async.commit_group;" ::: "memory");
}
template <int N>
__device__ __forceinline__ void cp_wait() {
    asm volatile("cp.async.wait_group %0;" :: "n"(N) : "memory");
}
__device__ __forceinline__ void ldsm4(uint32_t* r, uint32_t addr) {
    asm volatile("ldmatrix.sync.aligned.m8n8.x4.shared.b16 {%0,%1,%2,%3}, [%4];"
                 : "=r"(r[0]), "=r"(r[1]), "=r"(r[2]), "=r"(r[3]) : "r"(addr));
}
__device__ __forceinline__ void ldsm4t(uint32_t* r, uint32_t addr) {
    asm volatile("ldmatrix.sync.aligned.m8n8.x4.trans.shared.b16 {%0,%1,%2,%3}, [%4];"
                 : "=r"(r[0]), "=r"(r[1]), "=r"(r[2]), "=r"(r[3]) : "r"(addr));
}
__device__ __forceinline__ void mma_f16(float* d, const uint32_t* a, const uint32_t* b) {
    asm volatile("mma.sync.aligned.m16n8k16.row.col.f32.f16.f16.f32 "
                 "{%0,%1,%2,%3}, {%4,%5,%6,%7}, {%8,%9}, {%0,%1,%2,%3};"
                 : "+f"(d[0]), "+f"(d[1]), "+f"(d[2]), "+f"(d[3])
                 : "r"(a[0]), "r"(a[1]), "r"(a[2]), "r"(a[3]), "r"(b[0]), "r"(b[1]));
}

// ============================================================================
// Tile geometry
// ============================================================================
#define KC      32
#define ROWB    80
#define TILE_B  (128 * ROWB)         // 10240 B
#define VROWB   272
#define VTILE_B (32 * VROWB)         // 8704 B

template <typename T>
__device__ __forceinline__ void load_tile(const T* __restrict__ g,
                                          int ldg, uint32_t sdst, int tid)
{
    #pragma unroll
    for (int it = 0; it < 2; ++it) {
        int idx = tid + it * 256;
        int row = idx >> 2, seg = idx & 3;
        cp16(sdst + (uint32_t)(row * ROWB + seg * 16),
             (const char*)(g + (size_t)row * ldg) + seg * 16);
    }
}
__device__ __forceinline__ void load_vtile(const __half* __restrict__ g,
                                           uint32_t sdst, int tid)
{
    #pragma unroll
    for (int it = 0; it < 2; ++it) {
        int idx = tid + it * 256;
        int row = idx >> 4, seg = idx & 15;
        cp16(sdst + (uint32_t)(row * VROWB + seg * 16),
             (const char*)(g + (size_t)row * Dn) + seg * 16);
    }
}

// ============================================================================
// Preprocessing
// ============================================================================
__global__ void __launch_bounds__(256)
half_kernel(const float4* __restrict__ X, __half* __restrict__ H)
{
    size_t i = (size_t)blockIdx.x * 256 + threadIdx.x;
    float4 v = X[i];
    __half2* H2 = (__half2*)H;
    H2[2*i]   = __floats2half2_rn(v.x, v.y);
    H2[2*i+1] = __floats2half2_rn(v.z, v.w);
}

// W[k][n] fp32 -> T[n][k] fp16
__global__ void __launch_bounds__(256)
halfT_kernel(const float* __restrict__ W, __half* __restrict__ T)
{
    __shared__ float t[32][33];
    int bx = blockIdx.x * 32;   // n
    int by = blockIdx.y * 32;   // k
    int tx = threadIdx.x, ty = threadIdx.y;
    #pragma unroll
    for (int i = 0; i < 32; i += 8)
        t[ty + i][tx] = W[(size_t)(by + ty + i) * Dn + bx + tx];
    __syncthreads();
    #pragma unroll
    for (int i = 0; i < 32; i += 8)
        T[(size_t)(bx + ty + i) * Dn + by + tx] = __float2half_rn(t[tx][ty + i]);
}

// ============================================================================
// fp16 single x single GEMM (1 pass/kk). 256 threads, 8 warps, warp 64x32,
// CTA 128x128. EPI: 0 = bias->fp32, 1 = bias+RoPE->fp16, 2 = bias->fp16.
// ============================================================================
#define SBUF_B      (2 * TILE_B)     // A, B
#define GEMM_SMEM_S (2 * SBUF_B)     // 40960

template <int EPI>
__global__ void __launch_bounds__(256)
gemm_f16s(const __half* __restrict__ A, const __half* __restrict__ B,
          const float* __restrict__ bias, __half* __restrict__ O,
          float* __restrict__ Cf)
{
    extern __shared__ char smem_raw[];
    const uint32_t sb = smem_u32(smem_raw);

    const int tid  = threadIdx.x;
    const int wid  = tid >> 5;
    const int lane = tid & 31;
    const int rowStart = blockIdx.y * 128;
    const int colStart = blockIdx.x * 128;
    const int warp_m = (wid & 1) * 64;
    const int warp_n = (wid >> 1) * 32;

    const __half* gA = A + (size_t)rowStart * Dn;
    const __half* gB = B + (size_t)colStart * Dn;

    const uint32_t aoff = (uint32_t)((lane & 15) * ROWB + (lane >> 4) * 16);
    const uint32_t boff = (uint32_t)(((lane & 7) + ((lane >> 4) << 3)) * ROWB
                                     + ((lane >> 3) & 1) * 16);

    float acc[4][4][4];
    #pragma unroll
    for (int i = 0; i < 4; i++)
        #pragma unroll
        for (int j = 0; j < 4; j++)
            #pragma unroll
            for (int r = 0; r < 4; r++) acc[i][j][r] = 0.f;

    const int NCHUNK = Dn / KC;   // 64

    {
        const uint32_t bb = sb;
        load_tile(gA, Dn, bb,          tid);
        load_tile(gB, Dn, bb + TILE_B, tid);
        cp_commit();
    }

    #pragma unroll 1
    for (int c = 0; c < NCHUNK; ++c) {
        if (c + 1 < NCHUNK) {
            const uint32_t bb = sb + ((c + 1) & 1) * SBUF_B;
            const int k0 = (c + 1) * KC;
            load_tile(gA + k0, Dn, bb,          tid);
            load_tile(gB + k0, Dn, bb + TILE_B, tid);
            cp_commit();
            cp_wait<1>();
        } else {
            cp_wait<0>();
        }
        __syncthreads();

        const uint32_t bb = sb + (c & 1) * SBUF_B;
        const uint32_t sA = bb, sB = bb + TILE_B;

        #pragma unroll
        for (int kk = 0; kk < 2; ++kk) {
            const uint32_t kb = (uint32_t)(kk * 32);
            uint32_t afrag[4][4], bfrag[4][2];

            #pragma unroll
            for (int i = 0; i < 4; ++i)
                ldsm4(afrag[i], sA + aoff + kb + (uint32_t)((warp_m + i*16) * ROWB));
            #pragma unroll
            for (int p = 0; p < 2; ++p) {
                uint32_t r[4];
                ldsm4(r, sB + boff + kb + (uint32_t)((warp_n + p*16) * ROWB));
                bfrag[p*2][0] = r[0]; bfrag[p*2][1] = r[1];
                bfrag[p*2+1][0] = r[2]; bfrag[p*2+1][1] = r[3];
            }
            #pragma unroll
            for (int i = 0; i < 4; ++i)
                #pragma unroll
                for (int j = 0; j < 4; ++j)
                    mma_f16(acc[i][j], afrag[i], bfrag[j]);
        }
        __syncthreads();
    }

    #pragma unroll
    for (int i = 0; i < 4; ++i) {
        const int r0 = rowStart + warp_m + i * 16 + (lane >> 2);
        #pragma unroll
        for (int half = 0; half < 2; ++half) {
            const int r = r0 + half * 8;
            const int s = r & (Sn - 1);
            #pragma unroll
            for (int j = 0; j < 4; ++j) {
                const int c0 = colStart + warp_n + j * 8 + (lane & 3) * 2;
                float v0 = acc[i][j][half*2]   + bias[c0];
                float v1 = acc[i][j][half*2+1] + bias[c0 + 1];
                if (EPI == 1) {
                    int pidx = (c0 & (HDn - 1)) >> 1;
                    float inv = exp2f((float)pidx * (-13.287712379549449f / 64.0f));
                    float sn, cs;
                    sincosf((float)s * inv, &sn, &cs);
                    float e = v0, o = v1;
                    v0 = e * cs - o * sn;
                    v1 = o * cs + e * sn;
                }
                if (EPI == 0)
                    *(float2*)&Cf[(size_t)r * Dn + c0] = make_float2(v0, v1);
                else
                    *(__half2*)&O[(size_t)r * Dn + c0] = __floats2half2_rn(v0, v1);
            }
        }
    }
}

// ============================================================================
// Logits: Q x K (fp16 single, 1 pass), fp32 out, upper tiles skipped.
// ============================================================================
#define LBUF_B     (2 * TILE_B)
#define LOGIT_SMEM (2 * LBUF_B)      // 40960

__global__ void __launch_bounds__(256)
logits_f16(const __half* __restrict__ Q, const __half* __restrict__ K,
           float* __restrict__ P)
{
    const int bh = blockIdx.z;
    const int rowStart = blockIdx.y * 128;
    const int colStart = blockIdx.x * 128;
    if (colStart > rowStart) return;

    extern __shared__ char smem_raw[];
    const uint32_t sb = smem_u32(smem_raw);

    const int b = bh >> 4, h = bh & 15;
    const int tid  = threadIdx.x;
    const int wid  = tid >> 5;
    const int lane = tid & 31;
    const int warp_m = (wid & 1) * 64;
    const int warp_n = (wid >> 1) * 32;

    const __half* gQ = Q + ((size_t)(b * Sn + rowStart) * Hn + h) * HDn;
    const __half* gK = K + ((size_t)(b * Sn + colStart) * Hn + h) * HDn;

    const uint32_t aoff = (uint32_t)((lane & 15) * ROWB + (lane >> 4) * 16);
    const uint32_t boff = (uint32_t)(((lane & 7) + ((lane >> 4) << 3)) * ROWB
                                     + ((lane >> 3) & 1) * 16);

    float acc[4][4][4];
    #pragma unroll
    for (int i = 0; i < 4; i++)
        #pragma unroll
        for (int j = 0; j < 4; j++)
            #pragma unroll
            for (int r = 0; r < 4; r++) acc[i][j][r] = 0.f;

    {
        const uint32_t bb = sb;
        load_tile(gQ, Dn, bb,          tid);
        load_tile(gK, Dn, bb + TILE_B, tid);
        cp_commit();
    }

    #pragma unroll 1
    for (int c = 0; c < 4; ++c) {
        if (c + 1 < 4) {
            const uint32_t bb = sb + ((c + 1) & 1) * LBUF_B;
            const int k0 = (c + 1) * KC;
            load_tile(gQ + k0, Dn, bb,          tid);
            load_tile(gK + k0, Dn, bb + TILE_B, tid);
            cp_commit();
            cp_wait<1>();
        } else {
            cp_wait<0>();
        }
        __syncthreads();

        const uint32_t bb = sb + (c & 1) * LBUF_B;
        const uint32_t sQ = bb, sK = bb + TILE_B;

        #pragma unroll
        for (int kk = 0; kk < 2; ++kk) {
            const uint32_t kb = (uint32_t)(kk * 32);
            uint32_t afrag[4][4], bfrag[4][2];

            #pragma unroll
            for (int i = 0; i < 4; ++i)
                ldsm4(afrag[i], sQ + aoff + kb + (uint32_t)((warp_m + i*16) * ROWB));
            #pragma unroll
            for (int p = 0; p < 2; ++p) {
                uint32_t r[4];
                ldsm4(r, sK + boff + kb + (uint32_t)((warp_n + p*16) * ROWB));
                bfrag[p*2][0] = r[0]; bfrag[p*2][1] = r[1];
                bfrag[p*2+1][0] = r[2]; bfrag[p*2+1][1] = r[3];
            }
            #pragma unroll
            for (int i = 0; i < 4; ++i)
                #pragma unroll
                for (int j = 0; j < 4; ++j)
                    mma_f16(acc[i][j], afrag[i], bfrag[j]);
        }
        __syncthreads();
    }

    const float scale = 0.08838834764831843f;
    float* Pout = P + (size_t)bh * Sn * Sn;
    #pragma unroll
    for (int i = 0; i < 4; ++i) {
        const int s0 = rowStart + warp_m + i * 16 + (lane >> 2);
        #pragma unroll
        for (int half = 0; half < 2; ++half) {
            const int s = s0 + half * 8;
            #pragma unroll
            for (int j = 0; j < 4; ++j) {
                const int t0 = colStart + warp_n + j * 8 + (lane & 3) * 2;
                *(float2*)&Pout[(size_t)s * Sn + t0] =
                    make_float2(acc[i][j][half*2] * scale, acc[i][j][half*2+1] * scale);
            }
        }
    }
}

// ============================================================================
// Softmax: fp32 logits -> fp16 probs, mask by index.
// ============================================================================
__global__ void __launch_bounds__(128)
softmax_kernel(const float* __restrict__ P, __half* __restrict__ P16)
{
    const size_t row = blockIdx.x;
    const float* p = P + row * Sn;
    const int s = (int)(row & (Sn - 1));
    const int tid = threadIdx.x;
    float4 v = ((const float4*)p)[tid];
    const int t0 = tid * 4;
    v.x = (t0     <= s) ? v.x : -1e9f;
    v.y = (t0 + 1 <= s) ? v.y : -1e9f;
    v.z = (t0 + 2 <= s) ? v.z : -1e9f;
    v.w = (t0 + 3 <= s) ? v.w : -1e9f;

    float mx = fmaxf(fmaxf(v.x, v.y), fmaxf(v.z, v.w));
    #pragma unroll
    for (int o = 16; o; o >>= 1) mx = fmaxf(mx, __shfl_xor_sync(0xffffffffu, mx, o));
    __shared__ float red[4];
    if ((tid & 31) == 0) red[tid >> 5] = mx;
    __syncthreads();
    mx = fmaxf(fmaxf(red[0], red[1]), fmaxf(red[2], red[3]));

    float e0 = expf(v.x - mx), e1 = expf(v.y - mx);
    float e2 = expf(v.z - mx), e3 = expf(v.w - mx);
    float sm = e0 + e1 + e2 + e3;
    #pragma unroll
    for (int o = 16; o; o >>= 1) sm += __shfl_xor_sync(0xffffffffu, sm, o);
    __shared__ float red2[4];
    if ((tid & 31) == 0) red2[tid >> 5] = sm;
    __syncthreads();
    sm = red2[0] + red2[1] + red2[2] + red2[3];

    const float inv = 1.0f / sm;
    __half2* P2 = (__half2*)(P16 + row * Sn);
    P2[tid*2]   = __floats2half2_rn(e0 * inv, e1 * inv);
    P2[tid*2+1] = __floats2half2_rn(e2 * inv, e3 * inv);
}

// ============================================================================
// AV: P x V (fp16 single, 1 pass); fp16 out.
// ============================================================================
#define AVBUF_B  (TILE_B + VTILE_B)       // 18944
#define AV_SMEM  (2 * AVBUF_B)            // 37888

__global__ void __launch_bounds__(256)
av_f16(const __half* __restrict__ P16, const __half* __restrict__ V,
       __half* __restrict__ O16)
{
    extern __shared__ char smem_raw[];
    const uint32_t sb = smem_u32(smem_raw);

    const int bh = blockIdx.z;
    const int b = bh >> 4, h = bh & 15;
    const int rowStart = blockIdx.y * 128;
    const int tid  = threadIdx.x;
    const int wid  = tid >> 5;
    const int lane = tid & 31;
    const int warp_m = (wid & 1) * 64;
    const int warp_n = (wid >> 1) * 32;

    const __half* gP = P16 + (size_t)bh * Sn * Sn + (size_t)rowStart * Sn;
    const __half* gV = V + (size_t)(b * Sn) * Dn + h * HDn;

    const uint32_t aoff  = (uint32_t)((lane & 15) * ROWB + (lane >> 4) * 16);
    const uint32_t boffT = (uint32_t)(((lane & 7) + ((lane >> 3) & 1) * 8) * VROWB
                                      + (lane >> 4) * 16);

    float acc[4][4][4];
    #pragma unroll
    for (int i = 0; i < 4; i++)
        #pragma unroll
        for (int j = 0; j < 4; j++)
            #pragma unroll
            for (int r = 0; r < 4; r++) acc[i][j][r] = 0.f;

    const int nchunk = (blockIdx.y + 1) * 4;

    {
        const uint32_t bb = sb;
        load_tile (gP, Sn, bb, tid);
        load_vtile(gV, bb + TILE_B, tid);
        cp_commit();
    }

    #pragma unroll 1
    for (int c = 0; c < nchunk; ++c) {
        if (c + 1 < nchunk) {
            const uint32_t bb = sb + ((c + 1) & 1) * AVBUF_B;
            const int k0 = (c + 1) * KC;
            load_tile (gP + k0, Sn, bb, tid);
            load_vtile(gV + (size_t)k0 * Dn, bb + TILE_B, tid);
            cp_commit();
            cp_wait<1>();
        } else {
            cp_wait<0>();
        }
        __syncthreads();

        const uint32_t bb = sb + (c & 1) * AVBUF_B;
        const uint32_t sP = bb, sV = bb + TILE_B;

        #pragma unroll
        for (int kk = 0; kk < 2; ++kk) {
            const uint32_t kbA = (uint32_t)(kk * 32);
            const uint32_t kbB = (uint32_t)(kk * 16 * VROWB);
            uint32_t afrag[4][4], bfrag[4][2];

            #pragma unroll
            for (int i = 0; i < 4; ++i)
                ldsm4(afrag[i], sP + aoff + kbA + (uint32_t)((warp_m + i*16) * ROWB));
            #pragma unroll
            for (int g = 0; g < 2; ++g) {
                uint32_t r[4];
                ldsm4t(r, sV + boffT + kbB + (uint32_t)((warp_n + g*16) * 2));
                bfrag[g*2][0] = r[0]; bfrag[g*2][1] = r[1];
                bfrag[g*2+1][0] = r[2]; bfrag[g*2+1][1] = r[3];
            }
            #pragma unroll
            for (int i = 0; i < 4; ++i)
                #pragma unroll
                for (int j = 0; j < 4; ++j)
                    mma_f16(acc[i][j], afrag[i], bfrag[j]);
        }
        __syncthreads();
    }

    #pragma unroll
    for (int i = 0; i < 4; ++i) {
        const int s0 = rowStart + warp_m + i * 16 + (lane >> 2);
        #pragma unroll
        for (int half = 0; half < 2; ++half) {
            const int s = s0 + half * 8;
            const size_t rbase = ((size_t)(b * Sn + s)) * Dn + h * HDn;
            #pragma unroll
            for (int j = 0; j < 4; ++j) {
                const int c0 = warp_n + j * 8 + (lane & 3) * 2;
                *(__half2*)&O16[rbase + c0] =
                    __floats2half2_rn(acc[i][j][half*2], acc[i][j][half*2+1]);
            }
        }
    }
}

// ============================================================================
extern "C" void kernel_launch(void* const* d_in, const int* in_sizes, int n_in,
                              void* d_out, int out_size)
{
    const float* x  = (const float*)d_in[0];
    const float* wq = (const float*)d_in[2];
    const float* bq = (const float*)d_in[3];
    const float* wk = (const float*)d_in[4];
    const float* bk = (const float*)d_in[5];
    const float* wv = (const float*)d_in[6];
    const float* bv = (const float*)d_in[7];
    const float* wo = (const float*)d_in[8];
    const float* bo = (const float*)d_in[9];
    float* out = (float*)d_out;

    float* pp;
    __half *p16, *x16, *o16, *w16, *q16, *k16, *v16;
    cudaGetSymbolAddress((void**)&pp,  g_p);
    cudaGetSymbolAddress((void**)&p16, g_p16);
    cudaGetSymbolAddress((void**)&x16, g_x16);
    cudaGetSymbolAddress((void**)&o16, g_o16);
    cudaGetSymbolAddress((void**)&w16, g_w16);
    cudaGetSymbolAddress((void**)&q16, g_q16);
    cudaGetSymbolAddress((void**)&k16, g_k16);
    cudaGetSymbolAddress((void**)&v16, g_v16);

    cudaFuncSetAttribute(gemm_f16s<0>, cudaFuncAttributeMaxDynamicSharedMemorySize, GEMM_SMEM_S);
    cudaFuncSetAttribute(gemm_f16s<1>, cudaFuncAttributeMaxDynamicSharedMemorySize, GEMM_SMEM_S);
    cudaFuncSetAttribute(gemm_f16s<2>, cudaFuncAttributeMaxDynamicSharedMemorySize, GEMM_SMEM_S);
    cudaFuncSetAttribute(logits_f16,  cudaFuncAttributeMaxDynamicSharedMemorySize, LOGIT_SMEM);
    cudaFuncSetAttribute(av_f16,      cudaFuncAttributeMaxDynamicSharedMemorySize, AV_SMEM);

    const int nSplitBlks = (int)(((size_t)Mtot * Dn / 4) / 256);
    dim3 gT(Dn / 32, Dn / 32), bT(32, 8);
    dim3 gG(Dn / 128, Mtot / 128);   // (16, 64)

    const size_t WSZ = (size_t)Dn * Dn;

    // --- preprocessing up front ---
    half_kernel<<<nSplitBlks, 256>>>((const float4*)x, x16);
    halfT_kernel<<<gT, bT>>>(wq, w16);
    halfT_kernel<<<gT, bT>>>(wk, w16 + WSZ);
    halfT_kernel<<<gT, bT>>>(wv, w16 + 2*WSZ);
    halfT_kernel<<<gT, bT>>>(wo, w16 + 3*WSZ);

    // --- Q/K/V projections (fp16 single, 1 pass) ---
    gemm_f16s<1><<<gG, 256, GEMM_SMEM_S>>>(x16, w16,         bq, q16, nullptr);
    gemm_f16s<1><<<gG, 256, GEMM_SMEM_S>>>(x16, w16 + WSZ,   bk, k16, nullptr);
    gemm_f16s<2><<<gG, 256, GEMM_SMEM_S>>>(x16, w16 + 2*WSZ, bv, v16, nullptr);

    // --- attention (fp16 single) ---
    dim3 glog(Sn / 128, Sn / 128, Bn * Hn);
    logits_f16<<<glog, 256, LOGIT_SMEM>>>(q16, k16, pp);
    softmax_kernel<<<Bn * Hn * Sn, 128>>>(pp, p16);
    dim3 gav(1, Sn / 128, Bn * Hn);
    av_f16<<<gav, 256, AV_SMEM>>>(p16, v16, o16);

    // --- output projection (fp16 single, fp32 out) ---
    gemm_f16s<0><<<gG, 256, GEMM_SMEM_S>>>(o16, w16 + 3*WSZ, bo, nullptr, out);
}

// round 13
// speedup vs baseline: 2.5375x; 1.0916x over previous
#include <cuda_runtime.h>
#include <cuda_fp16.h>
#include <math.h>
#include <stdint.h>

#define Bn   16
#define Sn   512
#define Dn   2048
#define Hn   16
#define HDn  128
#define Mtot (Bn*Sn)      // 8192

// ---------------- scratch (alloc-free: __device__ globals) ----------------
__device__ __half g_x16[(size_t)Mtot * Dn];          // 32 MB x (fp16)
__device__ __half g_o16[(size_t)Mtot * Dn];          // 32 MB attn-out (fp16)
__device__ __half g_w16[(size_t)4 * Dn * Dn];        // 32 MB W^T q|k|v|o
__device__ __half g_q16[(size_t)Mtot * Dn];          // 32 MB Q
__device__ __half g_k16[(size_t)Mtot * Dn];          // 32 MB K
__device__ __half g_v16[(size_t)Mtot * Dn];          // 32 MB V

// ============================================================================
// PTX helpers
// ============================================================================
__device__ __forceinline__ uint32_t smem_u32(const void* p) {
    uint32_t a;
    asm("{ .reg .u64 t; cvta.to.shared.u64 t, %1; cvt.u32.u64 %0, t; }" : "=r"(a) : "l"(p));
    return a;
}
__device__ __forceinline__ void cp16(uint32_t saddr, const void* gptr) {
    asm volatile("cp.async.cg.shared.global [%0], [%1], 16;" :: "r"(saddr), "l"(gptr) : "memory");
}
__device__ __forceinline__ void cp_commit() {
    asm volatile("cp.async.commit_group;" ::: "memory");
}
template <int N>
__device__ __forceinline__ void cp_wait() {
    asm volatile("cp.async.wait_group %0;" :: "n"(N) : "memory");
}
__device__ __forceinline__ void ldsm4(uint32_t* r, uint32_t addr) {
    asm volatile("ldmatrix.sync.aligned.m8n8.x4.shared.b16 {%0,%1,%2,%3}, [%4];"
                 : "=r"(r[0]), "=r"(r[1]), "=r"(r[2]), "=r"(r[3]) : "r"(addr));
}
__device__ __forceinline__ void ldsm4t(uint32_t* r, uint32_t addr) {
    asm volatile("ldmatrix.sync.aligned.m8n8.x4.trans.shared.b16 {%0,%1,%2,%3}, [%4];"
                 : "=r"(r[0]), "=r"(r[1]), "=r"(r[2]), "=r"(r[3]) : "r"(addr));
}
__device__ __forceinline__ void mma_f16(float* d, const uint32_t* a, const uint32_t* b) {
    asm volatile("mma.sync.aligned.m16n8k16.row.col.f32.f16.f16.f32 "
                 "{%0,%1,%2,%3}, {%4,%5,%6,%7}, {%8,%9}, {%0,%1,%2,%3};"
                 : "+f"(d[0]), "+f"(d[1]), "+f"(d[2]), "+f"(d[3])
                 : "r"(a[0]), "r"(a[1]), "r"(a[2]), "r"(a[3]), "r"(b[0]), "r"(b[1]));
}
__device__ __forceinline__ uint32_t pack_h2(float a, float b) {
    __half2 h = __floats2half2_rn(a, b);
    return *reinterpret_cast<uint32_t*>(&h);
}

// ============================================================================
// Tile geometry
// ============================================================================
#define KC      32
#define ROWB    80
#define TILE_B  (128 * ROWB)         // 10240 B
#define VROWB   272                  // 128 fp16 + 16B pad

template <typename T>
__device__ __forceinline__ void load_tile(const T* __restrict__ g,
                                          int ldg, uint32_t sdst, int tid)
{
    #pragma unroll
    for (int it = 0; it < 2; ++it) {
        int idx = tid + it * 256;
        int row = idx >> 2, seg = idx & 3;
        cp16(sdst + (uint32_t)(row * ROWB + seg * 16),
             (const char*)(g + (size_t)row * ldg) + seg * 16);
    }
}
// 128 rows x 128 fp16 cols (256B payload, VROWB stride), 256 threads
__device__ __forceinline__ void load_tile128w(const __half* __restrict__ g,
                                              uint32_t sdst, int tid)
{
    #pragma unroll
    for (int it = 0; it < 8; ++it) {
        int idx = tid + it * 256;
        int row = idx >> 4, seg = idx & 15;
        cp16(sdst + (uint32_t)(row * VROWB + seg * 16),
             (const char*)(g + (size_t)row * Dn) + seg * 16);
    }
}

// ============================================================================
// Preprocessing
// ============================================================================
__global__ void __launch_bounds__(256)
half_kernel(const float4* __restrict__ X, __half* __restrict__ H)
{
    size_t i = (size_t)blockIdx.x * 256 + threadIdx.x;
    float4 v = X[i];
    __half2* H2 = (__half2*)H;
    H2[2*i]   = __floats2half2_rn(v.x, v.y);
    H2[2*i+1] = __floats2half2_rn(v.z, v.w);
}

__global__ void __launch_bounds__(256)
halfT_kernel(const float* __restrict__ W, __half* __restrict__ T)
{
    __shared__ float t[32][33];
    int bx = blockIdx.x * 32;   // n
    int by = blockIdx.y * 32;   // k
    int tx = threadIdx.x, ty = threadIdx.y;
    #pragma unroll
    for (int i = 0; i < 32; i += 8)
        t[ty + i][tx] = W[(size_t)(by + ty + i) * Dn + bx + tx];
    __syncthreads();
    #pragma unroll
    for (int i = 0; i < 32; i += 8)
        T[(size_t)(bx + ty + i) * Dn + by + tx] = __float2half_rn(t[tx][ty + i]);
}

// ============================================================================
// fp16 single x single GEMM (unchanged from R12).
// EPI: 0 = bias->fp32, 1 = bias+RoPE->fp16, 2 = bias->fp16.
// ============================================================================
#define SBUF_B      (2 * TILE_B)
#define GEMM_SMEM_S (2 * SBUF_B)     // 40960

template <int EPI>
__global__ void __launch_bounds__(256)
gemm_f16s(const __half* __restrict__ A, const __half* __restrict__ B,
          const float* __restrict__ bias, __half* __restrict__ O,
          float* __restrict__ Cf)
{
    extern __shared__ char smem_raw[];
    const uint32_t sb = smem_u32(smem_raw);

    const int tid  = threadIdx.x;
    const int wid  = tid >> 5;
    const int lane = tid & 31;
    const int rowStart = blockIdx.y * 128;
    const int colStart = blockIdx.x * 128;
    const int warp_m = (wid & 1) * 64;
    const int warp_n = (wid >> 1) * 32;

    const __half* gA = A + (size_t)rowStart * Dn;
    const __half* gB = B + (size_t)colStart * Dn;

    const uint32_t aoff = (uint32_t)((lane & 15) * ROWB + (lane >> 4) * 16);
    const uint32_t boff = (uint32_t)(((lane & 7) + ((lane >> 4) << 3)) * ROWB
                                     + ((lane >> 3) & 1) * 16);

    float acc[4][4][4];
    #pragma unroll
    for (int i = 0; i < 4; i++)
        #pragma unroll
        for (int j = 0; j < 4; j++)
            #pragma unroll
            for (int r = 0; r < 4; r++) acc[i][j][r] = 0.f;

    const int NCHUNK = Dn / KC;   // 64

    {
        const uint32_t bb = sb;
        load_tile(gA, Dn, bb,          tid);
        load_tile(gB, Dn, bb + TILE_B, tid);
        cp_commit();
    }

    #pragma unroll 1
    for (int c = 0; c < NCHUNK; ++c) {
        if (c + 1 < NCHUNK) {
            const uint32_t bb = sb + ((c + 1) & 1) * SBUF_B;
            const int k0 = (c + 1) * KC;
            load_tile(gA + k0, Dn, bb,          tid);
            load_tile(gB + k0, Dn, bb + TILE_B, tid);
            cp_commit();
            cp_wait<1>();
        } else {
            cp_wait<0>();
        }
        __syncthreads();

        const uint32_t bb = sb + (c & 1) * SBUF_B;
        const uint32_t sA = bb, sB = bb + TILE_B;

        #pragma unroll
        for (int kk = 0; kk < 2; ++kk) {
            const uint32_t kb = (uint32_t)(kk * 32);
            uint32_t afrag[4][4], bfrag[4][2];

            #pragma unroll
            for (int i = 0; i < 4; ++i)
                ldsm4(afrag[i], sA + aoff + kb + (uint32_t)((warp_m + i*16) * ROWB));
            #pragma unroll
            for (int p = 0; p < 2; ++p) {
                uint32_t r[4];
                ldsm4(r, sB + boff + kb + (uint32_t)((warp_n + p*16) * ROWB));
                bfrag[p*2][0] = r[0]; bfrag[p*2][1] = r[1];
                bfrag[p*2+1][0] = r[2]; bfrag[p*2+1][1] = r[3];
            }
            #pragma unroll
            for (int i = 0; i < 4; ++i)
                #pragma unroll
                for (int j = 0; j < 4; ++j)
                    mma_f16(acc[i][j], afrag[i], bfrag[j]);
        }
        __syncthreads();
    }

    #pragma unroll
    for (int i = 0; i < 4; ++i) {
        const int r0 = rowStart + warp_m + i * 16 + (lane >> 2);
        #pragma unroll
        for (int half = 0; half < 2; ++half) {
            const int r = r0 + half * 8;
            const int s = r & (Sn - 1);
            #pragma unroll
            for (int j = 0; j < 4; ++j) {
                const int c0 = colStart + warp_n + j * 8 + (lane & 3) * 2;
                float v0 = acc[i][j][half*2]   + bias[c0];
                float v1 = acc[i][j][half*2+1] + bias[c0 + 1];
                if (EPI == 1) {
                    int pidx = (c0 & (HDn - 1)) >> 1;
                    float inv = exp2f((float)pidx * (-13.287712379549449f / 64.0f));
                    float sn, cs;
                    sincosf((float)s * inv, &sn, &cs);
                    float e = v0, o = v1;
                    v0 = e * cs - o * sn;
                    v1 = o * cs + e * sn;
                }
                if (EPI == 0)
                    *(float2*)&Cf[(size_t)r * Dn + c0] = make_float2(v0, v1);
                else
                    *(__half2*)&O[(size_t)r * Dn + c0] = __floats2half2_rn(v0, v1);
            }
        }
    }
}

// ============================================================================
// Flash-fused attention: per CTA = (bh, 128-row block). 8 warps x 16 rows,
// each warp spans the full 128-t width -> warp-private online softmax.
// P fragments built in registers from S accumulators (C->A identity).
// ============================================================================
#define QSZ        (128 * VROWB)           // 34816
#define KVSZ       (2 * QSZ)               // 69632 (K + V)
#define FLASH_SMEM (QSZ + 2 * KVSZ)        // 174080

__global__ void __launch_bounds__(256)
flash_f16(const __half* __restrict__ Q, const __half* __restrict__ K,
          const __half* __restrict__ V, __half* __restrict__ O16)
{
    extern __shared__ char smem_raw[];
    const uint32_t sb = smem_u32(smem_raw);

    const int rb = blockIdx.x;            // 0..3 (row block)
    const int bh = blockIdx.y;
    const int b  = bh >> 4, h = bh & 15;
    const int tid  = threadIdx.x;
    const int wid  = tid >> 5;
    const int lane = tid & 31;

    const size_t headoff = (size_t)(b * Sn) * Dn + h * HDn;
    const __half* gQ = Q + headoff + (size_t)(rb * 128) * Dn;
    const __half* gK = K + headoff;
    const __half* gV = V + headoff;

    const uint32_t sQ = sb;
    const uint32_t aoffV  = (uint32_t)((lane & 15) * VROWB + (lane >> 4) * 16);
    const uint32_t boffV  = (uint32_t)(((lane & 7) + ((lane >> 4) << 3)) * VROWB
                                       + ((lane >> 3) & 1) * 16);
    const uint32_t boffTV = (uint32_t)(((lane & 7) + ((lane >> 3) & 1) * 8) * VROWB
                                       + (lane >> 4) * 16);

    float oacc[16][4];
    #pragma unroll
    for (int j = 0; j < 16; ++j)
        #pragma unroll
        for (int r = 0; r < 4; ++r) oacc[j][r] = 0.f;
    float m[2] = {-1e30f, -1e30f};
    float l[2] = {0.f, 0.f};

    // prefetch Q + KV block 0
    load_tile128w(gQ, sQ, tid);
    load_tile128w(gK, sb + QSZ, tid);
    load_tile128w(gV, sb + QSZ + QSZ, tid);
    cp_commit();

    const float scale = 0.08838834764831843f;   // 1/sqrt(128)
    const uint32_t aQ = sQ + (uint32_t)(wid * 16) * VROWB + aoffV;

    #pragma unroll 1
    for (int kb = 0; kb <= rb; ++kb) {
        if (kb < rb) {
            const uint32_t bb = sb + QSZ + ((kb + 1) & 1) * KVSZ;
            load_tile128w(gK + (size_t)((kb + 1) * 128) * Dn, bb, tid);
            load_tile128w(gV + (size_t)((kb + 1) * 128) * Dn, bb + QSZ, tid);
            cp_commit();
            cp_wait<1>();
        } else {
            cp_wait<0>();
        }
        __syncthreads();

        const uint32_t kvb = sb + QSZ + (kb & 1) * KVSZ;
        const uint32_t sK = kvb, sV = kvb + QSZ;

        // ---- S = Q K^T (contraction over d=128, 8 k-steps) ----
        float sacc[16][4];
        #pragma unroll
        for (int j = 0; j < 16; ++j)
            #pragma unroll
            for (int r = 0; r < 4; ++r) sacc[j][r] = 0.f;

        #pragma unroll
        for (int kd = 0; kd < 8; ++kd) {
            uint32_t af[4];
            ldsm4(af, aQ + (uint32_t)(kd * 32));
            #pragma unroll
            for (int p = 0; p < 8; ++p) {
                uint32_t r[4];
                ldsm4(r, sK + (uint32_t)(p * 16) * VROWB + boffV + (uint32_t)(kd * 32));
                uint32_t b0[2] = {r[0], r[1]}, b1[2] = {r[2], r[3]};
                mma_f16(sacc[2*p],     af, b0);
                mma_f16(sacc[2*p + 1], af, b1);
            }
        }

        // ---- scale + causal mask (diagonal block only) ----
        const bool diag = (kb == rb);
        #pragma unroll
        for (int j = 0; j < 16; ++j)
            #pragma unroll
            for (int r = 0; r < 4; ++r) {
                float v = sacc[j][r] * scale;
                if (diag) {
                    int t_loc = j * 8 + (lane & 3) * 2 + (r & 1);
                    int s_loc = wid * 16 + (lane >> 2) + ((r >> 1) & 1) * 8;
                    if (t_loc > s_loc) v = -1e30f;
                }
                sacc[j][r] = v;
            }

        // ---- online softmax (per row-half h: rows lane>>2 and +8) ----
        float bm[2] = {-1e30f, -1e30f};
        #pragma unroll
        for (int j = 0; j < 16; ++j) {
            bm[0] = fmaxf(bm[0], fmaxf(sacc[j][0], sacc[j][1]));
            bm[1] = fmaxf(bm[1], fmaxf(sacc[j][2], sacc[j][3]));
        }
        #pragma unroll
        for (int o = 1; o <= 2; o <<= 1) {
            bm[0] = fmaxf(bm[0], __shfl_xor_sync(0xffffffffu, bm[0], o));
            bm[1] = fmaxf(bm[1], __shfl_xor_sync(0xffffffffu, bm[1], o));
        }
        float mn[2], f[2];
        #pragma unroll
        for (int hh = 0; hh < 2; ++hh) {
            mn[hh] = fmaxf(m[hh], bm[hh]);
            f[hh]  = __expf(m[hh] - mn[hh]);
            m[hh]  = mn[hh];
        }

        float rs[2] = {0.f, 0.f};
        #pragma unroll
        for (int j = 0; j < 16; ++j) {
            #pragma unroll
            for (int r = 0; r < 4; ++r) {
                const int hh = r >> 1;
                float e = __expf(sacc[j][r] - mn[hh]);
                sacc[j][r] = e;
                rs[hh] += e;
            }
        }
        #pragma unroll
        for (int o = 1; o <= 2; o <<= 1) {
            rs[0] += __shfl_xor_sync(0xffffffffu, rs[0], o);
            rs[1] += __shfl_xor_sync(0xffffffffu, rs[1], o);
        }
        l[0] = l[0] * f[0] + rs[0];
        l[1] = l[1] * f[1] + rs[1];

        #pragma unroll
        for (int j = 0; j < 16; ++j) {
            oacc[j][0] *= f[0]; oacc[j][1] *= f[0];
            oacc[j][2] *= f[1]; oacc[j][3] *= f[1];
        }

        // ---- P fragments (C->A register identity) + O += P V ----
        #pragma unroll
        for (int kt = 0; kt < 8; ++kt) {
            uint32_t pk[4];
            pk[0] = pack_h2(sacc[2*kt][0],     sacc[2*kt][1]);
            pk[1] = pack_h2(sacc[2*kt][2],     sacc[2*kt][3]);
            pk[2] = pack_h2(sacc[2*kt + 1][0], sacc[2*kt + 1][1]);
            pk[3] = pack_h2(sacc[2*kt + 1][2], sacc[2*kt + 1][3]);
            #pragma unroll
            for (int g = 0; g < 8; ++g) {
                uint32_t r[4];
                ldsm4t(r, sV + (uint32_t)(kt * 16) * VROWB + boffTV + (uint32_t)(g * 32));
                uint32_t b0[2] = {r[0], r[1]}, b1[2] = {r[2], r[3]};
                mma_f16(oacc[2*g],     pk, b0);
                mma_f16(oacc[2*g + 1], pk, b1);
            }
        }
        __syncthreads();   // protect buffer before next prefetch overwrite
    }

    // ---- finalize: O /= l, store fp16 ----
    const float inv0 = 1.f / l[0], inv1 = 1.f / l[1];
    #pragma unroll
    for (int hh = 0; hh < 2; ++hh) {
        const int s = rb * 128 + wid * 16 + (lane >> 2) + hh * 8;
        const size_t rbase = ((size_t)(b * Sn + s)) * Dn + h * HDn;
        const float inv = hh ? inv1 : inv0;
        #pragma unroll
        for (int j = 0; j < 16; ++j) {
            const int d = j * 8 + (lane & 3) * 2;
            *(__half2*)&O16[rbase + d] =
                __floats2half2_rn(oacc[j][hh*2] * inv, oacc[j][hh*2 + 1] * inv);
        }
    }
}

// ============================================================================
extern "C" void kernel_launch(void* const* d_in, const int* in_sizes, int n_in,
                              void* d_out, int out_size)
{
    const float* x  = (const float*)d_in[0];
    const float* wq = (const float*)d_in[2];
    const float* bq = (const float*)d_in[3];
    const float* wk = (const float*)d_in[4];
    const float* bk = (const float*)d_in[5];
    const float* wv = (const float*)d_in[6];
    const float* bv = (const float*)d_in[7];
    const float* wo = (const float*)d_in[8];
    const float* bo = (const float*)d_in[9];
    float* out = (float*)d_out;

    __half *x16, *o16, *w16, *q16, *k16, *v16;
    cudaGetSymbolAddress((void**)&x16, g_x16);
    cudaGetSymbolAddress((void**)&o16, g_o16);
    cudaGetSymbolAddress((void**)&w16, g_w16);
    cudaGetSymbolAddress((void**)&q16, g_q16);
    cudaGetSymbolAddress((void**)&k16, g_k16);
    cudaGetSymbolAddress((void**)&v16, g_v16);

    cudaFuncSetAttribute(gemm_f16s<0>, cudaFuncAttributeMaxDynamicSharedMemorySize, GEMM_SMEM_S);
    cudaFuncSetAttribute(gemm_f16s<1>, cudaFuncAttributeMaxDynamicSharedMemorySize, GEMM_SMEM_S);
    cudaFuncSetAttribute(gemm_f16s<2>, cudaFuncAttributeMaxDynamicSharedMemorySize, GEMM_SMEM_S);
    cudaFuncSetAttribute(flash_f16,   cudaFuncAttributeMaxDynamicSharedMemorySize, FLASH_SMEM);

    const int nSplitBlks = (int)(((size_t)Mtot * Dn / 4) / 256);
    dim3 gT(Dn / 32, Dn / 32), bT(32, 8);
    dim3 gG(Dn / 128, Mtot / 128);   // (16, 64)

    const size_t WSZ = (size_t)Dn * Dn;

    // --- preprocessing up front ---
    half_kernel<<<nSplitBlks, 256>>>((const float4*)x, x16);
    halfT_kernel<<<gT, bT>>>(wq, w16);
    halfT_kernel<<<gT, bT>>>(wk, w16 + WSZ);
    halfT_kernel<<<gT, bT>>>(wv, w16 + 2*WSZ);
    halfT_kernel<<<gT, bT>>>(wo, w16 + 3*WSZ);

    // --- Q/K/V projections ---
    gemm_f16s<1><<<gG, 256, GEMM_SMEM_S>>>(x16, w16,         bq, q16, nullptr);
    gemm_f16s<1><<<gG, 256, GEMM_SMEM_S>>>(x16, w16 + WSZ,   bk, k16, nullptr);
    gemm_f16s<2><<<gG, 256, GEMM_SMEM_S>>>(x16, w16 + 2*WSZ, bv, v16, nullptr);

    // --- flash-fused attention (logits+softmax+AV in one kernel) ---
    dim3 gF(Sn / 128, Bn * Hn);      // (4, 256)
    flash_f16<<<gF, 256, FLASH_SMEM>>>(q16, k16, v16, o16);

    // --- output projection ---
    gemm_f16s<0><<<gG, 256, GEMM_SMEM_S>>>(o16, w16 + 3*WSZ, bo, nullptr, out);
}

// round 14
// speedup vs baseline: 2.7691x; 1.0913x over previous
#include <cuda_runtime.h>
#include <cuda_fp16.h>
#include <math.h>
#include <stdint.h>

#define Bn   16
#define Sn   512
#define Dn   2048
#define Hn   16
#define HDn  128
#define Mtot (Bn*Sn)      // 8192
#define NQKV (3 * Dn)     // 6144

// ---------------- scratch (alloc-free: __device__ globals) ----------------
__device__ __half g_x16[(size_t)Mtot * Dn];          // 32 MB x (fp16)
__device__ __half g_o16[(size_t)Mtot * Dn];          // 32 MB attn-out (fp16)
__device__ __half g_wqkv[(size_t)Dn * NQKV];         // 24 MB W q|k|v  [k][n'] n'=6144
__device__ __half g_wo16[(size_t)Dn * Dn];           // 8 MB  W o      [k][n]
__device__ __half g_q16[(size_t)Mtot * Dn];          // 32 MB Q
__device__ __half g_k16[(size_t)Mtot * Dn];          // 32 MB K
__device__ __half g_v16[(size_t)Mtot * Dn];          // 32 MB V

// ============================================================================
// PTX helpers
// ============================================================================
__device__ __forceinline__ uint32_t smem_u32(const void* p) {
    uint32_t a;
    asm("{ .reg .u64 t; cvta.to.shared.u64 t, %1; cvt.u32.u64 %0, t; }" : "=r"(a) : "l"(p));
    return a;
}
__device__ __forceinline__ void cp16(uint32_t saddr, const void* gptr) {
    asm volatile("cp.async.cg.shared.global [%0], [%1], 16;" :: "r"(saddr), "l"(gptr) : "memory");
}
__device__ __forceinline__ void cp_commit() {
    asm volatile("cp.async.commit_group;" ::: "memory");
}
template <int N>
__device__ __forceinline__ void cp_wait() {
    asm volatile("cp.async.wait_group %0;" :: "n"(N) : "memory");
}
__device__ __forceinline__ void ldsm4(uint32_t* r, uint32_t addr) {
    asm volatile("ldmatrix.sync.aligned.m8n8.x4.shared.b16 {%0,%1,%2,%3}, [%4];"
                 : "=r"(r[0]), "=r"(r[1]), "=r"(r[2]), "=r"(r[3]) : "r"(addr));
}
__device__ __forceinline__ void ldsm4t(uint32_t* r, uint32_t addr) {
    asm volatile("ldmatrix.sync.aligned.m8n8.x4.trans.shared.b16 {%0,%1,%2,%3}, [%4];"
                 : "=r"(r[0]), "=r"(r[1]), "=r"(r[2]), "=r"(r[3]) : "r"(addr));
}
__device__ __forceinline__ void mma_f16(float* d, const uint32_t* a, const uint32_t* b) {
    asm volatile("mma.sync.aligned.m16n8k16.row.col.f32.f16.f16.f32 "
                 "{%0,%1,%2,%3}, {%4,%5,%6,%7}, {%8,%9}, {%0,%1,%2,%3};"
                 : "+f"(d[0]), "+f"(d[1]), "+f"(d[2]), "+f"(d[3])
                 : "r"(a[0]), "r"(a[1]), "r"(a[2]), "r"(a[3]), "r"(b[0]), "r"(b[1]));
}
__device__ __forceinline__ uint32_t pack_h2(float a, float b) {
    __half2 h = __floats2half2_rn(a, b);
    return *reinterpret_cast<uint32_t*>(&h);
}

// ============================================================================
// Tile geometry
// ============================================================================
#define KC      32
#define ROWB    80                   // A tiles: 32 fp16 + pad
#define TILE_B  (128 * ROWB)         // 10240 B
#define VROWB   272                  // 128 fp16 + 16B pad (wide rows)
#define WTILE_B (32 * VROWB)         // 8704 B (32 k-rows x 128 n)

// A tile: 128 rows x 32 halves
template <typename T>
__device__ __forceinline__ void load_tile(const T* __restrict__ g,
                                          int ldg, uint32_t sdst, int tid)
{
    #pragma unroll
    for (int it = 0; it < 2; ++it) {
        int idx = tid + it * 256;
        int row = idx >> 2, seg = idx & 3;
        cp16(sdst + (uint32_t)(row * ROWB + seg * 16),
             (const char*)(g + (size_t)row * ldg) + seg * 16);
    }
}
// W/V tile: 32 rows x 128 halves, row stride ldg halves
__device__ __forceinline__ void load_wtile(const __half* __restrict__ g,
                                           int ldg, uint32_t sdst, int tid)
{
    #pragma unroll
    for (int it = 0; it < 2; ++it) {
        int idx = tid + it * 256;
        int row = idx >> 4, seg = idx & 15;
        cp16(sdst + (uint32_t)(row * VROWB + seg * 16),
             (const char*)(g + (size_t)row * ldg) + seg * 16);
    }
}
// Q/K/V flash tile: 128 rows x 128 halves
__device__ __forceinline__ void load_tile128w(const __half* __restrict__ g,
                                              uint32_t sdst, int tid)
{
    #pragma unroll
    for (int it = 0; it < 8; ++it) {
        int idx = tid + it * 256;
        int row = idx >> 4, seg = idx & 15;
        cp16(sdst + (uint32_t)(row * VROWB + seg * 16),
             (const char*)(g + (size_t)row * Dn) + seg * 16);
    }
}

// ============================================================================
// Preprocessing: x fp32->fp16; W fp32->fp16 (NO transpose, natural [k][n])
// ============================================================================
__global__ void __launch_bounds__(256)
half_kernel(const float4* __restrict__ X, __half* __restrict__ H)
{
    size_t i = (size_t)blockIdx.x * 256 + threadIdx.x;
    float4 v = X[i];
    __half2* H2 = (__half2*)H;
    H2[2*i]   = __floats2half2_rn(v.x, v.y);
    H2[2*i+1] = __floats2half2_rn(v.z, v.w);
}

// q|k|v concatenated along n: out[k][which*2048 + n]
__global__ void __launch_bounds__(256)
convW3_kernel(const float4* __restrict__ Wq, const float4* __restrict__ Wk,
              const float4* __restrict__ Wv, __half* __restrict__ Out)
{
    const size_t QUARTER = (size_t)Dn * Dn / 4;     // float4 count per matrix
    size_t idx = (size_t)blockIdx.x * 256 + threadIdx.x;   // 0 .. 3*QUARTER-1
    int which = (int)(idx / QUARTER);
    size_t rem = idx - (size_t)which * QUARTER;
    size_t k   = rem / (Dn / 4);
    size_t seg = rem - k * (Dn / 4);
    const float4* src = (which == 0) ? Wq : (which == 1) ? Wk : Wv;
    float4 v = src[k * (Dn / 4) + seg];
    __half2* dst = (__half2*)&Out[k * NQKV + (size_t)which * Dn + seg * 4];
    dst[0] = __floats2half2_rn(v.x, v.y);
    dst[1] = __floats2half2_rn(v.z, v.w);
}

__global__ void __launch_bounds__(256)
convW_kernel(const float4* __restrict__ W, __half* __restrict__ Out)
{
    size_t i = (size_t)blockIdx.x * 256 + threadIdx.x;
    float4 v = W[i];
    __half2* dst = (__half2*)&Out[i * 4];
    dst[0] = __floats2half2_rn(v.x, v.y);
    dst[1] = __floats2half2_rn(v.z, v.w);
}

// ============================================================================
// NT GEMM: A [M][2048] fp16 row-major x W [2048][N'] fp16 row-major (B via
// trans-ldmatrix). 256 threads, 8 warps, warp 64x32, CTA 128x128, 1 pass/kk.
// EPI 0: WO -> fp32 out, single bias.  EPI 1: merged QKV -> fp16, per-slab
// bias/output selection, RoPE on q/k slabs.
// ============================================================================
#define NTBUF_B     (TILE_B + WTILE_B)   // 18944
#define GEMM_SMEM_NT (2 * NTBUF_B)       // 37888

template <int EPI>
__global__ void __launch_bounds__(256)
gemm_nt(const __half* __restrict__ A, const __half* __restrict__ W, int ldw,
        const float* __restrict__ b0, const float* __restrict__ b1,
        const float* __restrict__ b2,
        __half* __restrict__ o0, __half* __restrict__ o1,
        __half* __restrict__ o2, float* __restrict__ Cf)
{
    extern __shared__ char smem_raw[];
    const uint32_t sb = smem_u32(smem_raw);

    const int tid  = threadIdx.x;
    const int wid  = tid >> 5;
    const int lane = tid & 31;
    const int rowStart = blockIdx.y * 128;
    const int colStart = blockIdx.x * 128;
    const int which = colStart >> 11;          // slab (0 for WO)
    const int ccol  = colStart & (Dn - 1);
    const int warp_m = (wid & 1) * 64;
    const int warp_n = (wid >> 1) * 32;

    const float* bias = (EPI == 0) ? b0 : (which == 0) ? b0 : (which == 1) ? b1 : b2;
    __half* OH = (which == 0) ? o0 : (which == 1) ? o1 : o2;
    const bool rope = (EPI == 1) && (which < 2);

    const __half* gA = A + (size_t)rowStart * Dn;
    const __half* gW = W + colStart;

    const uint32_t aoff  = (uint32_t)((lane & 15) * ROWB + (lane >> 4) * 16);
    const uint32_t boffT = (uint32_t)(((lane & 7) + ((lane >> 3) & 1) * 8) * VROWB
                                      + (lane >> 4) * 16);

    float acc[4][4][4];
    #pragma unroll
    for (int i = 0; i < 4; i++)
        #pragma unroll
        for (int j = 0; j < 4; j++)
            #pragma unroll
            for (int r = 0; r < 4; r++) acc[i][j][r] = 0.f;

    const int NCHUNK = Dn / KC;   // 64

    {
        const uint32_t bb = sb;
        load_tile (gA, Dn, bb, tid);
        load_wtile(gW, ldw, bb + TILE_B, tid);
        cp_commit();
    }

    #pragma unroll 1
    for (int c = 0; c < NCHUNK; ++c) {
        if (c + 1 < NCHUNK) {
            const uint32_t bb = sb + ((c + 1) & 1) * NTBUF_B;
            const int k0 = (c + 1) * KC;
            load_tile (gA + k0, Dn, bb, tid);
            load_wtile(gW + (size_t)k0 * ldw, ldw, bb + TILE_B, tid);
            cp_commit();
            cp_wait<1>();
        } else {
            cp_wait<0>();
        }
        __syncthreads();

        const uint32_t bb = sb + (c & 1) * NTBUF_B;
        const uint32_t sA = bb, sW = bb + TILE_B;

        #pragma unroll
        for (int kk = 0; kk < 2; ++kk) {
            const uint32_t kbA = (uint32_t)(kk * 32);
            const uint32_t kbB = (uint32_t)(kk * 16 * VROWB);
            uint32_t afrag[4][4], bfrag[4][2];

            #pragma unroll
            for (int i = 0; i < 4; ++i)
                ldsm4(afrag[i], sA + aoff + kbA + (uint32_t)((warp_m + i*16) * ROWB));
            #pragma unroll
            for (int g = 0; g < 2; ++g) {
                uint32_t r[4];
                ldsm4t(r, sW + boffT + kbB + (uint32_t)((warp_n + g*16) * 2));
                bfrag[g*2][0] = r[0]; bfrag[g*2][1] = r[1];
                bfrag[g*2+1][0] = r[2]; bfrag[g*2+1][1] = r[3];
            }
            #pragma unroll
            for (int i = 0; i < 4; ++i)
                #pragma unroll
                for (int j = 0; j < 4; ++j)
                    mma_f16(acc[i][j], afrag[i], bfrag[j]);
        }
        __syncthreads();
    }

    #pragma unroll
    for (int i = 0; i < 4; ++i) {
        const int r0 = rowStart + warp_m + i * 16 + (lane >> 2);
        #pragma unroll
        for (int half = 0; half < 2; ++half) {
            const int r = r0 + half * 8;
            const int s = r & (Sn - 1);
            #pragma unroll
            for (int j = 0; j < 4; ++j) {
                const int c0 = ccol + warp_n + j * 8 + (lane & 3) * 2;
                float v0 = acc[i][j][half*2]   + bias[c0];
                float v1 = acc[i][j][half*2+1] + bias[c0 + 1];
                if (rope) {
                    int pidx = (c0 & (HDn - 1)) >> 1;
                    float inv = exp2f((float)pidx * (-13.287712379549449f / 64.0f));
                    float sn, cs;
                    sincosf((float)s * inv, &sn, &cs);
                    float e = v0, o = v1;
                    v0 = e * cs - o * sn;
                    v1 = o * cs + e * sn;
                }
                if (EPI == 0)
                    *(float2*)&Cf[(size_t)r * Dn + c0] = make_float2(v0, v1);
                else
                    *(__half2*)&OH[(size_t)r * Dn + c0] = __floats2half2_rn(v0, v1);
            }
        }
    }
}

// ============================================================================
// Flash-fused attention (unchanged from R13)
// ============================================================================
#define QSZ        (128 * VROWB)           // 34816
#define KVSZ       (2 * QSZ)               // 69632
#define FLASH_SMEM (QSZ + 2 * KVSZ)        // 174080

__global__ void __launch_bounds__(256)
flash_f16(const __half* __restrict__ Q, const __half* __restrict__ K,
          const __half* __restrict__ V, __half* __restrict__ O16)
{
    extern __shared__ char smem_raw[];
    const uint32_t sb = smem_u32(smem_raw);

    const int rb = blockIdx.x;
    const int bh = blockIdx.y;
    const int b  = bh >> 4, h = bh & 15;
    const int tid  = threadIdx.x;
    const int wid  = tid >> 5;
    const int lane = tid & 31;

    const size_t headoff = (size_t)(b * Sn) * Dn + h * HDn;
    const __half* gQ = Q + headoff + (size_t)(rb * 128) * Dn;
    const __half* gK = K + headoff;
    const __half* gV = V + headoff;

    const uint32_t sQ = sb;
    const uint32_t aoffV  = (uint32_t)((lane & 15) * VROWB + (lane >> 4) * 16);
    const uint32_t boffV  = (uint32_t)(((lane & 7) + ((lane >> 4) << 3)) * VROWB
                                       + ((lane >> 3) & 1) * 16);
    const uint32_t boffTV = (uint32_t)(((lane & 7) + ((lane >> 3) & 1) * 8) * VROWB
                                       + (lane >> 4) * 16);

    float oacc[16][4];
    #pragma unroll
    for (int j = 0; j < 16; ++j)
        #pragma unroll
        for (int r = 0; r < 4; ++r) oacc[j][r] = 0.f;
    float m[2] = {-1e30f, -1e30f};
    float l[2] = {0.f, 0.f};

    load_tile128w(gQ, sQ, tid);
    load_tile128w(gK, sb + QSZ, tid);
    load_tile128w(gV, sb + QSZ + QSZ, tid);
    cp_commit();

    const float scale = 0.08838834764831843f;
    const uint32_t aQ = sQ + (uint32_t)(wid * 16) * VROWB + aoffV;

    #pragma unroll 1
    for (int kb = 0; kb <= rb; ++kb) {
        if (kb < rb) {
            const uint32_t bb = sb + QSZ + ((kb + 1) & 1) * KVSZ;
            load_tile128w(gK + (size_t)((kb + 1) * 128) * Dn, bb, tid);
            load_tile128w(gV + (size_t)((kb + 1) * 128) * Dn, bb + QSZ, tid);
            cp_commit();
            cp_wait<1>();
        } else {
            cp_wait<0>();
        }
        __syncthreads();

        const uint32_t kvb = sb + QSZ + (kb & 1) * KVSZ;
        const uint32_t sK = kvb, sV = kvb + QSZ;

        float sacc[16][4];
        #pragma unroll
        for (int j = 0; j < 16; ++j)
            #pragma unroll
            for (int r = 0; r < 4; ++r) sacc[j][r] = 0.f;

        #pragma unroll
        for (int kd = 0; kd < 8; ++kd) {
            uint32_t af[4];
            ldsm4(af, aQ + (uint32_t)(kd * 32));
            #pragma unroll
            for (int p = 0; p < 8; ++p) {
                uint32_t r[4];
                ldsm4(r, sK + (uint32_t)(p * 16) * VROWB + boffV + (uint32_t)(kd * 32));
                uint32_t b0[2] = {r[0], r[1]}, b1[2] = {r[2], r[3]};
                mma_f16(sacc[2*p],     af, b0);
                mma_f16(sacc[2*p + 1], af, b1);
            }
        }

        const bool diag = (kb == rb);
        #pragma unroll
        for (int j = 0; j < 16; ++j)
            #pragma unroll
            for (int r = 0; r < 4; ++r) {
                float v = sacc[j][r] * scale;
                if (diag) {
                    int t_loc = j * 8 + (lane & 3) * 2 + (r & 1);
                    int s_loc = wid * 16 + (lane >> 2) + ((r >> 1) & 1) * 8;
                    if (t_loc > s_loc) v = -1e30f;
                }
                sacc[j][r] = v;
            }

        float bm[2] = {-1e30f, -1e30f};
        #pragma unroll
        for (int j = 0; j < 16; ++j) {
            bm[0] = fmaxf(bm[0], fmaxf(sacc[j][0], sacc[j][1]));
            bm[1] = fmaxf(bm[1], fmaxf(sacc[j][2], sacc[j][3]));
        }
        #pragma unroll
        for (int o = 1; o <= 2; o <<= 1) {
            bm[0] = fmaxf(bm[0], __shfl_xor_sync(0xffffffffu, bm[0], o));
            bm[1] = fmaxf(bm[1], __shfl_xor_sync(0xffffffffu, bm[1], o));
        }
        float mn[2], f[2];
        #pragma unroll
        for (int hh = 0; hh < 2; ++hh) {
            mn[hh] = fmaxf(m[hh], bm[hh]);
            f[hh]  = __expf(m[hh] - mn[hh]);
            m[hh]  = mn[hh];
        }

        float rs[2] = {0.f, 0.f};
        #pragma unroll
        for (int j = 0; j < 16; ++j) {
            #pragma unroll
            for (int r = 0; r < 4; ++r) {
                const int hh = r >> 1;
                float e = __expf(sacc[j][r] - mn[hh]);
                sacc[j][r] = e;
                rs[hh] += e;
            }
        }
        #pragma unroll
        for (int o = 1; o <= 2; o <<= 1) {
            rs[0] += __shfl_xor_sync(0xffffffffu, rs[0], o);
            rs[1] += __shfl_xor_sync(0xffffffffu, rs[1], o);
        }
        l[0] = l[0] * f[0] + rs[0];
        l[1] = l[1] * f[1] + rs[1];

        #pragma unroll
        for (int j = 0; j < 16; ++j) {
            oacc[j][0] *= f[0]; oacc[j][1] *= f[0];
            oacc[j][2] *= f[1]; oacc[j][3] *= f[1];
        }

        #pragma unroll
        for (int kt = 0; kt < 8; ++kt) {
            uint32_t pk[4];
            pk[0] = pack_h2(sacc[2*kt][0],     sacc[2*kt][1]);
            pk[1] = pack_h2(sacc[2*kt][2],     sacc[2*kt][3]);
            pk[2] = pack_h2(sacc[2*kt + 1][0], sacc[2*kt + 1][1]);
            pk[3] = pack_h2(sacc[2*kt + 1][2], sacc[2*kt + 1][3]);
            #pragma unroll
            for (int g = 0; g < 8; ++g) {
                uint32_t r[4];
                ldsm4t(r, sV + (uint32_t)(kt * 16) * VROWB + boffTV + (uint32_t)(g * 32));
                uint32_t b0[2] = {r[0], r[1]}, b1[2] = {r[2], r[3]};
                mma_f16(oacc[2*g],     pk, b0);
                mma_f16(oacc[2*g + 1], pk, b1);
            }
        }
        __syncthreads();
    }

    const float inv0 = 1.f / l[0], inv1 = 1.f / l[1];
    #pragma unroll
    for (int hh = 0; hh < 2; ++hh) {
        const int s = rb * 128 + wid * 16 + (lane >> 2) + hh * 8;
        const size_t rbase = ((size_t)(b * Sn + s)) * Dn + h * HDn;
        const float inv = hh ? inv1 : inv0;
        #pragma unroll
        for (int j = 0; j < 16; ++j) {
            const int d = j * 8 + (lane & 3) * 2;
            *(__half2*)&O16[rbase + d] =
                __floats2half2_rn(oacc[j][hh*2] * inv, oacc[j][hh*2 + 1] * inv);
        }
    }
}

// ============================================================================
extern "C" void kernel_launch(void* const* d_in, const int* in_sizes, int n_in,
                              void* d_out, int out_size)
{
    const float* x  = (const float*)d_in[0];
    const float* wq = (const float*)d_in[2];
    const float* bq = (const float*)d_in[3];
    const float* wk = (const float*)d_in[4];
    const float* bk = (const float*)d_in[5];
    const float* wv = (const float*)d_in[6];
    const float* bv = (const float*)d_in[7];
    const float* wo = (const float*)d_in[8];
    const float* bo = (const float*)d_in[9];
    float* out = (float*)d_out;

    __half *x16, *o16, *wqkv, *wo16, *q16, *k16, *v16;
    cudaGetSymbolAddress((void**)&x16,  g_x16);
    cudaGetSymbolAddress((void**)&o16,  g_o16);
    cudaGetSymbolAddress((void**)&wqkv, g_wqkv);
    cudaGetSymbolAddress((void**)&wo16, g_wo16);
    cudaGetSymbolAddress((void**)&q16,  g_q16);
    cudaGetSymbolAddress((void**)&k16,  g_k16);
    cudaGetSymbolAddress((void**)&v16,  g_v16);

    cudaFuncSetAttribute(gemm_nt<0>, cudaFuncAttributeMaxDynamicSharedMemorySize, GEMM_SMEM_NT);
    cudaFuncSetAttribute(gemm_nt<1>, cudaFuncAttributeMaxDynamicSharedMemorySize, GEMM_SMEM_NT);
    cudaFuncSetAttribute(flash_f16,  cudaFuncAttributeMaxDynamicSharedMemorySize, FLASH_SMEM);

    const int nXBlks = (int)(((size_t)Mtot * Dn / 4) / 256);    // 16384
    const int nW3Blks = (int)(((size_t)3 * Dn * Dn / 4) / 256); // 12288
    const int nW1Blks = (int)(((size_t)Dn * Dn / 4) / 256);     // 4096

    // --- preprocessing (conversions only; no transposes) ---
    half_kernel<<<nXBlks, 256>>>((const float4*)x, x16);
    convW3_kernel<<<nW3Blks, 256>>>((const float4*)wq, (const float4*)wk,
                                    (const float4*)wv, wqkv);
    convW_kernel<<<nW1Blks, 256>>>((const float4*)wo, wo16);

    // --- merged QKV projection (one launch, grid 48x64) ---
    dim3 gQKV(NQKV / 128, Mtot / 128);
    gemm_nt<1><<<gQKV, 256, GEMM_SMEM_NT>>>(x16, wqkv, NQKV,
                                            bq, bk, bv, q16, k16, v16, nullptr);

    // --- flash-fused attention ---
    dim3 gF(Sn / 128, Bn * Hn);
    flash_f16<<<gF, 256, FLASH_SMEM>>>(q16, k16, v16, o16);

    // --- output projection ---
    dim3 gWO(Dn / 128, Mtot / 128);
    gemm_nt<0><<<gWO, 256, GEMM_SMEM_NT>>>(o16, wo16, Dn,
                                           bo, nullptr, nullptr,
                                           nullptr, nullptr, nullptr, out);
}